// round 2
// baseline (speedup 1.0000x reference)
#include <cuda_runtime.h>

#define EPSF 1e-5f

// Problem constants
#define NND 256        // nodes
#define DD  128        // node dim
#define HH  512        // hidden
#define NR  65536      // NND*NND edge rows

// -------- scratch (device globals: allocation-free rule) --------
__device__ float g_edges[NR * DD];   // 33.5 MB
__device__ float g_adj[NR];
__device__ float g_msgs[NR];
__device__ float g_nodes[NND * DD];
__device__ float g_P[NND * HH];
__device__ float g_Q[NND * HH];

// ---------------------------------------------------------------
__global__ void k_copy_nodes(const float* __restrict__ src) {
    int i = blockIdx.x * blockDim.x + threadIdx.x;
    if (i < NND * DD) g_nodes[i] = src[i];
}

// edges init: dist -> LN(dist*w+b) -> relu, plus adjacency
__global__ void k_init_edges(const float* __restrict__ coords,
                             const float* __restrict__ w, const float* __restrict__ b,
                             const float* __restrict__ gg, const float* __restrict__ bb) {
    int warp = threadIdx.x >> 5, lane = threadIdx.x & 31;
    int row = blockIdx.x * 8 + warp;
    int i = row >> 8, j = row & 255;
    float dx = coords[i*3+0] - coords[j*3+0];
    float dy = coords[i*3+1] - coords[j*3+1];
    float dz = coords[i*3+2] - coords[j*3+2];
    float sq = dx*dx + dy*dy + dz*dz;
    float dist = sq > 0.f ? sqrtf(sq) : 0.f;
    if (lane == 0) g_adj[row] = (dist < 10.f) ? 1.f : 0.f;
    float e[4]; float s = 0.f, ss = 0.f;
#pragma unroll
    for (int t = 0; t < 4; t++) {
        int d = lane + 32*t;
        e[t] = dist * w[d] + b[d];
        s += e[t]; ss += e[t]*e[t];
    }
#pragma unroll
    for (int o = 16; o; o >>= 1) {
        s  += __shfl_xor_sync(0xffffffffu, s, o);
        ss += __shfl_xor_sync(0xffffffffu, ss, o);
    }
    float mean = s * (1.f/128.f);
    float var  = ss * (1.f/128.f) - mean*mean;
    float rs   = rsqrtf(var + EPSF);
#pragma unroll
    for (int t = 0; t < 4; t++) {
        int d = lane + 32*t;
        float v = (e[t]-mean)*rs*gg[d] + bb[d];
        g_edges[row*DD + d] = fmaxf(v, 0.f);
    }
}

// msgs[i,j] = adj[i,j] * dot(edges[i,j,:], nodes[i,:])
__global__ void k_msgs() {
    int warp = threadIdx.x >> 5, lane = threadIdx.x & 31;
    int row = blockIdx.x * 8 + warp;
    int i = row >> 8;
    const float4* e4 = (const float4*)(g_edges + row*DD);
    const float4* n4 = (const float4*)(g_nodes + i*DD);
    float4 a = e4[lane], c = n4[lane];
    float s = a.x*c.x + a.y*c.y + a.z*c.z + a.w*c.w;
#pragma unroll
    for (int o = 16; o; o >>= 1) s += __shfl_xor_sync(0xffffffffu, s, o);
    if (lane == 0) g_msgs[row] = g_adj[row] * s;
}

// P = nodes @ W1e[128:256],  Q = nodes @ W1e[256:384]
__global__ void __launch_bounds__(512) k_pq(const float* __restrict__ Wp,
                                            const float* __restrict__ Wq) {
    __shared__ float xs[32 * 128];
    int tid = threadIdx.x;
    int r0 = blockIdx.x * 32;
    const float* W = blockIdx.y ? Wq : Wp;
    float* out = blockIdx.y ? g_Q : g_P;
    float4* xs4 = (float4*)xs;
    const float4* src = (const float4*)(g_nodes + r0*DD);
#pragma unroll
    for (int t = 0; t < 2; t++) xs4[tid + t*512] = src[tid + t*512];
    __syncthreads();
    float acc[32];
#pragma unroll
    for (int r = 0; r < 32; r++) acc[r] = 0.f;
    for (int k = 0; k < 128; k++) {
        float wv = W[k*HH + tid];
#pragma unroll
        for (int r = 0; r < 32; r++) acc[r] = fmaf(xs[r*128 + k], wv, acc[r]);
    }
#pragma unroll
    for (int r = 0; r < 32; r++) out[(r0+r)*HH + tid] = acc[r];
}

// ---------------------------------------------------------------
// Fused edge update: edges += relu(LN(edges@W1a + P[i] + Q[j] + b1)) @ W2 + b2
// BM=64 rows, full N=512, K=128. 512 threads.
__global__ void __launch_bounds__(512, 1) k_edge(
        const float* __restrict__ W1a, const float* __restrict__ b1,
        const float* __restrict__ gg,  const float* __restrict__ bb,
        const float* __restrict__ W2,  const float* __restrict__ b2) {
    extern __shared__ float sm[];
    float* As   = sm;               // 64*128  = 8192
    float* Bs   = As + 8192;        // 16*512  = 8192
    float* Hs   = Bs + 8192;        // 64*512  = 32768
    float* Ps   = Hs + 32768;       // 512
    float* redS = Ps + 512;         // 128
    float* redQ = redS + 128;       // 128

    const int tid  = threadIdx.x;
    const int row0 = blockIdx.x * 64;
    const int i    = row0 >> 8;
    const int j0   = row0 & 255;

    {   // load edges tile (also the residual source)
        const float4* src = (const float4*)(g_edges + row0*DD);
        float4* dst = (float4*)As;
#pragma unroll
        for (int t = 0; t < 4; t++) dst[tid + t*512] = src[tid + t*512];
    }
    Ps[tid] = g_P[i*HH + tid] + b1[tid];
    __syncthreads();

    const int tr = tid >> 6, tc = tid & 63;
    const int m0 = tr * 8,  c0 = tc * 8;
    float acc[8][8];
#pragma unroll
    for (int mm = 0; mm < 8; mm++)
#pragma unroll
        for (int nn = 0; nn < 8; nn++) acc[mm][nn] = 0.f;

    // GEMM1: y = edges @ W1a  (K=128, 8 k-tiles of 16)
    for (int kt = 0; kt < 8; kt++) {
        {
            const float4* w4 = (const float4*)(W1a + kt*8192);
            float4* dst = (float4*)Bs;
#pragma unroll
            for (int t = 0; t < 4; t++) dst[tid + t*512] = w4[tid + t*512];
        }
        __syncthreads();
#pragma unroll
        for (int k = 0; k < 16; k++) {
            float4 t0 = *(const float4*)&Bs[k*HH + c0];
            float4 t1 = *(const float4*)&Bs[k*HH + c0 + 4];
#pragma unroll
            for (int mm = 0; mm < 8; mm++) {
                float a = As[(m0+mm)*128 + kt*16 + k];
                acc[mm][0] = fmaf(a, t0.x, acc[mm][0]);
                acc[mm][1] = fmaf(a, t0.y, acc[mm][1]);
                acc[mm][2] = fmaf(a, t0.z, acc[mm][2]);
                acc[mm][3] = fmaf(a, t0.w, acc[mm][3]);
                acc[mm][4] = fmaf(a, t1.x, acc[mm][4]);
                acc[mm][5] = fmaf(a, t1.y, acc[mm][5]);
                acc[mm][6] = fmaf(a, t1.z, acc[mm][6]);
                acc[mm][7] = fmaf(a, t1.w, acc[mm][7]);
            }
        }
        __syncthreads();
    }

    // epilogue: add P[i]+b1 and Q[j], then LN stats per row
    const int warp = tid >> 5, lane = tid & 31;
#pragma unroll
    for (int mm = 0; mm < 8; mm++) {
        const float* Qr = g_Q + (j0 + m0 + mm)*HH + c0;
        float s = 0.f, ss = 0.f;
#pragma unroll
        for (int nn = 0; nn < 8; nn++) {
            float y = acc[mm][nn] + Ps[c0+nn] + Qr[nn];
            acc[mm][nn] = y; s += y; ss += y*y;
        }
#pragma unroll
        for (int o = 16; o; o >>= 1) {
            s  += __shfl_xor_sync(0xffffffffu, s, o);
            ss += __shfl_xor_sync(0xffffffffu, ss, o);
        }
        if (lane == 0) { redS[warp*8 + mm] = s; redQ[warp*8 + mm] = ss; }
    }
    __syncthreads();
#pragma unroll
    for (int mm = 0; mm < 8; mm++) {
        float s  = redS[(tr*2)*8 + mm] + redS[(tr*2+1)*8 + mm];
        float ss = redQ[(tr*2)*8 + mm] + redQ[(tr*2+1)*8 + mm];
        float mean = s * (1.f/512.f);
        float var  = ss * (1.f/512.f) - mean*mean;
        float rs   = rsqrtf(var + EPSF);
        float4 o0, o1;
        o0.x = fmaxf((acc[mm][0]-mean)*rs*gg[c0+0] + bb[c0+0], 0.f);
        o0.y = fmaxf((acc[mm][1]-mean)*rs*gg[c0+1] + bb[c0+1], 0.f);
        o0.z = fmaxf((acc[mm][2]-mean)*rs*gg[c0+2] + bb[c0+2], 0.f);
        o0.w = fmaxf((acc[mm][3]-mean)*rs*gg[c0+3] + bb[c0+3], 0.f);
        o1.x = fmaxf((acc[mm][4]-mean)*rs*gg[c0+4] + bb[c0+4], 0.f);
        o1.y = fmaxf((acc[mm][5]-mean)*rs*gg[c0+5] + bb[c0+5], 0.f);
        o1.z = fmaxf((acc[mm][6]-mean)*rs*gg[c0+6] + bb[c0+6], 0.f);
        o1.w = fmaxf((acc[mm][7]-mean)*rs*gg[c0+7] + bb[c0+7], 0.f);
        *(float4*)&Hs[(m0+mm)*HH + c0]     = o0;
        *(float4*)&Hs[(m0+mm)*HH + c0 + 4] = o1;
    }
    __syncthreads();

    // GEMM2: out = h @ W2 (K=512), + residual + b2
    const int tc2 = tid & 31, tr2 = tid >> 5;  // cols tc2*4, rows tr2*4..+3
    float acc2[4][4];
#pragma unroll
    for (int rr = 0; rr < 4; rr++)
#pragma unroll
        for (int cc = 0; cc < 4; cc++) acc2[rr][cc] = 0.f;
    for (int kt = 0; kt < 32; kt++) {
        ((float4*)Bs)[tid] = ((const float4*)(W2 + kt*2048))[tid];
        __syncthreads();
#pragma unroll
        for (int k = 0; k < 16; k++) {
            float4 w = *(const float4*)&Bs[k*128 + tc2*4];
#pragma unroll
            for (int rr = 0; rr < 4; rr++) {
                float hv = Hs[(tr2*4+rr)*HH + kt*16 + k];
                acc2[rr][0] = fmaf(hv, w.x, acc2[rr][0]);
                acc2[rr][1] = fmaf(hv, w.y, acc2[rr][1]);
                acc2[rr][2] = fmaf(hv, w.z, acc2[rr][2]);
                acc2[rr][3] = fmaf(hv, w.w, acc2[rr][3]);
            }
        }
        __syncthreads();
    }
#pragma unroll
    for (int rr = 0; rr < 4; rr++) {
        int rm = tr2*4 + rr;
        int c  = tc2*4;
        float4 o;
        o.x = acc2[rr][0] + As[rm*128 + c+0] + b2[c+0];
        o.y = acc2[rr][1] + As[rm*128 + c+1] + b2[c+1];
        o.z = acc2[rr][2] + As[rm*128 + c+2] + b2[c+2];
        o.w = acc2[rr][3] + As[rm*128 + c+3] + b2[c+3];
        *(float4*)&g_edges[(row0+rm)*DD + c] = o;
    }
}

// ---------------------------------------------------------------
// shared building blocks for the 32-row MLP kernels (node update / final)
template<int KD>
__device__ __forceinline__ void mlp_ln_relu_32(
        const float* Xs, float* Bs, float* Hs, float* redS, float* redQ,
        const float* __restrict__ W1, const float* __restrict__ b1,
        const float* __restrict__ gg, const float* __restrict__ bb) {
    const int tid = threadIdx.x;
    const int tr = tid >> 6, tc = tid & 63;
    const int m0 = tr * 4, c0 = tc * 8;
    float acc[4][8];
#pragma unroll
    for (int mm = 0; mm < 4; mm++)
#pragma unroll
        for (int nn = 0; nn < 8; nn++) acc[mm][nn] = 0.f;

    for (int kt = 0; kt < KD/16; kt++) {
        {
            const float4* w4 = (const float4*)(W1 + kt*8192);
            float4* dst = (float4*)Bs;
#pragma unroll
            for (int t = 0; t < 4; t++) dst[tid + t*512] = w4[tid + t*512];
        }
        __syncthreads();
#pragma unroll
        for (int k = 0; k < 16; k++) {
            float4 t0 = *(const float4*)&Bs[k*HH + c0];
            float4 t1 = *(const float4*)&Bs[k*HH + c0 + 4];
#pragma unroll
            for (int mm = 0; mm < 4; mm++) {
                float a = Xs[(m0+mm)*KD + kt*16 + k];
                acc[mm][0] = fmaf(a, t0.x, acc[mm][0]);
                acc[mm][1] = fmaf(a, t0.y, acc[mm][1]);
                acc[mm][2] = fmaf(a, t0.z, acc[mm][2]);
                acc[mm][3] = fmaf(a, t0.w, acc[mm][3]);
                acc[mm][4] = fmaf(a, t1.x, acc[mm][4]);
                acc[mm][5] = fmaf(a, t1.y, acc[mm][5]);
                acc[mm][6] = fmaf(a, t1.z, acc[mm][6]);
                acc[mm][7] = fmaf(a, t1.w, acc[mm][7]);
            }
        }
        __syncthreads();
    }
    const int warp = tid >> 5, lane = tid & 31;
#pragma unroll
    for (int mm = 0; mm < 4; mm++) {
        float s = 0.f, ss = 0.f;
#pragma unroll
        for (int nn = 0; nn < 8; nn++) {
            float y = acc[mm][nn] + b1[c0+nn];
            acc[mm][nn] = y; s += y; ss += y*y;
        }
#pragma unroll
        for (int o = 16; o; o >>= 1) {
            s  += __shfl_xor_sync(0xffffffffu, s, o);
            ss += __shfl_xor_sync(0xffffffffu, ss, o);
        }
        if (lane == 0) { redS[warp*4 + mm] = s; redQ[warp*4 + mm] = ss; }
    }
    __syncthreads();
#pragma unroll
    for (int mm = 0; mm < 4; mm++) {
        float s  = redS[(tr*2)*4 + mm] + redS[(tr*2+1)*4 + mm];
        float ss = redQ[(tr*2)*4 + mm] + redQ[(tr*2+1)*4 + mm];
        float mean = s * (1.f/512.f);
        float var  = ss * (1.f/512.f) - mean*mean;
        float rs   = rsqrtf(var + EPSF);
#pragma unroll
        for (int nn = 0; nn < 8; nn++) {
            int c = c0 + nn;
            float h = (acc[mm][nn]-mean)*rs*gg[c] + bb[c];
            Hs[(m0+mm)*HH + c] = fmaxf(h, 0.f);
        }
    }
    __syncthreads();
}

__device__ __forceinline__ void gemm2_32(const float* Hs, float* Bs,
                                         const float* __restrict__ W2,
                                         float acc2[2][4]) {
    const int tid = threadIdx.x;
    const int tc2 = tid & 31, tr2 = tid >> 5;  // cols tc2*4, rows tr2*2..+1
#pragma unroll
    for (int rr = 0; rr < 2; rr++)
#pragma unroll
        for (int cc = 0; cc < 4; cc++) acc2[rr][cc] = 0.f;
    for (int kt = 0; kt < 32; kt++) {
        ((float4*)Bs)[tid] = ((const float4*)(W2 + kt*2048))[tid];
        __syncthreads();
#pragma unroll
        for (int k = 0; k < 16; k++) {
            float4 w = *(const float4*)&Bs[k*128 + tc2*4];
#pragma unroll
            for (int rr = 0; rr < 2; rr++) {
                float hv = Hs[(tr2*2+rr)*HH + kt*16 + k];
                acc2[rr][0] = fmaf(hv, w.x, acc2[rr][0]);
                acc2[rr][1] = fmaf(hv, w.y, acc2[rr][1]);
                acc2[rr][2] = fmaf(hv, w.z, acc2[rr][2]);
                acc2[rr][3] = fmaf(hv, w.w, acc2[rr][3]);
            }
        }
        __syncthreads();
    }
}

// node update: nodes += relu(LN([nodes|msgs]@W1 + b1)) @ W2 + b2
__global__ void __launch_bounds__(512, 1) k_node(
        const float* __restrict__ W1, const float* __restrict__ b1,
        const float* __restrict__ gg, const float* __restrict__ bb,
        const float* __restrict__ W2, const float* __restrict__ b2) {
    extern __shared__ float sm[];
    float* Xs   = sm;            // 32*384 = 12288
    float* Bs   = Xs + 12288;    // 8192
    float* Hs   = Bs + 8192;     // 16384
    float* redS = Hs + 16384;    // 64
    float* redQ = redS + 64;     // 64
    const int tid = threadIdx.x;
    const int r0 = blockIdx.x * 32;
    float4* xs4 = (float4*)Xs;
    {
        const float4* nsrc = (const float4*)(g_nodes + r0*DD);
#pragma unroll
        for (int t = 0; t < 2; t++) {
            int idx = tid + t*512;            // < 1024
            int row = idx >> 5, c4 = idx & 31;
            xs4[row*96 + c4] = nsrc[idx];
        }
        const float4* msrc = (const float4*)(g_msgs + r0*256);
#pragma unroll
        for (int t = 0; t < 4; t++) {
            int idx = tid + t*512;            // < 2048
            int row = idx >> 6, c4 = idx & 63;
            xs4[row*96 + 32 + c4] = msrc[idx];
        }
    }
    __syncthreads();
    mlp_ln_relu_32<384>(Xs, Bs, Hs, redS, redQ, W1, b1, gg, bb);
    float acc2[2][4];
    gemm2_32(Hs, Bs, W2, acc2);
    const int tc2 = tid & 31, tr2 = tid >> 5;
#pragma unroll
    for (int rr = 0; rr < 2; rr++) {
        int rm = tr2*2 + rr;
        int c  = tc2*4;
        float4 o;
        o.x = acc2[rr][0] + Xs[rm*384 + c+0] + b2[c+0];
        o.y = acc2[rr][1] + Xs[rm*384 + c+1] + b2[c+1];
        o.z = acc2[rr][2] + Xs[rm*384 + c+2] + b2[c+2];
        o.w = acc2[rr][3] + Xs[rm*384 + c+3] + b2[c+3];
        *(float4*)&g_nodes[(r0+rm)*DD + c] = o;
    }
}

// final: nodes_out = relu(LN(nd@no1))@no2+b ; coords = relu(LN(no@sp1))@sp2+b
__global__ void __launch_bounds__(512, 1) k_final(
        const float* __restrict__ no1_w, const float* __restrict__ no1_b,
        const float* __restrict__ no_g,  const float* __restrict__ no_bt,
        const float* __restrict__ no2_w, const float* __restrict__ no2_b,
        const float* __restrict__ sp1_w, const float* __restrict__ sp1_b,
        const float* __restrict__ sp_g,  const float* __restrict__ sp_bt,
        const float* __restrict__ sp2_w, const float* __restrict__ sp2_b,
        float* __restrict__ out_nodes, float* __restrict__ out_coords) {
    extern __shared__ float sm[];
    float* Xs   = sm;            // 4096
    float* Bs   = Xs + 4096;     // 8192
    float* Hs   = Bs + 8192;     // 16384
    float* X2   = Hs + 16384;    // 4096
    float* redS = X2 + 4096;     // 64
    float* redQ = redS + 64;     // 64
    const int tid = threadIdx.x;
    const int r0 = blockIdx.x * 32;
    {
        const float4* src = (const float4*)(g_nodes + r0*DD);
        float4* d4 = (float4*)Xs;
#pragma unroll
        for (int t = 0; t < 2; t++) d4[tid + t*512] = src[tid + t*512];
    }
    __syncthreads();
    mlp_ln_relu_32<128>(Xs, Bs, Hs, redS, redQ, no1_w, no1_b, no_g, no_bt);
    float acc2[2][4];
    gemm2_32(Hs, Bs, no2_w, acc2);
    const int tc2 = tid & 31, tr2 = tid >> 5;
#pragma unroll
    for (int rr = 0; rr < 2; rr++) {
        int rm = tr2*2 + rr;
        int c  = tc2*4;
        float4 o;
        o.x = acc2[rr][0] + no2_b[c+0];
        o.y = acc2[rr][1] + no2_b[c+1];
        o.z = acc2[rr][2] + no2_b[c+2];
        o.w = acc2[rr][3] + no2_b[c+3];
        *(float4*)&out_nodes[(r0+rm)*DD + c] = o;
        *(float4*)&X2[rm*128 + c] = o;
    }
    __syncthreads();
    mlp_ln_relu_32<128>(X2, Bs, Hs, redS, redQ, sp1_w, sp1_b, sp_g, sp_bt);
    if (tid < 96) {
        int row = tid / 3, cc = tid % 3;
        float s = sp2_b[cc];
        for (int k = 0; k < 512; k++) s = fmaf(Hs[row*HH + k], sp2_w[k*3 + cc], s);
        out_coords[(r0+row)*3 + cc] = s;
    }
}

// ---------------------------------------------------------------
extern "C" void kernel_launch(void* const* d_in, const int* in_sizes, int n_in,
                              void* d_out, int out_size) {
    const float* nodes  = (const float*)d_in[0];
    const float* coords = (const float*)d_in[1];
    const float* ee_w   = (const float*)d_in[2];
    const float* ee_b   = (const float*)d_in[3];
    const float* ee_g   = (const float*)d_in[4];
    const float* ee_bt  = (const float*)d_in[5];
    const float* nu1_w  = (const float*)d_in[6];
    const float* nu1_b  = (const float*)d_in[7];
    const float* nu_g   = (const float*)d_in[8];
    const float* nu_bt  = (const float*)d_in[9];
    const float* nu2_w  = (const float*)d_in[10];
    const float* nu2_b  = (const float*)d_in[11];
    const float* eu1_w  = (const float*)d_in[12];
    const float* eu1_b  = (const float*)d_in[13];
    const float* eu_g   = (const float*)d_in[14];
    const float* eu_bt  = (const float*)d_in[15];
    const float* eu2_w  = (const float*)d_in[16];
    const float* eu2_b  = (const float*)d_in[17];
    const float* sp1_w  = (const float*)d_in[18];
    const float* sp1_b  = (const float*)d_in[19];
    const float* sp_g   = (const float*)d_in[20];
    const float* sp_bt  = (const float*)d_in[21];
    const float* sp2_w  = (const float*)d_in[22];
    const float* sp2_b  = (const float*)d_in[23];
    const float* no1_w  = (const float*)d_in[24];
    const float* no1_b  = (const float*)d_in[25];
    const float* no_g   = (const float*)d_in[26];
    const float* no_bt  = (const float*)d_in[27];
    const float* no2_w  = (const float*)d_in[28];
    const float* no2_b  = (const float*)d_in[29];
    float* out = (float*)d_out;

    const int SME = (8192 + 8192 + 32768 + 512 + 128 + 128) * 4;   // 199680 B
    const int SMN = (12288 + 8192 + 16384 + 64 + 64) * 4;          // 147968 B
    const int SMF = (4096 + 8192 + 16384 + 4096 + 64 + 64) * 4;    // 131584 B
    cudaFuncSetAttribute(k_edge,  cudaFuncAttributeMaxDynamicSharedMemorySize, SME);
    cudaFuncSetAttribute(k_node,  cudaFuncAttributeMaxDynamicSharedMemorySize, SMN);
    cudaFuncSetAttribute(k_final, cudaFuncAttributeMaxDynamicSharedMemorySize, SMF);

    k_copy_nodes<<<64, 512>>>(nodes);
    k_init_edges<<<8192, 256>>>(coords, ee_w, ee_b, ee_g, ee_bt);

    for (int l = 0; l < 4; l++) {
        k_msgs<<<8192, 256>>>();
        k_pq<<<dim3(8, 2), 512>>>(eu1_w + l*196608 + 65536,   // W1e[128:256]
                                  eu1_w + l*196608 + 131072); // W1e[256:384]
        k_edge<<<1024, 512, SME>>>(eu1_w + l*196608, eu1_b + l*512,
                                   eu_g + l*512, eu_bt + l*512,
                                   eu2_w + l*65536, eu2_b + l*128);
        k_node<<<8, 512, SMN>>>(nu1_w + l*196608, nu1_b + l*512,
                                nu_g + l*512, nu_bt + l*512,
                                nu2_w + l*65536, nu2_b + l*128);
    }
    k_final<<<8, 512, SMF>>>(no1_w, no1_b, no_g, no_bt, no2_w, no2_b,
                             sp1_w, sp1_b, sp_g, sp_bt, sp2_w, sp2_b,
                             out, out + 32768);
}

// round 5
// speedup vs baseline: 2.3055x; 2.3055x over previous
#include <cuda_runtime.h>
#include <cuda_bf16.h>
#include <cstdint>

#define EPSF 1e-5f
#define NND 256
#define DD  128
#define HH  512
#define NR  65536

// -------- scratch (device globals: allocation-free rule) --------
__device__ __align__(16) float g_edges[NR * DD];
__device__ float g_adj[NR];
__device__ float g_msgs[NR];
__device__ __align__(16) float g_nodes[NND * DD];
__device__ __align__(16) float g_P[NND * HH];
__device__ __align__(16) float g_Q[NND * HH];
// pre-swizzled bf16 weight tile images: [layer][chunk][128n][128k] hi/lo
__device__ __align__(16) __nv_bfloat16 g_W1h[262144];
__device__ __align__(16) __nv_bfloat16 g_W1l[262144];
__device__ __align__(16) __nv_bfloat16 g_W2h[262144];
__device__ __align__(16) __nv_bfloat16 g_W2l[262144];

// ================= low-level helpers =================
__device__ __forceinline__ uint32_t smem_to_u32(const void* p) {
    uint32_t a;
    asm("{ .reg .u64 t; cvta.to.shared.u64 t, %1; cvt.u32.u64 %0, t; }" : "=r"(a) : "l"(p));
    return a;
}
__device__ __forceinline__ void ldsm_x4(uint32_t* r, uint32_t addr) {
    asm volatile("ldmatrix.sync.aligned.m8n8.x4.shared.b16 {%0,%1,%2,%3}, [%4];"
        : "=r"(r[0]), "=r"(r[1]), "=r"(r[2]), "=r"(r[3]) : "r"(addr));
}
__device__ __forceinline__ void mma16816(float* c, const uint32_t* a, uint32_t b0, uint32_t b1) {
    asm volatile("mma.sync.aligned.m16n8k16.row.col.f32.bf16.bf16.f32 "
        "{%0,%1,%2,%3}, {%4,%5,%6,%7}, {%8,%9}, {%0,%1,%2,%3};"
        : "+f"(c[0]), "+f"(c[1]), "+f"(c[2]), "+f"(c[3])
        : "r"(a[0]), "r"(a[1]), "r"(a[2]), "r"(a[3]), "r"(b0), "r"(b1));
}
__device__ __forceinline__ void cpasync16(uint32_t dst, const void* src) {
    asm volatile("cp.async.cg.shared.global [%0], [%1], 16;" :: "r"(dst), "l"(src));
}
__device__ __forceinline__ void pack2(float a, float b, uint32_t& hi, uint32_t& lo) {
    __nv_bfloat16 ah = __float2bfloat16(a), bh = __float2bfloat16(b);
    float ar = a - __bfloat162float(ah), br = b - __bfloat162float(bh);
    __nv_bfloat16 al = __float2bfloat16(ar), bl = __float2bfloat16(br);
    hi = (uint32_t)__bfloat16_as_ushort(ah) | ((uint32_t)__bfloat16_as_ushort(bh) << 16);
    lo = (uint32_t)__bfloat16_as_ushort(al) | ((uint32_t)__bfloat16_as_ushort(bl) << 16);
}
// byte offset inside a [rows][128k] bf16 tile (256B/row, XOR-swizzled 16B chunks)
__device__ __host__ __forceinline__ uint32_t swz_off(int r, int k) {
    return (uint32_t)(r * 256 + ((((k >> 3) ^ (r & 7)) & 15) << 4) + (k & 7) * 2);
}

// ================= weight image prep =================
// W1 image (l,nc): elem(n,k) = W1[k][nc*128+n]; W2 image (l,kc): elem(n,k) = W2[kc*128+k][n]
__global__ void k_prep_w(const float* __restrict__ eu1_w, const float* __restrict__ eu2_w) {
    int idx = blockIdx.x * 256 + threadIdx.x;     // 524288
    int e = idx & 16383;
    int chunk = (idx >> 14) & 3;
    int l = (idx >> 16) & 3;
    int which = idx >> 18;
    int n = e >> 7, k = e & 127;
    float v;
    if (which == 0) v = eu1_w[l * 196608 + k * 512 + chunk * 128 + n];
    else            v = eu2_w[l * 65536 + (chunk * 128 + k) * 128 + n];
    __nv_bfloat16 h = __float2bfloat16(v);
    __nv_bfloat16 lo = __float2bfloat16(v - __bfloat162float(h));
    int dst = (l * 4 + chunk) * 16384 + (int)(swz_off(n, k) >> 1);
    if (which == 0) { g_W1h[dst] = h; g_W1l[dst] = lo; }
    else            { g_W2h[dst] = h; g_W2l[dst] = lo; }
}

// ================= small helper kernels =================
__global__ void k_copy_nodes(const float* __restrict__ src) {
    int i = blockIdx.x * blockDim.x + threadIdx.x;
    if (i < NND * DD) g_nodes[i] = src[i];
}

__global__ void k_init_edges(const float* __restrict__ coords,
                             const float* __restrict__ w, const float* __restrict__ b,
                             const float* __restrict__ gg, const float* __restrict__ bb) {
    int warp = threadIdx.x >> 5, lane = threadIdx.x & 31;
    int row = blockIdx.x * 8 + warp;
    int i = row >> 8, j = row & 255;
    float dx = coords[i*3+0] - coords[j*3+0];
    float dy = coords[i*3+1] - coords[j*3+1];
    float dz = coords[i*3+2] - coords[j*3+2];
    float sq = dx*dx + dy*dy + dz*dz;
    float dist = sq > 0.f ? sqrtf(sq) : 0.f;
    if (lane == 0) g_adj[row] = (dist < 10.f) ? 1.f : 0.f;
    float e[4]; float s = 0.f, ss = 0.f;
#pragma unroll
    for (int t = 0; t < 4; t++) {
        int d = lane + 32*t;
        e[t] = dist * w[d] + b[d];
        s += e[t]; ss += e[t]*e[t];
    }
#pragma unroll
    for (int o = 16; o; o >>= 1) {
        s  += __shfl_xor_sync(0xffffffffu, s, o);
        ss += __shfl_xor_sync(0xffffffffu, ss, o);
    }
    float mean = s * (1.f/128.f);
    float var  = ss * (1.f/128.f) - mean*mean;
    float rs   = rsqrtf(var + EPSF);
#pragma unroll
    for (int t = 0; t < 4; t++) {
        int d = lane + 32*t;
        float v = (e[t]-mean)*rs*gg[d] + bb[d];
        g_edges[row*DD + d] = fmaxf(v, 0.f);
    }
}

__global__ void k_msgs() {
    int warp = threadIdx.x >> 5, lane = threadIdx.x & 31;
    int row = blockIdx.x * 8 + warp;
    int i = row >> 8;
    const float4* e4 = (const float4*)(g_edges + row*DD);
    const float4* n4 = (const float4*)(g_nodes + i*DD);
    float4 a = e4[lane], c = n4[lane];
    float s = a.x*c.x + a.y*c.y + a.z*c.z + a.w*c.w;
#pragma unroll
    for (int o = 16; o; o >>= 1) s += __shfl_xor_sync(0xffffffffu, s, o);
    if (lane == 0) g_msgs[row] = g_adj[row] * s;
}

// P = nodes @ W1e[128:256], Q = nodes @ W1e[256:384]; grid (64,2), 512 thr
__global__ void __launch_bounds__(512) k_pq(const float* __restrict__ Wp,
                                            const float* __restrict__ Wq) {
    __shared__ float xs[512];
    int tid = threadIdx.x;
    int r0 = blockIdx.x * 4;
    const float* __restrict__ W = blockIdx.y ? Wq : Wp;
    float* out = blockIdx.y ? g_Q : g_P;
    xs[tid] = g_nodes[r0 * 128 + tid];
    __syncthreads();
    float a0 = 0.f, a1 = 0.f, a2 = 0.f, a3 = 0.f;
#pragma unroll 8
    for (int k = 0; k < 128; k++) {
        float wv = W[k * 512 + tid];
        a0 = fmaf(xs[k],       wv, a0);
        a1 = fmaf(xs[128 + k], wv, a1);
        a2 = fmaf(xs[256 + k], wv, a2);
        a3 = fmaf(xs[384 + k], wv, a3);
    }
    out[(r0+0)*512 + tid] = a0;
    out[(r0+1)*512 + tid] = a1;
    out[(r0+2)*512 + tid] = a2;
    out[(r0+3)*512 + tid] = a3;
}

// ================= HMMA fused edge update =================
// edges[64-row tile] += relu(LN(edges@W1a + P[i] + Q[j] + b1)) @ W2 + b2
// smem: AH@0(16K) AL@16K  Bbuf0@32K(64K) Bbuf1@96K(64K)
//       Pb@163840 Gam@165888 Bet@167936 B2@169984 redS@170496 redQ@170752 mean@171008 rstd@171264
__global__ void __launch_bounds__(512, 1) k_edge_mma(int l,
        const float* __restrict__ b1, const float* __restrict__ gg,
        const float* __restrict__ bb, const float* __restrict__ b2) {
    extern __shared__ char sm[];
    const uint32_t S = smem_to_u32(sm);
    const int tid = threadIdx.x, lane = tid & 31;
    const int wM = (tid >> 5) & 1, wN = tid >> 6;
    const int row0 = blockIdx.x * 64;
    const int i = row0 >> 8, j0 = row0 & 255;

    const uint32_t AH = S, AL = S + 16384, BB = S + 32768;
    float* Pb   = (float*)(sm + 163840);
    float* Gam  = (float*)(sm + 165888);
    float* Bet  = (float*)(sm + 167936);
    float* B2s  = (float*)(sm + 169984);
    float* redS = (float*)(sm + 170496);
    float* redQ = (float*)(sm + 170752);
    float* meanS = (float*)(sm + 171008);
    float* rstdS = (float*)(sm + 171264);

    Pb[tid]  = g_P[i*512 + tid] + b1[tid];
    Gam[tid] = gg[tid];
    Bet[tid] = bb[tid];
    if (tid < 128) B2s[tid] = b2[tid];
    if (tid < 64) { redS[tid] = 0.f; redQ[tid] = 0.f; }

    // prefetch W1 chunks 0,1
    auto fill = [&](int buf, const __nv_bfloat16* sH, const __nv_bfloat16* sL) {
        uint32_t dH = BB + (uint32_t)buf * 65536, dL = dH + 32768;
#pragma unroll
        for (int t = 0; t < 4; t++) {
            uint32_t byo = (uint32_t)(tid + t * 512) * 16;
            cpasync16(dH + byo, (const char*)sH + byo);
            cpasync16(dL + byo, (const char*)sL + byo);
        }
        asm volatile("cp.async.commit_group;" ::: "memory");
    };
    const __nv_bfloat16* W1Hb = g_W1h + l * 65536;
    const __nv_bfloat16* W1Lb = g_W1l + l * 65536;
    const __nv_bfloat16* W2Hb = g_W2h + l * 65536;
    const __nv_bfloat16* W2Lb = g_W2l + l * 65536;
    fill(0, W1Hb, W1Lb);
    fill(1, W1Hb + 16384, W1Lb + 16384);

    // A = edges tile -> bf16 hi/lo swizzled panels
#pragma unroll
    for (int t = 0; t < 4; t++) {
        int idx = tid + t * 512;                  // 0..2047
        int r = idx >> 5, c4 = idx & 31;
        int k0 = c4 * 4;
        float4 v = *(const float4*)&g_edges[(size_t)(row0 + r) * 128 + k0];
        uint32_t h0, l0, h1, l1;
        pack2(v.x, v.y, h0, l0);
        pack2(v.z, v.w, h1, l1);
        uint32_t off = swz_off(r, k0);
        *(uint2*)(sm + off)         = make_uint2(h0, h1);
        *(uint2*)(sm + 16384 + off) = make_uint2(l0, l1);
    }

    // ---- GEMM1: acc1 = A @ W1chunks (3-split) ----
    float acc1[4][2][2][4];
#pragma unroll
    for (int a = 0; a < 4; a++)
#pragma unroll
        for (int b = 0; b < 2; b++)
#pragma unroll
            for (int c = 0; c < 2; c++)
#pragma unroll
                for (int d = 0; d < 4; d++) acc1[a][b][c][d] = 0.f;

    const int aR  = wM * 32 + (lane & 15);
    const int aKx = lane >> 4;
    const int bR  = wN * 16 + (lane & 7) + ((lane & 16) >> 1);
    const int bKx = (lane & 8) >> 3;

#pragma unroll
    for (int nc = 0; nc < 4; nc++) {
        asm volatile("cp.async.wait_group 1;" ::: "memory");
        __syncthreads();
        uint32_t BH = BB + (uint32_t)(nc & 1) * 65536, BL = BH + 32768;
#pragma unroll
        for (int ks = 0; ks < 8; ks++) {
            uint32_t ah[2][4], al[2][4], bh[4], bl[4];
#pragma unroll
            for (int mt = 0; mt < 2; mt++) {
                int r = aR + mt * 16;
                uint32_t off = (uint32_t)r * 256 + (uint32_t)((((ks * 2 + aKx) ^ (r & 7)) & 15) << 4);
                ldsm_x4(ah[mt], AH + off);
                ldsm_x4(al[mt], AL + off);
            }
            {
                uint32_t off = (uint32_t)bR * 256 + (uint32_t)((((ks * 2 + bKx) ^ (bR & 7)) & 15) << 4);
                ldsm_x4(bh, BH + off);
                ldsm_x4(bl, BL + off);
            }
#pragma unroll
            for (int mt = 0; mt < 2; mt++) {
                mma16816(acc1[nc][mt][0], ah[mt], bh[0], bh[1]);
                mma16816(acc1[nc][mt][1], ah[mt], bh[2], bh[3]);
                mma16816(acc1[nc][mt][0], al[mt], bh[0], bh[1]);
                mma16816(acc1[nc][mt][1], al[mt], bh[2], bh[3]);
                mma16816(acc1[nc][mt][0], ah[mt], bl[0], bl[1]);
                mma16816(acc1[nc][mt][1], ah[mt], bl[2], bl[3]);
            }
        }
        __syncthreads();
        if (nc < 2) fill(nc & 1, W1Hb + (nc + 2) * 16384, W1Lb + (nc + 2) * 16384);
        else        fill(nc & 1, W2Hb + (nc - 2) * 16384, W2Lb + (nc - 2) * 16384);
    }

    // ---- epilogue: y = acc + P + Q, LN stats ----
    const int R = wM * 32 + (lane >> 2);
    const int colB = wN * 16 + (lane & 3) * 2;
    float s4[4] = {0.f, 0.f, 0.f, 0.f}, q4[4] = {0.f, 0.f, 0.f, 0.f};
#pragma unroll
    for (int nc = 0; nc < 4; nc++)
#pragma unroll
        for (int mt = 0; mt < 2; mt++)
#pragma unroll
            for (int nt = 0; nt < 2; nt++) {
                int col = nc * 128 + colB + nt * 8;
                int rA = j0 + R + mt * 16;
                float2 qa = *(const float2*)&g_Q[(size_t)rA * 512 + col];
                float2 qb = *(const float2*)&g_Q[(size_t)(rA + 8) * 512 + col];
                float p0 = Pb[col], p1 = Pb[col + 1];
                float* a = acc1[nc][mt][nt];
                a[0] += p0 + qa.x; a[1] += p1 + qa.y;
                a[2] += p0 + qb.x; a[3] += p1 + qb.y;
                s4[mt*2+0] += a[0] + a[1]; q4[mt*2+0] += a[0]*a[0] + a[1]*a[1];
                s4[mt*2+1] += a[2] + a[3]; q4[mt*2+1] += a[2]*a[2] + a[3]*a[3];
            }
#pragma unroll
    for (int o = 1; o <= 2; o <<= 1)
#pragma unroll
        for (int t = 0; t < 4; t++) {
            s4[t] += __shfl_xor_sync(0xffffffffu, s4[t], o);
            q4[t] += __shfl_xor_sync(0xffffffffu, q4[t], o);
        }
    if ((lane & 3) == 0) {
#pragma unroll
        for (int t = 0; t < 4; t++) {
            int rr = R + (t >> 1) * 16 + (t & 1) * 8;
            atomicAdd(&redS[rr], s4[t]);
            atomicAdd(&redQ[rr], q4[t]);
        }
    }
    __syncthreads();
    if (tid < 64) {
        float mean = redS[tid] * (1.f / 512.f);
        float var = redQ[tid] * (1.f / 512.f) - mean * mean;
        meanS[tid] = mean;
        rstdS[tid] = rsqrtf(var + EPSF);
    }
    __syncthreads();
    float mn[4], rs[4];
#pragma unroll
    for (int t = 0; t < 4; t++) {
        int rr = R + (t >> 1) * 16 + (t & 1) * 8;
        mn[t] = meanS[rr]; rs[t] = rstdS[rr];
    }

    // ---- GEMM2: out = relu(LN(y)) @ W2 (h staged per k-chunk in A panels) ----
    float acc2[2][2][4];
#pragma unroll
    for (int b = 0; b < 2; b++)
#pragma unroll
        for (int c = 0; c < 2; c++)
#pragma unroll
            for (int d = 0; d < 4; d++) acc2[b][c][d] = 0.f;

#pragma unroll
    for (int kc = 0; kc < 4; kc++) {
        if (kc == 3) asm volatile("cp.async.wait_group 0;" ::: "memory");
        else         asm volatile("cp.async.wait_group 1;" ::: "memory");
        // write normalized h chunk to A panels
#pragma unroll
        for (int mt = 0; mt < 2; mt++)
#pragma unroll
            for (int nt = 0; nt < 2; nt++) {
                int col = kc * 128 + colB + nt * 8;
                float g0 = Gam[col], g1 = Gam[col + 1];
                float be0 = Bet[col], be1 = Bet[col + 1];
                float* a = acc1[kc][mt][nt];
                float h0 = fmaxf((a[0] - mn[mt*2])   * rs[mt*2]   * g0 + be0, 0.f);
                float h1 = fmaxf((a[1] - mn[mt*2])   * rs[mt*2]   * g1 + be1, 0.f);
                float h2 = fmaxf((a[2] - mn[mt*2+1]) * rs[mt*2+1] * g0 + be0, 0.f);
                float h3 = fmaxf((a[3] - mn[mt*2+1]) * rs[mt*2+1] * g1 + be1, 0.f);
                uint32_t hh0, ll0, hh1, ll1;
                pack2(h0, h1, hh0, ll0);
                pack2(h2, h3, hh1, ll1);
                int kl = colB + nt * 8;
                int r1 = R + mt * 16, r2 = r1 + 8;
                uint32_t o1 = swz_off(r1, kl), o2 = swz_off(r2, kl);
                *(uint32_t*)(sm + o1) = hh0; *(uint32_t*)(sm + 16384 + o1) = ll0;
                *(uint32_t*)(sm + o2) = hh1; *(uint32_t*)(sm + 16384 + o2) = ll1;
            }
        __syncthreads();
        uint32_t BH = BB + (uint32_t)(kc & 1) * 65536, BL = BH + 32768;
#pragma unroll
        for (int ks = 0; ks < 8; ks++) {
            uint32_t ah[2][4], al[2][4], bh[4], bl[4];
#pragma unroll
            for (int mt = 0; mt < 2; mt++) {
                int r = aR + mt * 16;
                uint32_t off = (uint32_t)r * 256 + (uint32_t)((((ks * 2 + aKx) ^ (r & 7)) & 15) << 4);
                ldsm_x4(ah[mt], AH + off);
                ldsm_x4(al[mt], AL + off);
            }
            {
                uint32_t off = (uint32_t)bR * 256 + (uint32_t)((((ks * 2 + bKx) ^ (bR & 7)) & 15) << 4);
                ldsm_x4(bh, BH + off);
                ldsm_x4(bl, BL + off);
            }
#pragma unroll
            for (int mt = 0; mt < 2; mt++) {
                mma16816(acc2[mt][0], ah[mt], bh[0], bh[1]);
                mma16816(acc2[mt][1], ah[mt], bh[2], bh[3]);
                mma16816(acc2[mt][0], al[mt], bh[0], bh[1]);
                mma16816(acc2[mt][1], al[mt], bh[2], bh[3]);
                mma16816(acc2[mt][0], ah[mt], bl[0], bl[1]);
                mma16816(acc2[mt][1], ah[mt], bl[2], bl[3]);
            }
        }
        __syncthreads();
        if (kc < 2) fill(kc & 1, W2Hb + (kc + 2) * 16384, W2Lb + (kc + 2) * 16384);
    }

    // ---- output: acc2 + residual + b2 ----
#pragma unroll
    for (int mt = 0; mt < 2; mt++)
#pragma unroll
        for (int nt = 0; nt < 2; nt++) {
            int col = colB + nt * 8;
            int r1 = row0 + R + mt * 16;
            float b20 = B2s[col], b21 = B2s[col + 1];
            float2 e0 = *(const float2*)&g_edges[(size_t)r1 * 128 + col];
            float2 e1 = *(const float2*)&g_edges[(size_t)(r1 + 8) * 128 + col];
            float* a = acc2[mt][nt];
            *(float2*)&g_edges[(size_t)r1 * 128 + col]       = make_float2(a[0] + e0.x + b20, a[1] + e0.y + b21);
            *(float2*)&g_edges[(size_t)(r1 + 8) * 128 + col] = make_float2(a[2] + e1.x + b20, a[3] + e1.y + b21);
        }
}

// ================= BM=8 FFMA MLP blocks (node update / final) =================
template<int KD>
__device__ __forceinline__ void mlp8(const float* Xs, float* Bs, float* Hs, float* red,
        const float* __restrict__ W1, const float* __restrict__ b1,
        const float* __restrict__ gg, const float* __restrict__ bb, int tid) {
    int tr = tid >> 6, tc = tid & 63, c0 = tc * 8;
    float acc[8];
#pragma unroll
    for (int n = 0; n < 8; n++) acc[n] = 0.f;
    for (int kt = 0; kt < KD / 16; kt++) {
        float4* b4 = (float4*)Bs;
#pragma unroll
        for (int t = 0; t < 4; t++) {
            int idx = tid + t * 512;
            b4[idx] = *(const float4*)&W1[kt * 8192 + idx * 4];
        }
        __syncthreads();
#pragma unroll
        for (int k = 0; k < 16; k++) {
            float a = Xs[tr * KD + kt * 16 + k];
            const float* br = &Bs[k * 512 + c0];
#pragma unroll
            for (int n = 0; n < 8; n++) acc[n] = fmaf(a, br[n], acc[n]);
        }
        __syncthreads();
    }
    float s = 0.f, q = 0.f;
#pragma unroll
    for (int n = 0; n < 8; n++) {
        float y = acc[n] + b1[c0 + n];
        acc[n] = y; s += y; q += y * y;
    }
#pragma unroll
    for (int o = 16; o; o >>= 1) {
        s += __shfl_xor_sync(0xffffffffu, s, o);
        q += __shfl_xor_sync(0xffffffffu, q, o);
    }
    int wid = tid >> 5;
    if ((tid & 31) == 0) { red[wid] = s; red[16 + wid] = q; }
    __syncthreads();
    {
        float S = red[2 * tr] + red[2 * tr + 1];
        float Q2 = red[16 + 2 * tr] + red[16 + 2 * tr + 1];
        float mean = S * (1.f / 512.f);
        float var = Q2 * (1.f / 512.f) - mean * mean;
        float rstd = rsqrtf(var + EPSF);
#pragma unroll
        for (int n = 0; n < 8; n++)
            Hs[tr * 512 + c0 + n] = fmaxf((acc[n] - mean) * rstd * gg[c0 + n] + bb[c0 + n], 0.f);
    }
    __syncthreads();
}

__device__ __forceinline__ void gemm2_8(const float* Hs, float* Bs,
        const float* __restrict__ W2, int tid, float& o0, float& o1) {
    int col = tid & 127, rp = tid >> 7;
    o0 = 0.f; o1 = 0.f;
    for (int kt = 0; kt < 32; kt++) {
        ((float4*)Bs)[tid] = *(const float4*)&W2[kt * 2048 + tid * 4];
        __syncthreads();
#pragma unroll
        for (int k = 0; k < 16; k++) {
            float w = Bs[k * 128 + col];
            o0 = fmaf(Hs[(2 * rp) * 512 + kt * 16 + k], w, o0);
            o1 = fmaf(Hs[(2 * rp + 1) * 512 + kt * 16 + k], w, o1);
        }
        __syncthreads();
    }
}

// node update: nodes += relu(LN([nodes|msgs]@W1+b1))@W2+b2 ; BM=8, grid 32
__global__ void __launch_bounds__(512, 1) k_node(
        const float* __restrict__ W1, const float* __restrict__ b1,
        const float* __restrict__ gg, const float* __restrict__ bb,
        const float* __restrict__ W2, const float* __restrict__ b2) {
    extern __shared__ float smf[];
    float* Xs = smf;            // 8*384 = 3072
    float* Bs = Xs + 3072;      // 8192
    float* Hs = Bs + 8192;      // 4096
    float* red = Hs + 4096;     // 32
    int tid = threadIdx.x;
    int r0 = blockIdx.x * 8;
    {
        float4* x4 = (float4*)Xs;
        if (tid < 256) {
            int row = tid >> 5, c4 = tid & 31;
            x4[row * 96 + c4] = *(const float4*)&g_nodes[(r0 + row) * 128 + c4 * 4];
        }
        int row = tid >> 6, c4 = tid & 63;
        x4[row * 96 + 32 + c4] = *(const float4*)&g_msgs[(r0 + row) * 256 + c4 * 4];
    }
    __syncthreads();
    mlp8<384>(Xs, Bs, Hs, red, W1, b1, gg, bb, tid);
    float o0, o1;
    gemm2_8(Hs, Bs, W2, tid, o0, o1);
    int col = tid & 127, rp = tid >> 7;
    g_nodes[(r0 + 2 * rp) * 128 + col]     = o0 + Xs[(2 * rp) * 384 + col] + b2[col];
    g_nodes[(r0 + 2 * rp + 1) * 128 + col] = o1 + Xs[(2 * rp + 1) * 384 + col] + b2[col];
}

// final output head; BM=8, grid 32
__global__ void __launch_bounds__(512, 1) k_final(
        const float* __restrict__ no1_w, const float* __restrict__ no1_b,
        const float* __restrict__ no_g,  const float* __restrict__ no_bt,
        const float* __restrict__ no2_w, const float* __restrict__ no2_b,
        const float* __restrict__ sp1_w, const float* __restrict__ sp1_b,
        const float* __restrict__ sp_g,  const float* __restrict__ sp_bt,
        const float* __restrict__ sp2_w, const float* __restrict__ sp2_b,
        float* __restrict__ out_nodes, float* __restrict__ out_coords) {
    extern __shared__ float smf[];
    float* Xs = smf;           // 1024
    float* Bs = Xs + 1024;     // 8192
    float* Hs = Bs + 8192;     // 4096
    float* X2 = Hs + 4096;     // 1024
    float* red = X2 + 1024;    // 32
    int tid = threadIdx.x;
    int r0 = blockIdx.x * 8;
    if (tid < 256) ((float4*)Xs)[tid] = *(const float4*)&g_nodes[r0 * 128 + tid * 4];
    __syncthreads();
    mlp8<128>(Xs, Bs, Hs, red, no1_w, no1_b, no_g, no_bt, tid);
    float o0, o1;
    gemm2_8(Hs, Bs, no2_w, tid, o0, o1);
    int col = tid & 127, rp = tid >> 7;
    float v0 = o0 + no2_b[col], v1 = o1 + no2_b[col];
    out_nodes[(r0 + 2 * rp) * 128 + col] = v0;
    out_nodes[(r0 + 2 * rp + 1) * 128 + col] = v1;
    X2[(2 * rp) * 128 + col] = v0;
    X2[(2 * rp + 1) * 128 + col] = v1;
    __syncthreads();
    mlp8<128>(X2, Bs, Hs, red, sp1_w, sp1_b, sp_g, sp_bt, tid);
    int g = tid >> 4;
    if (g < 24) {
        int row = g / 3, cc = g - row * 3;
        int l16 = tid & 15;
        float s = 0.f;
        for (int k = l16; k < 512; k += 16) s = fmaf(Hs[row * 512 + k], sp2_w[k * 3 + cc], s);
#pragma unroll
        for (int o = 8; o; o >>= 1) s += __shfl_xor_sync(0xffffffffu, s, o);
        if (l16 == 0) out_coords[(r0 + row) * 3 + cc] = s + sp2_b[cc];
    }
}

// ================= launcher =================
extern "C" void kernel_launch(void* const* d_in, const int* in_sizes, int n_in,
                              void* d_out, int out_size) {
    const float* nodes  = (const float*)d_in[0];
    const float* coords = (const float*)d_in[1];
    const float* ee_w   = (const float*)d_in[2];
    const float* ee_b   = (const float*)d_in[3];
    const float* ee_g   = (const float*)d_in[4];
    const float* ee_bt  = (const float*)d_in[5];
    const float* nu1_w  = (const float*)d_in[6];
    const float* nu1_b  = (const float*)d_in[7];
    const float* nu_g   = (const float*)d_in[8];
    const float* nu_bt  = (const float*)d_in[9];
    const float* nu2_w  = (const float*)d_in[10];
    const float* nu2_b  = (const float*)d_in[11];
    const float* eu1_w  = (const float*)d_in[12];
    const float* eu1_b  = (const float*)d_in[13];
    const float* eu_g   = (const float*)d_in[14];
    const float* eu_bt  = (const float*)d_in[15];
    const float* eu2_w  = (const float*)d_in[16];
    const float* eu2_b  = (const float*)d_in[17];
    const float* sp1_w  = (const float*)d_in[18];
    const float* sp1_b  = (const float*)d_in[19];
    const float* sp_g   = (const float*)d_in[20];
    const float* sp_bt  = (const float*)d_in[21];
    const float* sp2_w  = (const float*)d_in[22];
    const float* sp2_b  = (const float*)d_in[23];
    const float* no1_w  = (const float*)d_in[24];
    const float* no1_b  = (const float*)d_in[25];
    const float* no_g   = (const float*)d_in[26];
    const float* no_bt  = (const float*)d_in[27];
    const float* no2_w  = (const float*)d_in[28];
    const float* no2_b  = (const float*)d_in[29];
    float* out = (float*)d_out;

    const int SME = 171520;
    const int SMN = (3072 + 8192 + 4096 + 32) * 4;
    const int SMF = (1024 + 8192 + 4096 + 1024 + 32) * 4;
    cudaFuncSetAttribute(k_edge_mma, cudaFuncAttributeMaxDynamicSharedMemorySize, SME);
    cudaFuncSetAttribute(k_node,     cudaFuncAttributeMaxDynamicSharedMemorySize, SMN);
    cudaFuncSetAttribute(k_final,    cudaFuncAttributeMaxDynamicSharedMemorySize, SMF);

    k_prep_w<<<2048, 256>>>(eu1_w, eu2_w);
    k_copy_nodes<<<64, 512>>>(nodes);
    k_init_edges<<<8192, 256>>>(coords, ee_w, ee_b, ee_g, ee_bt);

    for (int l = 0; l < 4; l++) {
        k_msgs<<<8192, 256>>>();
        k_pq<<<dim3(64, 2), 512>>>(eu1_w + l*196608 + 65536,
                                   eu1_w + l*196608 + 131072);
        k_edge_mma<<<1024, 512, SME>>>(l, eu1_b + l*512, eu_g + l*512,
                                       eu_bt + l*512, eu2_b + l*128);
        k_node<<<32, 512, SMN>>>(nu1_w + l*196608, nu1_b + l*512,
                                 nu_g + l*512, nu_bt + l*512,
                                 nu2_w + l*65536, nu2_b + l*128);
    }
    k_final<<<32, 512, SMF>>>(no1_w, no1_b, no_g, no_bt, no2_w, no2_b,
                              sp1_w, sp1_b, sp_g, sp_bt, sp2_w, sp2_b,
                              out, out + 32768);
}

// round 6
// speedup vs baseline: 2.7335x; 1.1856x over previous
#include <cuda_runtime.h>
#include <cuda_bf16.h>
#include <cstdint>

#define EPSF 1e-5f
#define NND 256
#define DD  128
#define HH  512
#define NR  65536

// -------- scratch (device globals: allocation-free rule) --------
__device__ __align__(16) float g_edges[NR * DD];
__device__ float g_adj[NR];
__device__ float g_msgs[NR];
__device__ __align__(16) float g_nodes[NND * DD];
__device__ __align__(16) float g_P[NND * HH];
__device__ __align__(16) float g_Q[NND * HH];
// pre-swizzled bf16 weight tile images: [layer][chunk][128n][128k] hi/lo
__device__ __align__(16) __nv_bfloat16 g_W1h[262144];
__device__ __align__(16) __nv_bfloat16 g_W1l[262144];
__device__ __align__(16) __nv_bfloat16 g_W2h[262144];
__device__ __align__(16) __nv_bfloat16 g_W2l[262144];

// ================= low-level helpers =================
__device__ __forceinline__ uint32_t smem_to_u32(const void* p) {
    uint32_t a;
    asm("{ .reg .u64 t; cvta.to.shared.u64 t, %1; cvt.u32.u64 %0, t; }" : "=r"(a) : "l"(p));
    return a;
}
__device__ __forceinline__ void ldsm_x4(uint32_t* r, uint32_t addr) {
    asm volatile("ldmatrix.sync.aligned.m8n8.x4.shared.b16 {%0,%1,%2,%3}, [%4];"
        : "=r"(r[0]), "=r"(r[1]), "=r"(r[2]), "=r"(r[3]) : "r"(addr));
}
__device__ __forceinline__ void mma16816(float* c, const uint32_t* a, uint32_t b0, uint32_t b1) {
    asm volatile("mma.sync.aligned.m16n8k16.row.col.f32.bf16.bf16.f32 "
        "{%0,%1,%2,%3}, {%4,%5,%6,%7}, {%8,%9}, {%0,%1,%2,%3};"
        : "+f"(c[0]), "+f"(c[1]), "+f"(c[2]), "+f"(c[3])
        : "r"(a[0]), "r"(a[1]), "r"(a[2]), "r"(a[3]), "r"(b0), "r"(b1));
}
__device__ __forceinline__ void cpasync16(uint32_t dst, const void* src) {
    asm volatile("cp.async.cg.shared.global [%0], [%1], 16;" :: "r"(dst), "l"(src));
}
__device__ __forceinline__ void pack2(float a, float b, uint32_t& hi, uint32_t& lo) {
    __nv_bfloat16 ah = __float2bfloat16(a), bh = __float2bfloat16(b);
    float ar = a - __bfloat162float(ah), br = b - __bfloat162float(bh);
    __nv_bfloat16 al = __float2bfloat16(ar), bl = __float2bfloat16(br);
    hi = (uint32_t)__bfloat16_as_ushort(ah) | ((uint32_t)__bfloat16_as_ushort(bh) << 16);
    lo = (uint32_t)__bfloat16_as_ushort(al) | ((uint32_t)__bfloat16_as_ushort(bl) << 16);
}
// byte offset inside a [rows][128k] bf16 tile (256B/row, XOR-swizzled 16B chunks)
__device__ __host__ __forceinline__ uint32_t swz_off(int r, int k) {
    return (uint32_t)(r * 256 + ((((k >> 3) ^ (r & 7)) & 15) << 4) + (k & 7) * 2);
}

// ================= weight image prep =================
// Only layers 0..2 need edge weights (layer 3 edge update is dead code).
__global__ void k_prep_w(const float* __restrict__ eu1_w, const float* __restrict__ eu2_w) {
    int idx = blockIdx.x * 256 + threadIdx.x;     // 524288
    int e = idx & 16383;
    int chunk = (idx >> 14) & 3;
    int l = (idx >> 16) & 3;
    int which = idx >> 18;
    if (l == 3) return;
    int n = e >> 7, k = e & 127;
    float v;
    if (which == 0) v = eu1_w[l * 196608 + k * 512 + chunk * 128 + n];
    else            v = eu2_w[l * 65536 + (chunk * 128 + k) * 128 + n];
    __nv_bfloat16 h = __float2bfloat16(v);
    __nv_bfloat16 lo = __float2bfloat16(v - __bfloat162float(h));
    int dst = (l * 4 + chunk) * 16384 + (int)(swz_off(n, k) >> 1);
    if (which == 0) { g_W1h[dst] = h; g_W1l[dst] = lo; }
    else            { g_W2h[dst] = h; g_W2l[dst] = lo; }
}

// ================= init: copy nodes + edges embedding + adjacency =================
__global__ void k_init(const float* __restrict__ nodes_in,
                       const float* __restrict__ coords,
                       const float* __restrict__ w, const float* __restrict__ b,
                       const float* __restrict__ gg, const float* __restrict__ bb) {
    if (blockIdx.x < 64) {
        int t = blockIdx.x * 256 + threadIdx.x;
        g_nodes[t] = nodes_in[t];
        g_nodes[t + 16384] = nodes_in[t + 16384];
    }
    int warp = threadIdx.x >> 5, lane = threadIdx.x & 31;
    int row = blockIdx.x * 8 + warp;
    int i = row >> 8, j = row & 255;
    float dx = coords[i*3+0] - coords[j*3+0];
    float dy = coords[i*3+1] - coords[j*3+1];
    float dz = coords[i*3+2] - coords[j*3+2];
    float sq = dx*dx + dy*dy + dz*dz;
    float dist = sq > 0.f ? sqrtf(sq) : 0.f;
    if (lane == 0) g_adj[row] = (dist < 10.f) ? 1.f : 0.f;
    float e[4]; float s = 0.f, ss = 0.f;
#pragma unroll
    for (int t = 0; t < 4; t++) {
        int d = lane + 32*t;
        e[t] = dist * w[d] + b[d];
        s += e[t]; ss += e[t]*e[t];
    }
#pragma unroll
    for (int o = 16; o; o >>= 1) {
        s  += __shfl_xor_sync(0xffffffffu, s, o);
        ss += __shfl_xor_sync(0xffffffffu, ss, o);
    }
    float mean = s * (1.f/128.f);
    float var  = ss * (1.f/128.f) - mean*mean;
    float rs   = rsqrtf(var + EPSF);
#pragma unroll
    for (int t = 0; t < 4; t++) {
        int d = lane + 32*t;
        float v = (e[t]-mean)*rs*gg[d] + bb[d];
        g_edges[row*DD + d] = fmaxf(v, 0.f);
    }
}

// standalone msgs (used only for the last layer, where edge update is skipped)
__global__ void k_msgs() {
    int warp = threadIdx.x >> 5, lane = threadIdx.x & 31;
    int row = blockIdx.x * 8 + warp;
    int i = row >> 8;
    const float4* e4 = (const float4*)(g_edges + row*DD);
    const float4* n4 = (const float4*)(g_nodes + i*DD);
    float4 a = e4[lane], c = n4[lane];
    float s = a.x*c.x + a.y*c.y + a.z*c.z + a.w*c.w;
#pragma unroll
    for (int o = 16; o; o >>= 1) s += __shfl_xor_sync(0xffffffffu, s, o);
    if (lane == 0) g_msgs[row] = g_adj[row] * s;
}

// P = nodes @ W1e[128:256], Q = nodes @ W1e[256:384]; grid (64,2), 512 thr
__global__ void __launch_bounds__(512) k_pq(const float* __restrict__ Wp,
                                            const float* __restrict__ Wq) {
    __shared__ float xs[512];
    int tid = threadIdx.x;
    int r0 = blockIdx.x * 4;
    const float* __restrict__ W = blockIdx.y ? Wq : Wp;
    float* out = blockIdx.y ? g_Q : g_P;
    xs[tid] = g_nodes[r0 * 128 + tid];
    __syncthreads();
    float a0 = 0.f, a1 = 0.f, a2 = 0.f, a3 = 0.f;
#pragma unroll 8
    for (int k = 0; k < 128; k++) {
        float wv = W[k * 512 + tid];
        a0 = fmaf(xs[k],       wv, a0);
        a1 = fmaf(xs[128 + k], wv, a1);
        a2 = fmaf(xs[256 + k], wv, a2);
        a3 = fmaf(xs[384 + k], wv, a3);
    }
    out[(r0+0)*512 + tid] = a0;
    out[(r0+1)*512 + tid] = a1;
    out[(r0+2)*512 + tid] = a2;
    out[(r0+3)*512 + tid] = a3;
}

// ================= HMMA fused edge update (+ fused msgs) =================
// edges[64-row tile] += relu(LN(edges@W1a + P[i] + Q[j] + b1)) @ W2 + b2
// also writes g_msgs for these rows from the OLD edges (pre-update)
__global__ void __launch_bounds__(512, 1) k_edge_mma(int l,
        const float* __restrict__ b1, const float* __restrict__ gg,
        const float* __restrict__ bb, const float* __restrict__ b2) {
    extern __shared__ char sm[];
    const uint32_t S = smem_to_u32(sm);
    const int tid = threadIdx.x, lane = tid & 31;
    const int wM = (tid >> 5) & 1, wN = tid >> 6;
    const int row0 = blockIdx.x * 64;
    const int i = row0 >> 8, j0 = row0 & 255;

    const uint32_t AH = S, AL = S + 16384, BB = S + 32768;
    float* Pb   = (float*)(sm + 163840);
    float* Gam  = (float*)(sm + 165888);
    float* Bet  = (float*)(sm + 167936);
    float* B2s  = (float*)(sm + 169984);
    float* redS = (float*)(sm + 170496);
    float* redQ = (float*)(sm + 170752);
    float* meanS = (float*)(sm + 171008);
    float* rstdS = (float*)(sm + 171264);

    Pb[tid]  = g_P[i*512 + tid] + b1[tid];
    Gam[tid] = gg[tid];
    Bet[tid] = bb[tid];
    if (tid < 128) B2s[tid] = b2[tid];
    if (tid < 64) { redS[tid] = 0.f; redQ[tid] = 0.f; }

    auto fill = [&](int buf, const __nv_bfloat16* sH, const __nv_bfloat16* sL) {
        uint32_t dH = BB + (uint32_t)buf * 65536, dL = dH + 32768;
#pragma unroll
        for (int t = 0; t < 4; t++) {
            uint32_t byo = (uint32_t)(tid + t * 512) * 16;
            cpasync16(dH + byo, (const char*)sH + byo);
            cpasync16(dL + byo, (const char*)sL + byo);
        }
        asm volatile("cp.async.commit_group;" ::: "memory");
    };
    const __nv_bfloat16* W1Hb = g_W1h + l * 65536;
    const __nv_bfloat16* W1Lb = g_W1l + l * 65536;
    const __nv_bfloat16* W2Hb = g_W2h + l * 65536;
    const __nv_bfloat16* W2Lb = g_W2l + l * 65536;
    fill(0, W1Hb, W1Lb);
    fill(1, W1Hb + 16384, W1Lb + 16384);

    // A = edges tile -> bf16 hi/lo swizzled panels; fused msgs = adj*(edges . nodes[i])
#pragma unroll
    for (int t = 0; t < 4; t++) {
        int idx = tid + t * 512;                  // 0..2047
        int r = idx >> 5, c4 = idx & 31;
        int k0 = c4 * 4;
        float4 v = *(const float4*)&g_edges[(size_t)(row0 + r) * 128 + k0];
        float4 nv = *(const float4*)&g_nodes[(size_t)i * 128 + k0];
        float dot = v.x*nv.x + v.y*nv.y + v.z*nv.z + v.w*nv.w;
#pragma unroll
        for (int o = 16; o; o >>= 1) dot += __shfl_xor_sync(0xffffffffu, dot, o);
        if (lane == 0) g_msgs[row0 + r] = g_adj[row0 + r] * dot;
        uint32_t h0, l0, h1, l1;
        pack2(v.x, v.y, h0, l0);
        pack2(v.z, v.w, h1, l1);
        uint32_t off = swz_off(r, k0);
        *(uint2*)(sm + off)         = make_uint2(h0, h1);
        *(uint2*)(sm + 16384 + off) = make_uint2(l0, l1);
    }

    // ---- GEMM1: acc1 = A @ W1chunks (3-split) ----
    float acc1[4][2][2][4];
#pragma unroll
    for (int a = 0; a < 4; a++)
#pragma unroll
        for (int b = 0; b < 2; b++)
#pragma unroll
            for (int c = 0; c < 2; c++)
#pragma unroll
                for (int d = 0; d < 4; d++) acc1[a][b][c][d] = 0.f;

    const int aR  = wM * 32 + (lane & 15);
    const int aKx = lane >> 4;
    const int bR  = wN * 16 + (lane & 7) + ((lane & 16) >> 1);
    const int bKx = (lane & 8) >> 3;

#pragma unroll
    for (int nc = 0; nc < 4; nc++) {
        asm volatile("cp.async.wait_group 1;" ::: "memory");
        __syncthreads();
        uint32_t BH = BB + (uint32_t)(nc & 1) * 65536, BL = BH + 32768;
#pragma unroll
        for (int ks = 0; ks < 8; ks++) {
            uint32_t ah[2][4], al[2][4], bh[4], bl[4];
#pragma unroll
            for (int mt = 0; mt < 2; mt++) {
                int r = aR + mt * 16;
                uint32_t off = (uint32_t)r * 256 + (uint32_t)((((ks * 2 + aKx) ^ (r & 7)) & 15) << 4);
                ldsm_x4(ah[mt], AH + off);
                ldsm_x4(al[mt], AL + off);
            }
            {
                uint32_t off = (uint32_t)bR * 256 + (uint32_t)((((ks * 2 + bKx) ^ (bR & 7)) & 15) << 4);
                ldsm_x4(bh, BH + off);
                ldsm_x4(bl, BL + off);
            }
#pragma unroll
            for (int mt = 0; mt < 2; mt++) {
                mma16816(acc1[nc][mt][0], ah[mt], bh[0], bh[1]);
                mma16816(acc1[nc][mt][1], ah[mt], bh[2], bh[3]);
                mma16816(acc1[nc][mt][0], al[mt], bh[0], bh[1]);
                mma16816(acc1[nc][mt][1], al[mt], bh[2], bh[3]);
                mma16816(acc1[nc][mt][0], ah[mt], bl[0], bl[1]);
                mma16816(acc1[nc][mt][1], ah[mt], bl[2], bl[3]);
            }
        }
        __syncthreads();
        if (nc < 2) fill(nc & 1, W1Hb + (nc + 2) * 16384, W1Lb + (nc + 2) * 16384);
        else        fill(nc & 1, W2Hb + (nc - 2) * 16384, W2Lb + (nc - 2) * 16384);
    }

    // ---- epilogue: y = acc + P + Q, LN stats ----
    const int R = wM * 32 + (lane >> 2);
    const int colB = wN * 16 + (lane & 3) * 2;
    float s4[4] = {0.f, 0.f, 0.f, 0.f}, q4[4] = {0.f, 0.f, 0.f, 0.f};
#pragma unroll
    for (int nc = 0; nc < 4; nc++)
#pragma unroll
        for (int mt = 0; mt < 2; mt++)
#pragma unroll
            for (int nt = 0; nt < 2; nt++) {
                int col = nc * 128 + colB + nt * 8;
                int rA = j0 + R + mt * 16;
                float2 qa = *(const float2*)&g_Q[(size_t)rA * 512 + col];
                float2 qb = *(const float2*)&g_Q[(size_t)(rA + 8) * 512 + col];
                float p0 = Pb[col], p1 = Pb[col + 1];
                float* a = acc1[nc][mt][nt];
                a[0] += p0 + qa.x; a[1] += p1 + qa.y;
                a[2] += p0 + qb.x; a[3] += p1 + qb.y;
                s4[mt*2+0] += a[0] + a[1]; q4[mt*2+0] += a[0]*a[0] + a[1]*a[1];
                s4[mt*2+1] += a[2] + a[3]; q4[mt*2+1] += a[2]*a[2] + a[3]*a[3];
            }
#pragma unroll
    for (int o = 1; o <= 2; o <<= 1)
#pragma unroll
        for (int t = 0; t < 4; t++) {
            s4[t] += __shfl_xor_sync(0xffffffffu, s4[t], o);
            q4[t] += __shfl_xor_sync(0xffffffffu, q4[t], o);
        }
    if ((lane & 3) == 0) {
#pragma unroll
        for (int t = 0; t < 4; t++) {
            int rr = R + (t >> 1) * 16 + (t & 1) * 8;
            atomicAdd(&redS[rr], s4[t]);
            atomicAdd(&redQ[rr], q4[t]);
        }
    }
    __syncthreads();
    if (tid < 64) {
        float mean = redS[tid] * (1.f / 512.f);
        float var = redQ[tid] * (1.f / 512.f) - mean * mean;
        meanS[tid] = mean;
        rstdS[tid] = rsqrtf(var + EPSF);
    }
    __syncthreads();
    float mn[4], rs[4];
#pragma unroll
    for (int t = 0; t < 4; t++) {
        int rr = R + (t >> 1) * 16 + (t & 1) * 8;
        mn[t] = meanS[rr]; rs[t] = rstdS[rr];
    }

    // ---- GEMM2: out = relu(LN(y)) @ W2 (h staged per k-chunk in A panels) ----
    float acc2[2][2][4];
#pragma unroll
    for (int b = 0; b < 2; b++)
#pragma unroll
        for (int c = 0; c < 2; c++)
#pragma unroll
            for (int d = 0; d < 4; d++) acc2[b][c][d] = 0.f;

#pragma unroll
    for (int kc = 0; kc < 4; kc++) {
        if (kc == 3) asm volatile("cp.async.wait_group 0;" ::: "memory");
        else         asm volatile("cp.async.wait_group 1;" ::: "memory");
#pragma unroll
        for (int mt = 0; mt < 2; mt++)
#pragma unroll
            for (int nt = 0; nt < 2; nt++) {
                int col = kc * 128 + colB + nt * 8;
                float g0 = Gam[col], g1 = Gam[col + 1];
                float be0 = Bet[col], be1 = Bet[col + 1];
                float* a = acc1[kc][mt][nt];
                float h0 = fmaxf((a[0] - mn[mt*2])   * rs[mt*2]   * g0 + be0, 0.f);
                float h1 = fmaxf((a[1] - mn[mt*2])   * rs[mt*2]   * g1 + be1, 0.f);
                float h2 = fmaxf((a[2] - mn[mt*2+1]) * rs[mt*2+1] * g0 + be0, 0.f);
                float h3 = fmaxf((a[3] - mn[mt*2+1]) * rs[mt*2+1] * g1 + be1, 0.f);
                uint32_t hh0, ll0, hh1, ll1;
                pack2(h0, h1, hh0, ll0);
                pack2(h2, h3, hh1, ll1);
                int kl = colB + nt * 8;
                int r1 = R + mt * 16, r2 = r1 + 8;
                uint32_t o1 = swz_off(r1, kl), o2 = swz_off(r2, kl);
                *(uint32_t*)(sm + o1) = hh0; *(uint32_t*)(sm + 16384 + o1) = ll0;
                *(uint32_t*)(sm + o2) = hh1; *(uint32_t*)(sm + 16384 + o2) = ll1;
            }
        __syncthreads();
        uint32_t BH = BB + (uint32_t)(kc & 1) * 65536, BL = BH + 32768;
#pragma unroll
        for (int ks = 0; ks < 8; ks++) {
            uint32_t ah[2][4], al[2][4], bh[4], bl[4];
#pragma unroll
            for (int mt = 0; mt < 2; mt++) {
                int r = aR + mt * 16;
                uint32_t off = (uint32_t)r * 256 + (uint32_t)((((ks * 2 + aKx) ^ (r & 7)) & 15) << 4);
                ldsm_x4(ah[mt], AH + off);
                ldsm_x4(al[mt], AL + off);
            }
            {
                uint32_t off = (uint32_t)bR * 256 + (uint32_t)((((ks * 2 + bKx) ^ (bR & 7)) & 15) << 4);
                ldsm_x4(bh, BH + off);
                ldsm_x4(bl, BL + off);
            }
#pragma unroll
            for (int mt = 0; mt < 2; mt++) {
                mma16816(acc2[mt][0], ah[mt], bh[0], bh[1]);
                mma16816(acc2[mt][1], ah[mt], bh[2], bh[3]);
                mma16816(acc2[mt][0], al[mt], bh[0], bh[1]);
                mma16816(acc2[mt][1], al[mt], bh[2], bh[3]);
                mma16816(acc2[mt][0], ah[mt], bl[0], bl[1]);
                mma16816(acc2[mt][1], ah[mt], bl[2], bl[3]);
            }
        }
        __syncthreads();
        if (kc < 2) fill(kc & 1, W2Hb + (kc + 2) * 16384, W2Lb + (kc + 2) * 16384);
    }

    // ---- output: acc2 + residual + b2 ----
#pragma unroll
    for (int mt = 0; mt < 2; mt++)
#pragma unroll
        for (int nt = 0; nt < 2; nt++) {
            int col = colB + nt * 8;
            int r1 = row0 + R + mt * 16;
            float b20 = B2s[col], b21 = B2s[col + 1];
            float2 e0 = *(const float2*)&g_edges[(size_t)r1 * 128 + col];
            float2 e1 = *(const float2*)&g_edges[(size_t)(r1 + 8) * 128 + col];
            float* a = acc2[mt][nt];
            *(float2*)&g_edges[(size_t)r1 * 128 + col]       = make_float2(a[0] + e0.x + b20, a[1] + e0.y + b21);
            *(float2*)&g_edges[(size_t)(r1 + 8) * 128 + col] = make_float2(a[2] + e1.x + b20, a[3] + e1.y + b21);
        }
}

// ================= BM=8 FFMA MLP blocks (node update / final) =================
template<int KD>
__device__ __forceinline__ void mlp8(const float* Xs, float* Bs, float* Hs, float* red,
        const float* __restrict__ W1, const float* __restrict__ b1,
        const float* __restrict__ gg, const float* __restrict__ bb, int tid) {
    int tr = tid >> 6, tc = tid & 63, c0 = tc * 8;
    float acc[8];
#pragma unroll
    for (int n = 0; n < 8; n++) acc[n] = 0.f;
    for (int kt = 0; kt < KD / 16; kt++) {
        float4* b4 = (float4*)Bs;
#pragma unroll
        for (int t = 0; t < 4; t++) {
            int idx = tid + t * 512;
            b4[idx] = *(const float4*)&W1[kt * 8192 + idx * 4];
        }
        __syncthreads();
#pragma unroll
        for (int k = 0; k < 16; k++) {
            float a = Xs[tr * KD + kt * 16 + k];
            const float* br = &Bs[k * 512 + c0];
#pragma unroll
            for (int n = 0; n < 8; n++) acc[n] = fmaf(a, br[n], acc[n]);
        }
        __syncthreads();
    }
    float s = 0.f, q = 0.f;
#pragma unroll
    for (int n = 0; n < 8; n++) {
        float y = acc[n] + b1[c0 + n];
        acc[n] = y; s += y; q += y * y;
    }
#pragma unroll
    for (int o = 16; o; o >>= 1) {
        s += __shfl_xor_sync(0xffffffffu, s, o);
        q += __shfl_xor_sync(0xffffffffu, q, o);
    }
    int wid = tid >> 5;
    if ((tid & 31) == 0) { red[wid] = s; red[16 + wid] = q; }
    __syncthreads();
    {
        float S = red[2 * tr] + red[2 * tr + 1];
        float Q2 = red[16 + 2 * tr] + red[16 + 2 * tr + 1];
        float mean = S * (1.f / 512.f);
        float var = Q2 * (1.f / 512.f) - mean * mean;
        float rstd = rsqrtf(var + EPSF);
#pragma unroll
        for (int n = 0; n < 8; n++)
            Hs[tr * 512 + c0 + n] = fmaxf((acc[n] - mean) * rstd * gg[c0 + n] + bb[c0 + n], 0.f);
    }
    __syncthreads();
}

__device__ __forceinline__ void gemm2_8(const float* Hs, float* Bs,
        const float* __restrict__ W2, int tid, float& o0, float& o1) {
    int col = tid & 127, rp = tid >> 7;
    o0 = 0.f; o1 = 0.f;
    for (int kt = 0; kt < 32; kt++) {
        ((float4*)Bs)[tid] = *(const float4*)&W2[kt * 2048 + tid * 4];
        __syncthreads();
#pragma unroll
        for (int k = 0; k < 16; k++) {
            float w = Bs[k * 128 + col];
            o0 = fmaf(Hs[(2 * rp) * 512 + kt * 16 + k], w, o0);
            o1 = fmaf(Hs[(2 * rp + 1) * 512 + kt * 16 + k], w, o1);
        }
        __syncthreads();
    }
}

// node update: nodes += relu(LN([nodes|msgs]@W1+b1))@W2+b2 ; BM=8, grid 32
__global__ void __launch_bounds__(512, 1) k_node(
        const float* __restrict__ W1, const float* __restrict__ b1,
        const float* __restrict__ gg, const float* __restrict__ bb,
        const float* __restrict__ W2, const float* __restrict__ b2) {
    extern __shared__ float smf[];
    float* Xs = smf;            // 8*384 = 3072
    float* Bs = Xs + 3072;      // 8192
    float* Hs = Bs + 8192;      // 4096
    float* red = Hs + 4096;     // 32
    int tid = threadIdx.x;
    int r0 = blockIdx.x * 8;
    {
        float4* x4 = (float4*)Xs;
        if (tid < 256) {
            int row = tid >> 5, c4 = tid & 31;
            x4[row * 96 + c4] = *(const float4*)&g_nodes[(r0 + row) * 128 + c4 * 4];
        }
        int row = tid >> 6, c4 = tid & 63;
        x4[row * 96 + 32 + c4] = *(const float4*)&g_msgs[(r0 + row) * 256 + c4 * 4];
    }
    __syncthreads();
    mlp8<384>(Xs, Bs, Hs, red, W1, b1, gg, bb, tid);
    float o0, o1;
    gemm2_8(Hs, Bs, W2, tid, o0, o1);
    int col = tid & 127, rp = tid >> 7;
    g_nodes[(r0 + 2 * rp) * 128 + col]     = o0 + Xs[(2 * rp) * 384 + col] + b2[col];
    g_nodes[(r0 + 2 * rp + 1) * 128 + col] = o1 + Xs[(2 * rp + 1) * 384 + col] + b2[col];
}

// final output head; BM=8, grid 32
__global__ void __launch_bounds__(512, 1) k_final(
        const float* __restrict__ no1_w, const float* __restrict__ no1_b,
        const float* __restrict__ no_g,  const float* __restrict__ no_bt,
        const float* __restrict__ no2_w, const float* __restrict__ no2_b,
        const float* __restrict__ sp1_w, const float* __restrict__ sp1_b,
        const float* __restrict__ sp_g,  const float* __restrict__ sp_bt,
        const float* __restrict__ sp2_w, const float* __restrict__ sp2_b,
        float* __restrict__ out_nodes, float* __restrict__ out_coords) {
    extern __shared__ float smf[];
    float* Xs = smf;           // 1024
    float* Bs = Xs + 1024;     // 8192
    float* Hs = Bs + 8192;     // 4096
    float* X2 = Hs + 4096;     // 1024
    float* red = X2 + 1024;    // 32
    int tid = threadIdx.x;
    int r0 = blockIdx.x * 8;
    if (tid < 256) ((float4*)Xs)[tid] = *(const float4*)&g_nodes[r0 * 128 + tid * 4];
    __syncthreads();
    mlp8<128>(Xs, Bs, Hs, red, no1_w, no1_b, no_g, no_bt, tid);
    float o0, o1;
    gemm2_8(Hs, Bs, no2_w, tid, o0, o1);
    int col = tid & 127, rp = tid >> 7;
    float v0 = o0 + no2_b[col], v1 = o1 + no2_b[col];
    out_nodes[(r0 + 2 * rp) * 128 + col] = v0;
    out_nodes[(r0 + 2 * rp + 1) * 128 + col] = v1;
    X2[(2 * rp) * 128 + col] = v0;
    X2[(2 * rp + 1) * 128 + col] = v1;
    __syncthreads();
    mlp8<128>(X2, Bs, Hs, red, sp1_w, sp1_b, sp_g, sp_bt, tid);
    int g = tid >> 4;
    if (g < 24) {
        int row = g / 3, cc = g - row * 3;
        int l16 = tid & 15;
        float s = 0.f;
        for (int k = l16; k < 512; k += 16) s = fmaf(Hs[row * 512 + k], sp2_w[k * 3 + cc], s);
#pragma unroll
        for (int o = 8; o; o >>= 1) s += __shfl_xor_sync(0xffffffffu, s, o);
        if (l16 == 0) out_coords[(r0 + row) * 3 + cc] = s + sp2_b[cc];
    }
}

// ================= launcher =================
extern "C" void kernel_launch(void* const* d_in, const int* in_sizes, int n_in,
                              void* d_out, int out_size) {
    const float* nodes  = (const float*)d_in[0];
    const float* coords = (const float*)d_in[1];
    const float* ee_w   = (const float*)d_in[2];
    const float* ee_b   = (const float*)d_in[3];
    const float* ee_g   = (const float*)d_in[4];
    const float* ee_bt  = (const float*)d_in[5];
    const float* nu1_w  = (const float*)d_in[6];
    const float* nu1_b  = (const float*)d_in[7];
    const float* nu_g   = (const float*)d_in[8];
    const float* nu_bt  = (const float*)d_in[9];
    const float* nu2_w  = (const float*)d_in[10];
    const float* nu2_b  = (const float*)d_in[11];
    const float* eu1_w  = (const float*)d_in[12];
    const float* eu1_b  = (const float*)d_in[13];
    const float* eu_g   = (const float*)d_in[14];
    const float* eu_bt  = (const float*)d_in[15];
    const float* eu2_w  = (const float*)d_in[16];
    const float* eu2_b  = (const float*)d_in[17];
    const float* sp1_w  = (const float*)d_in[18];
    const float* sp1_b  = (const float*)d_in[19];
    const float* sp_g   = (const float*)d_in[20];
    const float* sp_bt  = (const float*)d_in[21];
    const float* sp2_w  = (const float*)d_in[22];
    const float* sp2_b  = (const float*)d_in[23];
    const float* no1_w  = (const float*)d_in[24];
    const float* no1_b  = (const float*)d_in[25];
    const float* no_g   = (const float*)d_in[26];
    const float* no_bt  = (const float*)d_in[27];
    const float* no2_w  = (const float*)d_in[28];
    const float* no2_b  = (const float*)d_in[29];
    float* out = (float*)d_out;

    const int SME = 171520;
    const int SMN = (3072 + 8192 + 4096 + 32) * 4;
    const int SMF = (1024 + 8192 + 4096 + 1024 + 32) * 4;
    cudaFuncSetAttribute(k_edge_mma, cudaFuncAttributeMaxDynamicSharedMemorySize, SME);
    cudaFuncSetAttribute(k_node,     cudaFuncAttributeMaxDynamicSharedMemorySize, SMN);
    cudaFuncSetAttribute(k_final,    cudaFuncAttributeMaxDynamicSharedMemorySize, SMF);

    k_prep_w<<<2048, 256>>>(eu1_w, eu2_w);                      // launch 0
    k_init<<<8192, 256>>>(nodes, coords, ee_w, ee_b, ee_g, ee_bt);  // launch 1

    for (int l = 0; l < 3; l++) {
        k_pq<<<dim3(64, 2), 512>>>(eu1_w + l*196608 + 65536,    // launch 2 (l=0)
                                   eu1_w + l*196608 + 131072);
        k_edge_mma<<<1024, 512, SME>>>(l, eu1_b + l*512, eu_g + l*512,   // launch 3 (l=0)
                                       eu_bt + l*512, eu2_b + l*128);
        k_node<<<32, 512, SMN>>>(nu1_w + l*196608, nu1_b + l*512,
                                 nu_g + l*512, nu_bt + l*512,
                                 nu2_w + l*65536, nu2_b + l*128);
    }
    // layer 3: edge output is dead code (scan discards final edges) — msgs only
    k_msgs<<<8192, 256>>>();
    k_node<<<32, 512, SMN>>>(nu1_w + 3*196608, nu1_b + 3*512,
                             nu_g + 3*512, nu_bt + 3*512,
                             nu2_w + 3*65536, nu2_b + 3*128);
    k_final<<<32, 512, SMF>>>(no1_w, no1_b, no_g, no_bt, no2_w, no2_b,
                              sp1_w, sp1_b, sp_g, sp_bt, sp2_w, sp2_b,
                              out, out + 32768);
}

// round 7
// speedup vs baseline: 2.9512x; 1.0796x over previous
#include <cuda_runtime.h>
#include <cuda_bf16.h>
#include <cstdint>

#define EPSF 1e-5f
#define NND 256
#define DD  128
#define HH  512
#define NR  65536

// -------- scratch (device globals: allocation-free rule) --------
__device__ __align__(16) float g_edges[NR * DD];
__device__ float g_adj[NR];
__device__ float g_msgs[NR];
__device__ __align__(16) float g_nodes[NND * DD];
__device__ __align__(16) float g_P[NND * HH];
__device__ __align__(16) float g_Q[NND * HH];
// pre-swizzled bf16 weight tile images: [layer][chunk][128n][128k] hi/lo (layers 0..2)
__device__ __align__(16) __nv_bfloat16 g_W1h[262144];
__device__ __align__(16) __nv_bfloat16 g_W1l[262144];
__device__ __align__(16) __nv_bfloat16 g_W2h[262144];
__device__ __align__(16) __nv_bfloat16 g_W2l[262144];

// ================= low-level helpers =================
__device__ __forceinline__ uint32_t smem_to_u32(const void* p) {
    uint32_t a;
    asm("{ .reg .u64 t; cvta.to.shared.u64 t, %1; cvt.u32.u64 %0, t; }" : "=r"(a) : "l"(p));
    return a;
}
__device__ __forceinline__ void ldsm_x4(uint32_t* r, uint32_t addr) {
    asm volatile("ldmatrix.sync.aligned.m8n8.x4.shared.b16 {%0,%1,%2,%3}, [%4];"
        : "=r"(r[0]), "=r"(r[1]), "=r"(r[2]), "=r"(r[3]) : "r"(addr));
}
__device__ __forceinline__ void mma16816(float* c, const uint32_t* a, uint32_t b0, uint32_t b1) {
    asm volatile("mma.sync.aligned.m16n8k16.row.col.f32.bf16.bf16.f32 "
        "{%0,%1,%2,%3}, {%4,%5,%6,%7}, {%8,%9}, {%0,%1,%2,%3};"
        : "+f"(c[0]), "+f"(c[1]), "+f"(c[2]), "+f"(c[3])
        : "r"(a[0]), "r"(a[1]), "r"(a[2]), "r"(a[3]), "r"(b0), "r"(b1));
}
__device__ __forceinline__ void cpasync16(uint32_t dst, const void* src) {
    asm volatile("cp.async.cg.shared.global [%0], [%1], 16;" :: "r"(dst), "l"(src));
}
#define CP_COMMIT() asm volatile("cp.async.commit_group;" ::: "memory")
#define CP_WAIT1()  asm volatile("cp.async.wait_group 1;" ::: "memory")
__device__ __forceinline__ void pair_bar(int wN) {
    asm volatile("bar.sync %0, 64;" :: "r"(1 + wN) : "memory");
}
__device__ __forceinline__ void pack2(float a, float b, uint32_t& hi, uint32_t& lo) {
    __nv_bfloat16 ah = __float2bfloat16(a), bh = __float2bfloat16(b);
    float ar = a - __bfloat162float(ah), br = b - __bfloat162float(bh);
    __nv_bfloat16 al = __float2bfloat16(ar), bl = __float2bfloat16(br);
    hi = (uint32_t)__bfloat16_as_ushort(ah) | ((uint32_t)__bfloat16_as_ushort(bh) << 16);
    lo = (uint32_t)__bfloat16_as_ushort(al) | ((uint32_t)__bfloat16_as_ushort(bl) << 16);
}
// byte offset inside a [rows][128k] bf16 tile (256B/row, XOR-swizzled 16B chunks)
__device__ __host__ __forceinline__ uint32_t swz_off(int r, int k) {
    return (uint32_t)(r * 256 + ((((k >> 3) ^ (r & 7)) & 15) << 4) + (k & 7) * 2);
}

// ================= weight image prep (layers 0..2 only) =================
__global__ void k_prep_w(const float* __restrict__ eu1_w, const float* __restrict__ eu2_w) {
    int idx = blockIdx.x * 256 + threadIdx.x;     // < 393216
    int which = idx / 196608;
    int rem = idx - which * 196608;
    int l = rem >> 16;
    int e = rem & 65535;
    int chunk = e >> 14;
    int e2 = e & 16383;
    int n = e2 >> 7, k = e2 & 127;
    float v;
    if (which == 0) v = eu1_w[l * 196608 + k * 512 + chunk * 128 + n];
    else            v = eu2_w[l * 65536 + (chunk * 128 + k) * 128 + n];
    __nv_bfloat16 h = __float2bfloat16(v);
    __nv_bfloat16 lo = __float2bfloat16(v - __bfloat162float(h));
    int dst = (l * 4 + chunk) * 16384 + (int)(swz_off(n, k) >> 1);
    if (which == 0) { g_W1h[dst] = h; g_W1l[dst] = lo; }
    else            { g_W2h[dst] = h; g_W2l[dst] = lo; }
}

// ================= init: copy nodes + edges embedding + adjacency =================
__global__ void k_init(const float* __restrict__ nodes_in,
                       const float* __restrict__ coords,
                       const float* __restrict__ w, const float* __restrict__ b,
                       const float* __restrict__ gg, const float* __restrict__ bb) {
    if (blockIdx.x < 64) {
        int t = blockIdx.x * 256 + threadIdx.x;
        g_nodes[t] = nodes_in[t];
        g_nodes[t + 16384] = nodes_in[t + 16384];
    }
    int warp = threadIdx.x >> 5, lane = threadIdx.x & 31;
    int row = blockIdx.x * 8 + warp;
    int i = row >> 8, j = row & 255;
    float dx = coords[i*3+0] - coords[j*3+0];
    float dy = coords[i*3+1] - coords[j*3+1];
    float dz = coords[i*3+2] - coords[j*3+2];
    float sq = dx*dx + dy*dy + dz*dz;
    float dist = sq > 0.f ? sqrtf(sq) : 0.f;
    if (lane == 0) g_adj[row] = (dist < 10.f) ? 1.f : 0.f;
    float e[4]; float s = 0.f, ss = 0.f;
#pragma unroll
    for (int t = 0; t < 4; t++) {
        int d = lane + 32*t;
        e[t] = dist * w[d] + b[d];
        s += e[t]; ss += e[t]*e[t];
    }
#pragma unroll
    for (int o = 16; o; o >>= 1) {
        s  += __shfl_xor_sync(0xffffffffu, s, o);
        ss += __shfl_xor_sync(0xffffffffu, ss, o);
    }
    float mean = s * (1.f/128.f);
    float var  = ss * (1.f/128.f) - mean*mean;
    float rs   = rsqrtf(var + EPSF);
#pragma unroll
    for (int t = 0; t < 4; t++) {
        int d = lane + 32*t;
        float v = (e[t]-mean)*rs*gg[d] + bb[d];
        g_edges[row*DD + d] = fmaxf(v, 0.f);
    }
}

// standalone msgs (used only for the last layer)
__global__ void k_msgs() {
    int warp = threadIdx.x >> 5, lane = threadIdx.x & 31;
    int row = blockIdx.x * 8 + warp;
    int i = row >> 8;
    const float4* e4 = (const float4*)(g_edges + row*DD);
    const float4* n4 = (const float4*)(g_nodes + i*DD);
    float4 a = e4[lane], c = n4[lane];
    float s = a.x*c.x + a.y*c.y + a.z*c.z + a.w*c.w;
#pragma unroll
    for (int o = 16; o; o >>= 1) s += __shfl_xor_sync(0xffffffffu, s, o);
    if (lane == 0) g_msgs[row] = g_adj[row] * s;
}

// P/Q for layer 0 (from initial nodes); grid (64,2), 512 thr
__global__ void __launch_bounds__(512) k_pq(const float* __restrict__ Wp,
                                            const float* __restrict__ Wq) {
    __shared__ float xs[512];
    int tid = threadIdx.x;
    int r0 = blockIdx.x * 4;
    const float* __restrict__ W = blockIdx.y ? Wq : Wp;
    float* out = blockIdx.y ? g_Q : g_P;
    xs[tid] = g_nodes[r0 * 128 + tid];
    __syncthreads();
    float a0 = 0.f, a1 = 0.f, a2 = 0.f, a3 = 0.f;
#pragma unroll 8
    for (int k = 0; k < 128; k++) {
        float wv = W[k * 512 + tid];
        a0 = fmaf(xs[k],       wv, a0);
        a1 = fmaf(xs[128 + k], wv, a1);
        a2 = fmaf(xs[256 + k], wv, a2);
        a3 = fmaf(xs[384 + k], wv, a3);
    }
    out[(r0+0)*512 + tid] = a0;
    out[(r0+1)*512 + tid] = a1;
    out[(r0+2)*512 + tid] = a2;
    out[(r0+3)*512 + tid] = a3;
}

// ================= HMMA fused edge update (+ fused msgs) =================
// smem: panels 2x32KB @0 (hi 16K + lo 16K each), B 2x64KB @65536, params @196608
__global__ void __launch_bounds__(512, 1) k_edge_mma(int l,
        const float* __restrict__ b1, const float* __restrict__ gg,
        const float* __restrict__ bb, const float* __restrict__ b2) {
    extern __shared__ char sm[];
    const uint32_t S = smem_to_u32(sm);
    const int tid = threadIdx.x, lane = tid & 31;
    const int wM = (tid >> 5) & 1, wN = tid >> 6;
    const int row0 = blockIdx.x * 64;
    const int i = row0 >> 8, j0 = row0 & 255;

    const uint32_t PAN = S;               // 2 panels x 32KB
    const uint32_t BBs = S + 65536;       // 2 bufs x 64KB
    float* Pb    = (float*)(sm + 196608);
    float* Gam   = (float*)(sm + 198656);
    float* Bet   = (float*)(sm + 200704);
    float* B2s   = (float*)(sm + 202752);
    float* redS  = (float*)(sm + 203264);
    float* redQ  = (float*)(sm + 203520);
    float* meanS = (float*)(sm + 203776);
    float* rstdS = (float*)(sm + 204032);

    Pb[tid]  = g_P[i*512 + tid] + b1[tid];
    Gam[tid] = gg[tid];
    Bet[tid] = bb[tid];
    if (tid < 128) B2s[tid] = b2[tid];
    if (tid < 64) { redS[tid] = 0.f; redQ[tid] = 0.f; }

    // per-pair slice fill: pair wN owns B rows [wN*16, wN*16+16) = 4KB in hi and lo
    const int pid = tid & 63;
    auto fillw = [&](int buf, const __nv_bfloat16* sH, const __nv_bfloat16* sL) {
        uint32_t dH = BBs + (uint32_t)buf * 65536 + (uint32_t)wN * 4096;
        uint32_t dL = dH + 32768;
        const char* gH = (const char*)sH + wN * 4096;
        const char* gL = (const char*)sL + wN * 4096;
#pragma unroll
        for (int t = 0; t < 4; t++) {
            uint32_t byo = (uint32_t)(pid + t * 64) * 16;
            cpasync16(dH + byo, gH + byo);
            cpasync16(dL + byo, gL + byo);
        }
        CP_COMMIT();
    };
    const __nv_bfloat16* W1Hb = g_W1h + l * 65536;
    const __nv_bfloat16* W1Lb = g_W1l + l * 65536;
    const __nv_bfloat16* W2Hb = g_W2h + l * 65536;
    const __nv_bfloat16* W2Lb = g_W2l + l * 65536;
    fillw(0, W1Hb, W1Lb);
    fillw(1, W1Hb + 16384, W1Lb + 16384);

    // A = edges tile -> bf16 hi/lo panel 0; fused msgs from OLD edges
    {
        const int c4 = tid & 31, k0 = c4 * 4, rb = tid >> 5;
        const float4 nv = *(const float4*)&g_nodes[(size_t)i * 128 + k0];
        float4 v[4];
#pragma unroll
        for (int t = 0; t < 4; t++)
            v[t] = *(const float4*)&g_edges[(size_t)(row0 + rb + t * 16) * 128 + k0];
#pragma unroll
        for (int t = 0; t < 4; t++) {
            int r = rb + t * 16;
            float dot = v[t].x*nv.x + v[t].y*nv.y + v[t].z*nv.z + v[t].w*nv.w;
#pragma unroll
            for (int o = 16; o; o >>= 1) dot += __shfl_xor_sync(0xffffffffu, dot, o);
            if (lane == 0) g_msgs[row0 + r] = g_adj[row0 + r] * dot;
            uint32_t h0, l0, h1, l1;
            pack2(v[t].x, v[t].y, h0, l0);
            pack2(v[t].z, v[t].w, h1, l1);
            uint32_t off = swz_off(r, k0);
            *(uint2*)(sm + off)         = make_uint2(h0, h1);
            *(uint2*)(sm + 16384 + off) = make_uint2(l0, l1);
        }
    }
    __syncthreads();   // A panel 0 + params visible to all

    // ---- GEMM1 ----
    float acc1[4][2][2][4];
#pragma unroll
    for (int a = 0; a < 4; a++)
#pragma unroll
        for (int b = 0; b < 2; b++)
#pragma unroll
            for (int c = 0; c < 2; c++)
#pragma unroll
                for (int d = 0; d < 4; d++) acc1[a][b][c][d] = 0.f;

    const int aR  = wM * 32 + (lane & 15);
    const int aKx = lane >> 4;
    const int bR  = wN * 16 + (lane & 7) + ((lane & 16) >> 1);
    const int bKx = (lane & 8) >> 3;

#pragma unroll
    for (int nc = 0; nc < 4; nc++) {
        CP_WAIT1();
        pair_bar(wN);
        uint32_t BH = BBs + (uint32_t)(nc & 1) * 65536, BL = BH + 32768;
#pragma unroll
        for (int ks = 0; ks < 8; ks++) {
            uint32_t ah[2][4], al[2][4], bh[4], bl[4];
#pragma unroll
            for (int mt = 0; mt < 2; mt++) {
                int r = aR + mt * 16;
                uint32_t off = (uint32_t)r * 256 + (uint32_t)((((ks * 2 + aKx) ^ (r & 7)) & 15) << 4);
                ldsm_x4(ah[mt], PAN + off);
                ldsm_x4(al[mt], PAN + 16384 + off);
            }
            {
                uint32_t off = (uint32_t)bR * 256 + (uint32_t)((((ks * 2 + bKx) ^ (bR & 7)) & 15) << 4);
                ldsm_x4(bh, BH + off);
                ldsm_x4(bl, BL + off);
            }
#pragma unroll
            for (int mt = 0; mt < 2; mt++) {
                mma16816(acc1[nc][mt][0], ah[mt], bh[0], bh[1]);
                mma16816(acc1[nc][mt][1], ah[mt], bh[2], bh[3]);
            }
#pragma unroll
            for (int mt = 0; mt < 2; mt++) {
                mma16816(acc1[nc][mt][0], al[mt], bh[0], bh[1]);
                mma16816(acc1[nc][mt][1], al[mt], bh[2], bh[3]);
            }
#pragma unroll
            for (int mt = 0; mt < 2; mt++) {
                mma16816(acc1[nc][mt][0], ah[mt], bl[0], bl[1]);
                mma16816(acc1[nc][mt][1], ah[mt], bl[2], bl[3]);
            }
        }
        pair_bar(wN);
        if (nc < 2) fillw(nc & 1, W1Hb + (nc + 2) * 16384, W1Lb + (nc + 2) * 16384);
        else        fillw(nc & 1, W2Hb + (nc - 2) * 16384, W2Lb + (nc - 2) * 16384);
    }

    // ---- epilogue: y = acc + P + Q, LN stats ----
    const int R = wM * 32 + (lane >> 2);
    const int colB = wN * 16 + (lane & 3) * 2;
    float s4[4] = {0.f, 0.f, 0.f, 0.f}, q4[4] = {0.f, 0.f, 0.f, 0.f};
#pragma unroll
    for (int nc = 0; nc < 4; nc++)
#pragma unroll
        for (int mt = 0; mt < 2; mt++)
#pragma unroll
            for (int nt = 0; nt < 2; nt++) {
                int col = nc * 128 + colB + nt * 8;
                int rA = j0 + R + mt * 16;
                float2 qa = *(const float2*)&g_Q[(size_t)rA * 512 + col];
                float2 qb = *(const float2*)&g_Q[(size_t)(rA + 8) * 512 + col];
                float p0 = Pb[col], p1 = Pb[col + 1];
                float* a = acc1[nc][mt][nt];
                a[0] += p0 + qa.x; a[1] += p1 + qa.y;
                a[2] += p0 + qb.x; a[3] += p1 + qb.y;
                s4[mt*2+0] += a[0] + a[1]; q4[mt*2+0] += a[0]*a[0] + a[1]*a[1];
                s4[mt*2+1] += a[2] + a[3]; q4[mt*2+1] += a[2]*a[2] + a[3]*a[3];
            }
#pragma unroll
    for (int o = 1; o <= 2; o <<= 1)
#pragma unroll
        for (int t = 0; t < 4; t++) {
            s4[t] += __shfl_xor_sync(0xffffffffu, s4[t], o);
            q4[t] += __shfl_xor_sync(0xffffffffu, q4[t], o);
        }
    if ((lane & 3) == 0) {
#pragma unroll
        for (int t = 0; t < 4; t++) {
            int rr = R + (t >> 1) * 16 + (t & 1) * 8;
            atomicAdd(&redS[rr], s4[t]);
            atomicAdd(&redQ[rr], q4[t]);
        }
    }
    __syncthreads();
    if (tid < 64) {
        float mean = redS[tid] * (1.f / 512.f);
        float var = redQ[tid] * (1.f / 512.f) - mean * mean;
        meanS[tid] = mean;
        rstdS[tid] = rsqrtf(var + EPSF);
    }
    __syncthreads();
    float mn[4], rs[4];
#pragma unroll
    for (int t = 0; t < 4; t++) {
        int rr = R + (t >> 1) * 16 + (t & 1) * 8;
        mn[t] = meanS[rr]; rs[t] = rstdS[rr];
    }

    // ---- GEMM2 (double-buffered h panels) ----
    float acc2[2][2][4];
#pragma unroll
    for (int b = 0; b < 2; b++)
#pragma unroll
        for (int c = 0; c < 2; c++)
#pragma unroll
            for (int d = 0; d < 4; d++) acc2[b][c][d] = 0.f;

#pragma unroll
    for (int kc = 0; kc < 4; kc++) {
        const uint32_t p = (uint32_t)((kc & 1) ^ 1);
        const uint32_t AHp = PAN + p * 32768, ALp = AHp + 16384;
        // pack normalized h chunk into panel p
#pragma unroll
        for (int mt = 0; mt < 2; mt++)
#pragma unroll
            for (int nt = 0; nt < 2; nt++) {
                int col = kc * 128 + colB + nt * 8;
                float g0 = Gam[col], g1 = Gam[col + 1];
                float be0 = Bet[col], be1 = Bet[col + 1];
                float* a = acc1[kc][mt][nt];
                float h0 = fmaxf((a[0] - mn[mt*2])   * rs[mt*2]   * g0 + be0, 0.f);
                float h1 = fmaxf((a[1] - mn[mt*2])   * rs[mt*2]   * g1 + be1, 0.f);
                float h2 = fmaxf((a[2] - mn[mt*2+1]) * rs[mt*2+1] * g0 + be0, 0.f);
                float h3 = fmaxf((a[3] - mn[mt*2+1]) * rs[mt*2+1] * g1 + be1, 0.f);
                uint32_t hh0, ll0, hh1, ll1;
                pack2(h0, h1, hh0, ll0);
                pack2(h2, h3, hh1, ll1);
                int kl = colB + nt * 8;
                int r1 = R + mt * 16, r2 = r1 + 8;
                uint32_t o1 = swz_off(r1, kl), o2 = swz_off(r2, kl);
                *(uint32_t*)(sm + p * 32768 + o1) = hh0;
                *(uint32_t*)(sm + p * 32768 + 16384 + o1) = ll0;
                *(uint32_t*)(sm + p * 32768 + o2) = hh1;
                *(uint32_t*)(sm + p * 32768 + 16384 + o2) = ll1;
            }
        __syncthreads();      // h panel cross-warp
        CP_WAIT1();
        pair_bar(wN);
        uint32_t BH = BBs + (uint32_t)(kc & 1) * 65536, BL = BH + 32768;
#pragma unroll
        for (int ks = 0; ks < 8; ks++) {
            uint32_t ah[2][4], al[2][4], bh[4], bl[4];
#pragma unroll
            for (int mt = 0; mt < 2; mt++) {
                int r = aR + mt * 16;
                uint32_t off = (uint32_t)r * 256 + (uint32_t)((((ks * 2 + aKx) ^ (r & 7)) & 15) << 4);
                ldsm_x4(ah[mt], AHp + off);
                ldsm_x4(al[mt], ALp + off);
            }
            {
                uint32_t off = (uint32_t)bR * 256 + (uint32_t)((((ks * 2 + bKx) ^ (bR & 7)) & 15) << 4);
                ldsm_x4(bh, BH + off);
                ldsm_x4(bl, BL + off);
            }
#pragma unroll
            for (int mt = 0; mt < 2; mt++) {
                mma16816(acc2[mt][0], ah[mt], bh[0], bh[1]);
                mma16816(acc2[mt][1], ah[mt], bh[2], bh[3]);
            }
#pragma unroll
            for (int mt = 0; mt < 2; mt++) {
                mma16816(acc2[mt][0], al[mt], bh[0], bh[1]);
                mma16816(acc2[mt][1], al[mt], bh[2], bh[3]);
            }
#pragma unroll
            for (int mt = 0; mt < 2; mt++) {
                mma16816(acc2[mt][0], ah[mt], bl[0], bl[1]);
                mma16816(acc2[mt][1], ah[mt], bl[2], bl[3]);
            }
        }
        pair_bar(wN);
        if (kc < 2) fillw(kc & 1, W2Hb + (kc + 2) * 16384, W2Lb + (kc + 2) * 16384);
        else        CP_COMMIT();
    }

    // ---- output: acc2 + residual + b2 ----
#pragma unroll
    for (int mt = 0; mt < 2; mt++)
#pragma unroll
        for (int nt = 0; nt < 2; nt++) {
            int col = colB + nt * 8;
            int r1 = row0 + R + mt * 16;
            float b20 = B2s[col], b21 = B2s[col + 1];
            float2 e0 = *(const float2*)&g_edges[(size_t)r1 * 128 + col];
            float2 e1 = *(const float2*)&g_edges[(size_t)(r1 + 8) * 128 + col];
            float* a = acc2[mt][nt];
            *(float2*)&g_edges[(size_t)r1 * 128 + col]       = make_float2(a[0] + e0.x + b20, a[1] + e0.y + b21);
            *(float2*)&g_edges[(size_t)(r1 + 8) * 128 + col] = make_float2(a[2] + e1.x + b20, a[3] + e1.y + b21);
        }
}

// ================= pipelined BM=8 FFMA MLP blocks =================
template<int KD>
__device__ __forceinline__ void mlp8p(const float* Xs, float* Bs, float* Hs, float* red,
        const float* __restrict__ W1, const float* __restrict__ b1,
        const float* __restrict__ gg, const float* __restrict__ bb, int tid) {
    constexpr int NT = KD / 16;      // 32KB tiles (16k x 512n fp32)
    uint32_t bsa = smem_to_u32(Bs);
#pragma unroll
    for (int t = 0; t < 4; t++)
        cpasync16(bsa + tid * 16 + t * 8192, (const char*)W1 + tid * 16 + t * 8192);
    CP_COMMIT();
#pragma unroll
    for (int t = 0; t < 4; t++)
        cpasync16(bsa + 32768 + tid * 16 + t * 8192, (const char*)W1 + 32768 + tid * 16 + t * 8192);
    CP_COMMIT();

    int tr = tid >> 6, tc = tid & 63, c0 = tc * 8;
    float acc[8];
#pragma unroll
    for (int n = 0; n < 8; n++) acc[n] = 0.f;
    for (int kt = 0; kt < NT; kt++) {
        CP_WAIT1();
        __syncthreads();
        const float* B = Bs + (kt & 1) * 8192;
#pragma unroll
        for (int k = 0; k < 16; k++) {
            float a = Xs[tr * KD + kt * 16 + k];
            const float* br = &B[k * 512 + c0];
#pragma unroll
            for (int n = 0; n < 8; n++) acc[n] = fmaf(a, br[n], acc[n]);
        }
        __syncthreads();
        if (kt + 2 < NT) {
#pragma unroll
            for (int t = 0; t < 4; t++)
                cpasync16(bsa + (kt & 1) * 32768 + tid * 16 + t * 8192,
                          (const char*)W1 + (size_t)(kt + 2) * 32768 + tid * 16 + t * 8192);
        }
        CP_COMMIT();
    }
    float s = 0.f, q = 0.f;
#pragma unroll
    for (int n = 0; n < 8; n++) {
        float y = acc[n] + b1[c0 + n];
        acc[n] = y; s += y; q += y * y;
    }
#pragma unroll
    for (int o = 16; o; o >>= 1) {
        s += __shfl_xor_sync(0xffffffffu, s, o);
        q += __shfl_xor_sync(0xffffffffu, q, o);
    }
    int wid = tid >> 5;
    if ((tid & 31) == 0) { red[wid] = s; red[16 + wid] = q; }
    __syncthreads();
    {
        float S = red[2 * tr] + red[2 * tr + 1];
        float Q2 = red[16 + 2 * tr] + red[16 + 2 * tr + 1];
        float mean = S * (1.f / 512.f);
        float var = Q2 * (1.f / 512.f) - mean * mean;
        float rstd = rsqrtf(var + EPSF);
#pragma unroll
        for (int n = 0; n < 8; n++)
            Hs[tr * 512 + c0 + n] = fmaxf((acc[n] - mean) * rstd * gg[c0 + n] + bb[c0 + n], 0.f);
    }
    __syncthreads();
}

__device__ __forceinline__ void gemm2_8p(const float* Hs, float* Bs,
        const float* __restrict__ W2, int tid, float& o0, float& o1) {
    uint32_t bsa = smem_to_u32(Bs);
    cpasync16(bsa + tid * 16, (const char*)W2 + tid * 16);
    CP_COMMIT();
    cpasync16(bsa + 8192 + tid * 16, (const char*)W2 + 8192 + tid * 16);
    CP_COMMIT();
    int col = tid & 127, rp = tid >> 7;
    o0 = 0.f; o1 = 0.f;
    for (int kt = 0; kt < 32; kt++) {
        CP_WAIT1();
        __syncthreads();
        const float* B = Bs + (kt & 1) * 2048;
#pragma unroll
        for (int k = 0; k < 16; k++) {
            float w = B[k * 128 + col];
            o0 = fmaf(Hs[(2 * rp) * 512 + kt * 16 + k], w, o0);
            o1 = fmaf(Hs[(2 * rp + 1) * 512 + kt * 16 + k], w, o1);
        }
        __syncthreads();
        if (kt + 2 < 32)
            cpasync16(bsa + (kt & 1) * 8192 + tid * 16,
                      (const char*)W2 + (size_t)(kt + 2) * 8192 + tid * 16);
        CP_COMMIT();
    }
}

// node update + fused P/Q for next layer; BM=8, grid 32
__global__ void __launch_bounds__(512, 1) k_node(
        const float* __restrict__ W1, const float* __restrict__ b1,
        const float* __restrict__ gg, const float* __restrict__ bb,
        const float* __restrict__ W2, const float* __restrict__ b2,
        const float* __restrict__ Wp, const float* __restrict__ Wq, int do_pq) {
    extern __shared__ float smf[];
    float* Xs = smf;            // 3072
    float* Bs = Xs + 3072;      // 16384 (2x 32KB tiles)
    float* Hs = Bs + 16384;     // 4096
    float* Xn = Hs + 4096;      // 1024
    float* red = Xn + 1024;     // 32
    int tid = threadIdx.x;
    int r0 = blockIdx.x * 8;
    {
        float4* x4 = (float4*)Xs;
        if (tid < 256) {
            int row = tid >> 5, c4 = tid & 31;
            x4[row * 96 + c4] = *(const float4*)&g_nodes[(r0 + row) * 128 + c4 * 4];
        }
        int row = tid >> 6, c4 = tid & 63;
        x4[row * 96 + 32 + c4] = *(const float4*)&g_msgs[(r0 + row) * 256 + c4 * 4];
    }
    __syncthreads();
    mlp8p<384>(Xs, Bs, Hs, red, W1, b1, gg, bb, tid);
    float o0, o1;
    gemm2_8p(Hs, Bs, W2, tid, o0, o1);
    int col = tid & 127, rp = tid >> 7;
    float v0 = o0 + Xs[(2 * rp) * 384 + col] + b2[col];
    float v1 = o1 + Xs[(2 * rp + 1) * 384 + col] + b2[col];
    g_nodes[(r0 + 2 * rp) * 128 + col]     = v0;
    g_nodes[(r0 + 2 * rp + 1) * 128 + col] = v1;
    if (do_pq) {
        Xn[(2 * rp) * 128 + col] = v0;
        Xn[(2 * rp + 1) * 128 + col] = v1;
        __syncthreads();
        float pa[8], qa[8];
#pragma unroll
        for (int r = 0; r < 8; r++) { pa[r] = 0.f; qa[r] = 0.f; }
#pragma unroll 4
        for (int k = 0; k < 128; k++) {
            float wp = Wp[k * 512 + tid];
            float wq = Wq[k * 512 + tid];
#pragma unroll
            for (int r = 0; r < 8; r++) {
                pa[r] = fmaf(Xn[r * 128 + k], wp, pa[r]);
                qa[r] = fmaf(Xn[r * 128 + k], wq, qa[r]);
            }
        }
#pragma unroll
        for (int r = 0; r < 8; r++) {
            g_P[(r0 + r) * 512 + tid] = pa[r];
            g_Q[(r0 + r) * 512 + tid] = qa[r];
        }
    }
}

// final output head; BM=8, grid 32
__global__ void __launch_bounds__(512, 1) k_final(
        const float* __restrict__ no1_w, const float* __restrict__ no1_b,
        const float* __restrict__ no_g,  const float* __restrict__ no_bt,
        const float* __restrict__ no2_w, const float* __restrict__ no2_b,
        const float* __restrict__ sp1_w, const float* __restrict__ sp1_b,
        const float* __restrict__ sp_g,  const float* __restrict__ sp_bt,
        const float* __restrict__ sp2_w, const float* __restrict__ sp2_b,
        float* __restrict__ out_nodes, float* __restrict__ out_coords) {
    extern __shared__ float smf[];
    float* Xs = smf;           // 1024
    float* Bs = Xs + 1024;     // 16384
    float* Hs = Bs + 16384;    // 4096
    float* X2 = Hs + 4096;     // 1024
    float* red = X2 + 1024;    // 32
    int tid = threadIdx.x;
    int r0 = blockIdx.x * 8;
    if (tid < 256) ((float4*)Xs)[tid] = *(const float4*)&g_nodes[r0 * 128 + tid * 4];
    __syncthreads();
    mlp8p<128>(Xs, Bs, Hs, red, no1_w, no1_b, no_g, no_bt, tid);
    float o0, o1;
    gemm2_8p(Hs, Bs, no2_w, tid, o0, o1);
    int col = tid & 127, rp = tid >> 7;
    float v0 = o0 + no2_b[col], v1 = o1 + no2_b[col];
    out_nodes[(r0 + 2 * rp) * 128 + col] = v0;
    out_nodes[(r0 + 2 * rp + 1) * 128 + col] = v1;
    X2[(2 * rp) * 128 + col] = v0;
    X2[(2 * rp + 1) * 128 + col] = v1;
    __syncthreads();
    mlp8p<128>(X2, Bs, Hs, red, sp1_w, sp1_b, sp_g, sp_bt, tid);
    int g = tid >> 4;
    if (g < 24) {
        int row = g / 3, cc = g - row * 3;
        int l16 = tid & 15;
        float s = 0.f;
        for (int k = l16; k < 512; k += 16) s = fmaf(Hs[row * 512 + k], sp2_w[k * 3 + cc], s);
#pragma unroll
        for (int o = 8; o; o >>= 1) s += __shfl_xor_sync(0xffffffffu, s, o);
        if (l16 == 0) out_coords[(r0 + row) * 3 + cc] = s + sp2_b[cc];
    }
}

// ================= launcher =================
extern "C" void kernel_launch(void* const* d_in, const int* in_sizes, int n_in,
                              void* d_out, int out_size) {
    const float* nodes  = (const float*)d_in[0];
    const float* coords = (const float*)d_in[1];
    const float* ee_w   = (const float*)d_in[2];
    const float* ee_b   = (const float*)d_in[3];
    const float* ee_g   = (const float*)d_in[4];
    const float* ee_bt  = (const float*)d_in[5];
    const float* nu1_w  = (const float*)d_in[6];
    const float* nu1_b  = (const float*)d_in[7];
    const float* nu_g   = (const float*)d_in[8];
    const float* nu_bt  = (const float*)d_in[9];
    const float* nu2_w  = (const float*)d_in[10];
    const float* nu2_b  = (const float*)d_in[11];
    const float* eu1_w  = (const float*)d_in[12];
    const float* eu1_b  = (const float*)d_in[13];
    const float* eu_g   = (const float*)d_in[14];
    const float* eu_bt  = (const float*)d_in[15];
    const float* eu2_w  = (const float*)d_in[16];
    const float* eu2_b  = (const float*)d_in[17];
    const float* sp1_w  = (const float*)d_in[18];
    const float* sp1_b  = (const float*)d_in[19];
    const float* sp_g   = (const float*)d_in[20];
    const float* sp_bt  = (const float*)d_in[21];
    const float* sp2_w  = (const float*)d_in[22];
    const float* sp2_b  = (const float*)d_in[23];
    const float* no1_w  = (const float*)d_in[24];
    const float* no1_b  = (const float*)d_in[25];
    const float* no_g   = (const float*)d_in[26];
    const float* no_bt  = (const float*)d_in[27];
    const float* no2_w  = (const float*)d_in[28];
    const float* no2_b  = (const float*)d_in[29];
    float* out = (float*)d_out;

    const int SME = 204288;
    const int SMN = (3072 + 16384 + 4096 + 1024 + 32) * 4;
    const int SMF = (1024 + 16384 + 4096 + 1024 + 32) * 4;
    cudaFuncSetAttribute(k_edge_mma, cudaFuncAttributeMaxDynamicSharedMemorySize, SME);
    cudaFuncSetAttribute(k_node,     cudaFuncAttributeMaxDynamicSharedMemorySize, SMN);
    cudaFuncSetAttribute(k_final,    cudaFuncAttributeMaxDynamicSharedMemorySize, SMF);

    k_prep_w<<<1536, 256>>>(eu1_w, eu2_w);                          // 0
    k_init<<<8192, 256>>>(nodes, coords, ee_w, ee_b, ee_g, ee_bt);  // 1
    k_pq<<<dim3(64, 2), 512>>>(eu1_w + 65536, eu1_w + 131072);      // 2 (layer 0)

    for (int l = 0; l < 3; l++) {
        k_edge_mma<<<1024, 512, SME>>>(l, eu1_b + l*512, eu_g + l*512,   // 3 (l=0): ncu slot
                                       eu_bt + l*512, eu2_b + l*128);
        int do_pq = (l < 2) ? 1 : 0;
        const float* Wp = eu1_w + (l+1)*196608 + 65536;
        const float* Wq = eu1_w + (l+1)*196608 + 131072;
        k_node<<<32, 512, SMN>>>(nu1_w + l*196608, nu1_b + l*512,
                                 nu_g + l*512, nu_bt + l*512,
                                 nu2_w + l*65536, nu2_b + l*128,
                                 Wp, Wq, do_pq);
    }
    // layer 3: edge output is dead code — msgs only
    k_msgs<<<8192, 256>>>();
    k_node<<<32, 512, SMN>>>(nu1_w + 3*196608, nu1_b + 3*512,
                             nu_g + 3*512, nu_bt + 3*512,
                             nu2_w + 3*65536, nu2_b + 3*128,
                             nu1_w, nu1_w, 0);
    k_final<<<32, 512, SMF>>>(no1_w, no1_b, no_g, no_bt, no2_w, no2_b,
                              sp1_w, sp1_b, sp_g, sp_bt, sp2_w, sp2_b,
                              out, out + 32768);
}

// round 8
// speedup vs baseline: 3.8295x; 1.2976x over previous
#include <cuda_runtime.h>
#include <cuda_fp16.h>
#include <cstdint>

#define EPSF 1e-5f
#define NND 256
#define DD  128
#define HH  512
#define NR  65536

// -------- scratch (device globals: allocation-free rule) --------
__device__ __align__(16) float g_edges[NR * DD];
__device__ float g_adj[NR];
__device__ float g_msgs[NR];
__device__ __align__(16) float g_nodes[NND * DD];
__device__ __align__(16) float g_P[NND * HH];
__device__ __align__(16) float g_Q[NND * HH];
// pre-swizzled fp16 weight tile images: [layer 0..2][chunk 0..3][128n][128k]
__device__ __align__(16) __half g_W1h[196608];
__device__ __align__(16) __half g_W2h[196608];

// ================= low-level helpers =================
__device__ __forceinline__ uint32_t smem_to_u32(const void* p) {
    uint32_t a;
    asm("{ .reg .u64 t; cvta.to.shared.u64 t, %1; cvt.u32.u64 %0, t; }" : "=r"(a) : "l"(p));
    return a;
}
__device__ __forceinline__ void ldsm_x4(uint32_t* r, uint32_t addr) {
    asm volatile("ldmatrix.sync.aligned.m8n8.x4.shared.b16 {%0,%1,%2,%3}, [%4];"
        : "=r"(r[0]), "=r"(r[1]), "=r"(r[2]), "=r"(r[3]) : "r"(addr));
}
__device__ __forceinline__ void mma16816h(float* c, const uint32_t* a, uint32_t b0, uint32_t b1) {
    asm volatile("mma.sync.aligned.m16n8k16.row.col.f32.f16.f16.f32 "
        "{%0,%1,%2,%3}, {%4,%5,%6,%7}, {%8,%9}, {%0,%1,%2,%3};"
        : "+f"(c[0]), "+f"(c[1]), "+f"(c[2]), "+f"(c[3])
        : "r"(a[0]), "r"(a[1]), "r"(a[2]), "r"(a[3]), "r"(b0), "r"(b1));
}
__device__ __forceinline__ void cpasync16(uint32_t dst, const void* src) {
    asm volatile("cp.async.cg.shared.global [%0], [%1], 16;" :: "r"(dst), "l"(src));
}
#define CP_COMMIT() asm volatile("cp.async.commit_group;" ::: "memory")
#define CP_WAIT1()  asm volatile("cp.async.wait_group 1;" ::: "memory")
#define CP_WAIT0()  asm volatile("cp.async.wait_group 0;" ::: "memory")
__device__ __forceinline__ void pair_bar(int wN) {
    asm volatile("bar.sync %0, 64;" :: "r"(1 + wN) : "memory");
}
// fp16 hi/lo split pack of 2 floats
__device__ __forceinline__ void pack2h(float a, float b, uint32_t& hi, uint32_t& lo) {
    __half ah = __float2half_rn(a), bh = __float2half_rn(b);
    float ar = a - __half2float(ah), br = b - __half2float(bh);
    __half al = __float2half_rn(ar), bl = __float2half_rn(br);
    hi = (uint32_t)__half_as_ushort(ah) | ((uint32_t)__half_as_ushort(bh) << 16);
    lo = (uint32_t)__half_as_ushort(al) | ((uint32_t)__half_as_ushort(bl) << 16);
}
// byte offset inside a [rows][128k] fp16 tile (256B/row, XOR-swizzled 16B chunks)
__device__ __host__ __forceinline__ uint32_t swz_off(int r, int k) {
    return (uint32_t)(r * 256 + ((((k >> 3) ^ (r & 7)) & 15) << 4) + (k & 7) * 2);
}

// ================= weight image prep (layers 0..2, fp16 single) =================
__global__ void k_prep_w(const float* __restrict__ eu1_w, const float* __restrict__ eu2_w) {
    int idx = blockIdx.x * 256 + threadIdx.x;     // < 393216
    int which = idx / 196608;
    int rem = idx - which * 196608;
    int l = rem >> 16;
    int e = rem & 65535;
    int chunk = e >> 14;
    int e2 = e & 16383;
    int n = e2 >> 7, k = e2 & 127;
    float v;
    if (which == 0) v = eu1_w[l * 196608 + k * 512 + chunk * 128 + n];
    else            v = eu2_w[l * 65536 + (chunk * 128 + k) * 128 + n];
    int dst = (l * 4 + chunk) * 16384 + (int)(swz_off(n, k) >> 1);
    if (which == 0) g_W1h[dst] = __float2half_rn(v);
    else            g_W2h[dst] = __float2half_rn(v);
}

// ================= init: copy nodes + edges embedding + adjacency =================
__global__ void k_init(const float* __restrict__ nodes_in,
                       const float* __restrict__ coords,
                       const float* __restrict__ w, const float* __restrict__ b,
                       const float* __restrict__ gg, const float* __restrict__ bb) {
    if (blockIdx.x < 64) {
        int t = blockIdx.x * 256 + threadIdx.x;
        g_nodes[t] = nodes_in[t];
        g_nodes[t + 16384] = nodes_in[t + 16384];
    }
    int warp = threadIdx.x >> 5, lane = threadIdx.x & 31;
    int row = blockIdx.x * 8 + warp;
    int i = row >> 8, j = row & 255;
    float dx = coords[i*3+0] - coords[j*3+0];
    float dy = coords[i*3+1] - coords[j*3+1];
    float dz = coords[i*3+2] - coords[j*3+2];
    float sq = dx*dx + dy*dy + dz*dz;
    float dist = sq > 0.f ? sqrtf(sq) : 0.f;
    if (lane == 0) g_adj[row] = (dist < 10.f) ? 1.f : 0.f;
    float e[4]; float s = 0.f, ss = 0.f;
#pragma unroll
    for (int t = 0; t < 4; t++) {
        int d = lane + 32*t;
        e[t] = dist * w[d] + b[d];
        s += e[t]; ss += e[t]*e[t];
    }
#pragma unroll
    for (int o = 16; o; o >>= 1) {
        s  += __shfl_xor_sync(0xffffffffu, s, o);
        ss += __shfl_xor_sync(0xffffffffu, ss, o);
    }
    float mean = s * (1.f/128.f);
    float var  = ss * (1.f/128.f) - mean*mean;
    float rs   = rsqrtf(var + EPSF);
#pragma unroll
    for (int t = 0; t < 4; t++) {
        int d = lane + 32*t;
        float v = (e[t]-mean)*rs*gg[d] + bb[d];
        g_edges[row*DD + d] = fmaxf(v, 0.f);
    }
}

// standalone msgs (used only for the last layer)
__global__ void k_msgs() {
    int warp = threadIdx.x >> 5, lane = threadIdx.x & 31;
    int row = blockIdx.x * 8 + warp;
    int i = row >> 8;
    const float4* e4 = (const float4*)(g_edges + row*DD);
    const float4* n4 = (const float4*)(g_nodes + i*DD);
    float4 a = e4[lane], c = n4[lane];
    float s = a.x*c.x + a.y*c.y + a.z*c.z + a.w*c.w;
#pragma unroll
    for (int o = 16; o; o >>= 1) s += __shfl_xor_sync(0xffffffffu, s, o);
    if (lane == 0) g_msgs[row] = g_adj[row] * s;
}

// P/Q for layer 0 (from initial nodes); grid (64,2), 512 thr
__global__ void __launch_bounds__(512) k_pq(const float* __restrict__ Wp,
                                            const float* __restrict__ Wq) {
    __shared__ float xs[512];
    int tid = threadIdx.x;
    int r0 = blockIdx.x * 4;
    const float* __restrict__ W = blockIdx.y ? Wq : Wp;
    float* out = blockIdx.y ? g_Q : g_P;
    xs[tid] = g_nodes[r0 * 128 + tid];
    __syncthreads();
    float a0 = 0.f, a1 = 0.f, a2 = 0.f, a3 = 0.f;
#pragma unroll 8
    for (int k = 0; k < 128; k++) {
        float wv = W[k * 512 + tid];
        a0 = fmaf(xs[k],       wv, a0);
        a1 = fmaf(xs[128 + k], wv, a1);
        a2 = fmaf(xs[256 + k], wv, a2);
        a3 = fmaf(xs[384 + k], wv, a3);
    }
    out[(r0+0)*512 + tid] = a0;
    out[(r0+1)*512 + tid] = a1;
    out[(r0+2)*512 + tid] = a2;
    out[(r0+3)*512 + tid] = a3;
}

// ================= HMMA fused edge update (fp16 2-pass, + fused msgs) =================
// smem bytes: A panels 2x32KB @0 (ah 16K + al 16K each), B 2x32KB @65536, params @131072
__global__ void __launch_bounds__(512, 1) k_edge_mma(int l,
        const float* __restrict__ b1, const float* __restrict__ gg,
        const float* __restrict__ bb, const float* __restrict__ b2) {
    extern __shared__ char sm[];
    const uint32_t S = smem_to_u32(sm);
    const int tid = threadIdx.x, lane = tid & 31;
    const int wM = (tid >> 5) & 1, wN = tid >> 6;
    const int row0 = blockIdx.x * 64;
    const int i = row0 >> 8, j0 = row0 & 255;

    const uint32_t BBs = S + 65536;       // 2 bufs x 32KB
    float* Pb    = (float*)(sm + 131072);
    float* Gam   = (float*)(sm + 133120);
    float* Bet   = (float*)(sm + 135168);
    float* B2s   = (float*)(sm + 137216);
    float* redS  = (float*)(sm + 137728);
    float* redQ  = (float*)(sm + 137984);
    float* meanS = (float*)(sm + 138240);
    float* rstdS = (float*)(sm + 138496);

    Pb[tid]  = g_P[i*512 + tid] + b1[tid];
    Gam[tid] = gg[tid];
    Bet[tid] = bb[tid];
    if (tid < 128) B2s[tid] = b2[tid];
    if (tid < 64) { redS[tid] = 0.f; redQ[tid] = 0.f; }

    // per-pair slice fill: pair wN owns B rows [wN*16, wN*16+16) = 4KB
    const int pid = tid & 63;
    auto fillw = [&](int buf, const __half* sW) {
        uint32_t d = BBs + (uint32_t)buf * 32768 + (uint32_t)wN * 4096;
        const char* g = (const char*)sW + wN * 4096;
#pragma unroll
        for (int t = 0; t < 4; t++) {
            uint32_t byo = (uint32_t)(pid + t * 64) * 16;
            cpasync16(d + byo, g + byo);
        }
        CP_COMMIT();
    };
    const __half* W1b = g_W1h + l * 65536;
    const __half* W2b = g_W2h + l * 65536;
    fillw(0, W1b);
    fillw(1, W1b + 16384);

    // A = edges tile -> fp16 hi/lo panel 0; fused msgs from OLD edges
    {
        const int c4 = tid & 31, k0 = c4 * 4, rb = tid >> 5;
        const float4 nv = *(const float4*)&g_nodes[(size_t)i * 128 + k0];
        float4 v[4];
#pragma unroll
        for (int t = 0; t < 4; t++)
            v[t] = *(const float4*)&g_edges[(size_t)(row0 + rb + t * 16) * 128 + k0];
#pragma unroll
        for (int t = 0; t < 4; t++) {
            int r = rb + t * 16;
            float dot = v[t].x*nv.x + v[t].y*nv.y + v[t].z*nv.z + v[t].w*nv.w;
#pragma unroll
            for (int o = 16; o; o >>= 1) dot += __shfl_xor_sync(0xffffffffu, dot, o);
            if (lane == 0) g_msgs[row0 + r] = g_adj[row0 + r] * dot;
            uint32_t h0, l0, h1, l1;
            pack2h(v[t].x, v[t].y, h0, l0);
            pack2h(v[t].z, v[t].w, h1, l1);
            uint32_t off = swz_off(r, k0);
            *(uint2*)(sm + off)         = make_uint2(h0, h1);
            *(uint2*)(sm + 16384 + off) = make_uint2(l0, l1);
        }
    }
    __syncthreads();   // A panel 0 + params visible to all

    // ---- GEMM1: 2-pass fp16 ----
    float acc1[4][2][2][4];
#pragma unroll
    for (int a = 0; a < 4; a++)
#pragma unroll
        for (int b = 0; b < 2; b++)
#pragma unroll
            for (int c = 0; c < 2; c++)
#pragma unroll
                for (int d = 0; d < 4; d++) acc1[a][b][c][d] = 0.f;

    const int aR  = wM * 32 + (lane & 15);
    const int aKx = lane >> 4;
    const int bR  = wN * 16 + (lane & 7) + ((lane & 16) >> 1);
    const int bKx = (lane & 8) >> 3;

#pragma unroll
    for (int nc = 0; nc < 4; nc++) {
        CP_WAIT1();
        pair_bar(wN);
        uint32_t BH = BBs + (uint32_t)(nc & 1) * 32768;
#pragma unroll
        for (int ks = 0; ks < 8; ks++) {
            uint32_t ah[2][4], al[2][4], bh[4];
#pragma unroll
            for (int mt = 0; mt < 2; mt++) {
                int r = aR + mt * 16;
                uint32_t off = (uint32_t)r * 256 + (uint32_t)((((ks * 2 + aKx) ^ (r & 7)) & 15) << 4);
                ldsm_x4(ah[mt], S + off);
                ldsm_x4(al[mt], S + 16384 + off);
            }
            {
                uint32_t off = (uint32_t)bR * 256 + (uint32_t)((((ks * 2 + bKx) ^ (bR & 7)) & 15) << 4);
                ldsm_x4(bh, BH + off);
            }
#pragma unroll
            for (int mt = 0; mt < 2; mt++) {
                mma16816h(acc1[nc][mt][0], ah[mt], bh[0], bh[1]);
                mma16816h(acc1[nc][mt][1], ah[mt], bh[2], bh[3]);
            }
#pragma unroll
            for (int mt = 0; mt < 2; mt++) {
                mma16816h(acc1[nc][mt][0], al[mt], bh[0], bh[1]);
                mma16816h(acc1[nc][mt][1], al[mt], bh[2], bh[3]);
            }
        }
        pair_bar(wN);
        if (nc < 2) fillw(nc & 1, W1b + (nc + 2) * 16384);
        else        fillw(nc & 1, W2b + (nc - 2) * 16384);
    }

    // ---- epilogue: y = acc + P + Q, LN stats ----
    const int R = wM * 32 + (lane >> 2);
    const int colB = wN * 16 + (lane & 3) * 2;
    float s4[4] = {0.f, 0.f, 0.f, 0.f}, q4[4] = {0.f, 0.f, 0.f, 0.f};
#pragma unroll
    for (int nc = 0; nc < 4; nc++)
#pragma unroll
        for (int mt = 0; mt < 2; mt++)
#pragma unroll
            for (int nt = 0; nt < 2; nt++) {
                int col = nc * 128 + colB + nt * 8;
                int rA = j0 + R + mt * 16;
                float2 qa = *(const float2*)&g_Q[(size_t)rA * 512 + col];
                float2 qb = *(const float2*)&g_Q[(size_t)(rA + 8) * 512 + col];
                float p0 = Pb[col], p1 = Pb[col + 1];
                float* a = acc1[nc][mt][nt];
                a[0] += p0 + qa.x; a[1] += p1 + qa.y;
                a[2] += p0 + qb.x; a[3] += p1 + qb.y;
                s4[mt*2+0] += a[0] + a[1]; q4[mt*2+0] += a[0]*a[0] + a[1]*a[1];
                s4[mt*2+1] += a[2] + a[3]; q4[mt*2+1] += a[2]*a[2] + a[3]*a[3];
            }
#pragma unroll
    for (int o = 1; o <= 2; o <<= 1)
#pragma unroll
        for (int t = 0; t < 4; t++) {
            s4[t] += __shfl_xor_sync(0xffffffffu, s4[t], o);
            q4[t] += __shfl_xor_sync(0xffffffffu, q4[t], o);
        }
    if ((lane & 3) == 0) {
#pragma unroll
        for (int t = 0; t < 4; t++) {
            int rr = R + (t >> 1) * 16 + (t & 1) * 8;
            atomicAdd(&redS[rr], s4[t]);
            atomicAdd(&redQ[rr], q4[t]);
        }
    }
    __syncthreads();
    if (tid < 64) {
        float mean = redS[tid] * (1.f / 512.f);
        float var = redQ[tid] * (1.f / 512.f) - mean * mean;
        meanS[tid] = mean;
        rstdS[tid] = rsqrtf(var + EPSF);
    }
    __syncthreads();
    float mn[4], rs[4];
#pragma unroll
    for (int t = 0; t < 4; t++) {
        int rr = R + (t >> 1) * 16 + (t & 1) * 8;
        mn[t] = meanS[rr]; rs[t] = rstdS[rr];
    }

    // ---- GEMM2 (double-buffered h panels, 2-pass fp16) ----
    float acc2[2][2][4];
#pragma unroll
    for (int b = 0; b < 2; b++)
#pragma unroll
        for (int c = 0; c < 2; c++)
#pragma unroll
            for (int d = 0; d < 4; d++) acc2[b][c][d] = 0.f;

#pragma unroll
    for (int kc = 0; kc < 4; kc++) {
        const uint32_t p = (uint32_t)((kc & 1) ^ 1);
        const uint32_t AHp = S + p * 32768, ALp = AHp + 16384;
#pragma unroll
        for (int mt = 0; mt < 2; mt++)
#pragma unroll
            for (int nt = 0; nt < 2; nt++) {
                int col = kc * 128 + colB + nt * 8;
                float g0 = Gam[col], g1 = Gam[col + 1];
                float be0 = Bet[col], be1 = Bet[col + 1];
                float* a = acc1[kc][mt][nt];
                float h0 = fmaxf((a[0] - mn[mt*2])   * rs[mt*2]   * g0 + be0, 0.f);
                float h1 = fmaxf((a[1] - mn[mt*2])   * rs[mt*2]   * g1 + be1, 0.f);
                float h2 = fmaxf((a[2] - mn[mt*2+1]) * rs[mt*2+1] * g0 + be0, 0.f);
                float h3 = fmaxf((a[3] - mn[mt*2+1]) * rs[mt*2+1] * g1 + be1, 0.f);
                uint32_t hh0, ll0, hh1, ll1;
                pack2h(h0, h1, hh0, ll0);
                pack2h(h2, h3, hh1, ll1);
                int kl = colB + nt * 8;
                int r1 = R + mt * 16, r2 = r1 + 8;
                uint32_t o1 = swz_off(r1, kl), o2 = swz_off(r2, kl);
                *(uint32_t*)(sm + p * 32768 + o1) = hh0;
                *(uint32_t*)(sm + p * 32768 + 16384 + o1) = ll0;
                *(uint32_t*)(sm + p * 32768 + o2) = hh1;
                *(uint32_t*)(sm + p * 32768 + 16384 + o2) = ll1;
            }
        __syncthreads();      // h panel cross-warp
        if (kc == 3) CP_WAIT0(); else CP_WAIT1();
        pair_bar(wN);
        uint32_t BH = BBs + (uint32_t)(kc & 1) * 32768;
#pragma unroll
        for (int ks = 0; ks < 8; ks++) {
            uint32_t ah[2][4], al[2][4], bh[4];
#pragma unroll
            for (int mt = 0; mt < 2; mt++) {
                int r = aR + mt * 16;
                uint32_t off = (uint32_t)r * 256 + (uint32_t)((((ks * 2 + aKx) ^ (r & 7)) & 15) << 4);
                ldsm_x4(ah[mt], AHp + off);
                ldsm_x4(al[mt], ALp + off);
            }
            {
                uint32_t off = (uint32_t)bR * 256 + (uint32_t)((((ks * 2 + bKx) ^ (bR & 7)) & 15) << 4);
                ldsm_x4(bh, BH + off);
            }
#pragma unroll
            for (int mt = 0; mt < 2; mt++) {
                mma16816h(acc2[mt][0], ah[mt], bh[0], bh[1]);
                mma16816h(acc2[mt][1], ah[mt], bh[2], bh[3]);
            }
#pragma unroll
            for (int mt = 0; mt < 2; mt++) {
                mma16816h(acc2[mt][0], al[mt], bh[0], bh[1]);
                mma16816h(acc2[mt][1], al[mt], bh[2], bh[3]);
            }
        }
        pair_bar(wN);
        if (kc < 2) fillw(kc & 1, W2b + (kc + 2) * 16384);
        else        CP_COMMIT();
    }

    // ---- output: acc2 + residual + b2 ----
#pragma unroll
    for (int mt = 0; mt < 2; mt++)
#pragma unroll
        for (int nt = 0; nt < 2; nt++) {
            int col = colB + nt * 8;
            int r1 = row0 + R + mt * 16;
            float b20 = B2s[col], b21 = B2s[col + 1];
            float2 e0 = *(const float2*)&g_edges[(size_t)r1 * 128 + col];
            float2 e1 = *(const float2*)&g_edges[(size_t)(r1 + 8) * 128 + col];
            float* a = acc2[mt][nt];
            *(float2*)&g_edges[(size_t)r1 * 128 + col]       = make_float2(a[0] + e0.x + b20, a[1] + e0.y + b21);
            *(float2*)&g_edges[(size_t)(r1 + 8) * 128 + col] = make_float2(a[2] + e1.x + b20, a[3] + e1.y + b21);
        }
}

// ================= pipelined BM=4 FFMA MLP blocks (256 threads) =================
template<int KD>
__device__ __forceinline__ void mlp4p(const float* Xs, float* Bs, float* Hs, float* red,
        const float* __restrict__ W1, const float* __restrict__ b1,
        const float* __restrict__ gg, const float* __restrict__ bb, int tid) {
    constexpr int NT = KD / 16;      // 32KB tiles (16k x 512n fp32)
    uint32_t bsa = smem_to_u32(Bs);
#pragma unroll
    for (int t = 0; t < 8; t++)
        cpasync16(bsa + tid * 16 + t * 4096, (const char*)W1 + tid * 16 + t * 4096);
    CP_COMMIT();
#pragma unroll
    for (int t = 0; t < 8; t++)
        cpasync16(bsa + 32768 + tid * 16 + t * 4096, (const char*)W1 + 32768 + tid * 16 + t * 4096);
    CP_COMMIT();

    int tr = tid >> 6, tc = tid & 63, c0 = tc * 8;
    float acc[8];
#pragma unroll
    for (int n = 0; n < 8; n++) acc[n] = 0.f;
    for (int kt = 0; kt < NT; kt++) {
        CP_WAIT1();
        __syncthreads();
        const float* B = Bs + (kt & 1) * 8192;
#pragma unroll
        for (int k = 0; k < 16; k++) {
            float a = Xs[tr * KD + kt * 16 + k];
            const float* br = &B[k * 512 + c0];
#pragma unroll
            for (int n = 0; n < 8; n++) acc[n] = fmaf(a, br[n], acc[n]);
        }
        __syncthreads();
        if (kt + 2 < NT) {
#pragma unroll
            for (int t = 0; t < 8; t++)
                cpasync16(bsa + (kt & 1) * 32768 + tid * 16 + t * 4096,
                          (const char*)W1 + (size_t)(kt + 2) * 32768 + tid * 16 + t * 4096);
        }
        CP_COMMIT();
    }
    float s = 0.f, q = 0.f;
#pragma unroll
    for (int n = 0; n < 8; n++) {
        float y = acc[n] + b1[c0 + n];
        acc[n] = y; s += y; q += y * y;
    }
#pragma unroll
    for (int o = 16; o; o >>= 1) {
        s += __shfl_xor_sync(0xffffffffu, s, o);
        q += __shfl_xor_sync(0xffffffffu, q, o);
    }
    int wid = tid >> 5;
    if ((tid & 31) == 0) { red[wid] = s; red[8 + wid] = q; }
    __syncthreads();
    {
        float S = red[2 * tr] + red[2 * tr + 1];
        float Q2 = red[8 + 2 * tr] + red[8 + 2 * tr + 1];
        float mean = S * (1.f / 512.f);
        float var = Q2 * (1.f / 512.f) - mean * mean;
        float rstd = rsqrtf(var + EPSF);
#pragma unroll
        for (int n = 0; n < 8; n++)
            Hs[tr * 512 + c0 + n] = fmaxf((acc[n] - mean) * rstd * gg[c0 + n] + bb[c0 + n], 0.f);
    }
    __syncthreads();
}

__device__ __forceinline__ void gemm2_4p(const float* Hs, float* Bs,
        const float* __restrict__ W2, int tid, float& o0, float& o1) {
    uint32_t bsa = smem_to_u32(Bs);
#pragma unroll
    for (int t = 0; t < 2; t++)
        cpasync16(bsa + tid * 16 + t * 4096, (const char*)W2 + tid * 16 + t * 4096);
    CP_COMMIT();
#pragma unroll
    for (int t = 0; t < 2; t++)
        cpasync16(bsa + 8192 + tid * 16 + t * 4096, (const char*)W2 + 8192 + tid * 16 + t * 4096);
    CP_COMMIT();
    int col = tid & 127, rp = tid >> 7;
    o0 = 0.f; o1 = 0.f;
    for (int kt = 0; kt < 32; kt++) {
        CP_WAIT1();
        __syncthreads();
        const float* B = Bs + (kt & 1) * 2048;
#pragma unroll
        for (int k = 0; k < 16; k++) {
            float w = B[k * 128 + col];
            o0 = fmaf(Hs[(2 * rp) * 512 + kt * 16 + k], w, o0);
            o1 = fmaf(Hs[(2 * rp + 1) * 512 + kt * 16 + k], w, o1);
        }
        __syncthreads();
        if (kt + 2 < 32) {
#pragma unroll
            for (int t = 0; t < 2; t++)
                cpasync16(bsa + (kt & 1) * 8192 + tid * 16 + t * 4096,
                          (const char*)W2 + (size_t)(kt + 2) * 8192 + tid * 16 + t * 4096);
        }
        CP_COMMIT();
    }
}

// node update + fused P/Q for next layer; BM=4, grid 64, 256 thr
__global__ void __launch_bounds__(256, 1) k_node(
        const float* __restrict__ W1, const float* __restrict__ b1,
        const float* __restrict__ gg, const float* __restrict__ bb,
        const float* __restrict__ W2, const float* __restrict__ b2,
        const float* __restrict__ Wp, const float* __restrict__ Wq, int do_pq) {
    extern __shared__ float smf[];
    float* Xs = smf;            // 4*384 = 1536
    float* Bs = Xs + 1536;      // 16384
    float* Hs = Bs + 16384;     // 2048
    float* Xn = Hs + 2048;      // 512
    float* red = Xn + 512;      // 16
    int tid = threadIdx.x;
    int r0 = blockIdx.x * 4;
    {
        float4* x4 = (float4*)Xs;
        if (tid < 128) {
            int row = tid >> 5, c4 = tid & 31;
            x4[row * 96 + c4] = *(const float4*)&g_nodes[(r0 + row) * 128 + c4 * 4];
        }
        int row = tid >> 6, c4 = tid & 63;
        x4[row * 96 + 32 + c4] = *(const float4*)&g_msgs[(r0 + row) * 256 + c4 * 4];
    }
    __syncthreads();
    mlp4p<384>(Xs, Bs, Hs, red, W1, b1, gg, bb, tid);
    float o0, o1;
    gemm2_4p(Hs, Bs, W2, tid, o0, o1);
    int col = tid & 127, rp = tid >> 7;
    float v0 = o0 + Xs[(2 * rp) * 384 + col] + b2[col];
    float v1 = o1 + Xs[(2 * rp + 1) * 384 + col] + b2[col];
    g_nodes[(r0 + 2 * rp) * 128 + col]     = v0;
    g_nodes[(r0 + 2 * rp + 1) * 128 + col] = v1;
    if (do_pq) {
        Xn[(2 * rp) * 128 + col] = v0;
        Xn[(2 * rp + 1) * 128 + col] = v1;
        __syncthreads();
#pragma unroll
        for (int hfl = 0; hfl < 2; hfl++) {
            int c = hfl * 256 + tid;
            float pa[4], qa[4];
#pragma unroll
            for (int r = 0; r < 4; r++) { pa[r] = 0.f; qa[r] = 0.f; }
#pragma unroll 4
            for (int k = 0; k < 128; k++) {
                float wp = Wp[k * 512 + c];
                float wq = Wq[k * 512 + c];
#pragma unroll
                for (int r = 0; r < 4; r++) {
                    pa[r] = fmaf(Xn[r * 128 + k], wp, pa[r]);
                    qa[r] = fmaf(Xn[r * 128 + k], wq, qa[r]);
                }
            }
#pragma unroll
            for (int r = 0; r < 4; r++) {
                g_P[(r0 + r) * 512 + c] = pa[r];
                g_Q[(r0 + r) * 512 + c] = qa[r];
            }
        }
    }
}

// final output head; BM=4, grid 64, 256 thr
__global__ void __launch_bounds__(256, 1) k_final(
        const float* __restrict__ no1_w, const float* __restrict__ no1_b,
        const float* __restrict__ no_g,  const float* __restrict__ no_bt,
        const float* __restrict__ no2_w, const float* __restrict__ no2_b,
        const float* __restrict__ sp1_w, const float* __restrict__ sp1_b,
        const float* __restrict__ sp_g,  const float* __restrict__ sp_bt,
        const float* __restrict__ sp2_w, const float* __restrict__ sp2_b,
        float* __restrict__ out_nodes, float* __restrict__ out_coords) {
    extern __shared__ float smf[];
    float* Xs = smf;           // 512
    float* Bs = Xs + 512;      // 16384
    float* Hs = Bs + 16384;    // 2048
    float* X2 = Hs + 2048;     // 512
    float* red = X2 + 512;     // 16
    int tid = threadIdx.x;
    int r0 = blockIdx.x * 4;
    if (tid < 128) ((float4*)Xs)[tid] = *(const float4*)&g_nodes[r0 * 128 + tid * 4];
    __syncthreads();
    mlp4p<128>(Xs, Bs, Hs, red, no1_w, no1_b, no_g, no_bt, tid);
    float o0, o1;
    gemm2_4p(Hs, Bs, no2_w, tid, o0, o1);
    int col = tid & 127, rp = tid >> 7;
    float v0 = o0 + no2_b[col], v1 = o1 + no2_b[col];
    out_nodes[(r0 + 2 * rp) * 128 + col] = v0;
    out_nodes[(r0 + 2 * rp + 1) * 128 + col] = v1;
    X2[(2 * rp) * 128 + col] = v0;
    X2[(2 * rp + 1) * 128 + col] = v1;
    __syncthreads();
    mlp4p<128>(X2, Bs, Hs, red, sp1_w, sp1_b, sp_g, sp_bt, tid);
    int g = tid >> 4;
    if (g < 12) {
        int row = g / 3, cc = g - row * 3;
        int l16 = tid & 15;
        float s = 0.f;
        for (int k = l16; k < 512; k += 16) s = fmaf(Hs[row * 512 + k], sp2_w[k * 3 + cc], s);
#pragma unroll
        for (int o = 8; o; o >>= 1) s += __shfl_xor_sync(0xffffffffu, s, o);
        if (l16 == 0) out_coords[(r0 + row) * 3 + cc] = s + sp2_b[cc];
    }
}

// ================= launcher =================
extern "C" void kernel_launch(void* const* d_in, const int* in_sizes, int n_in,
                              void* d_out, int out_size) {
    const float* nodes  = (const float*)d_in[0];
    const float* coords = (const float*)d_in[1];
    const float* ee_w   = (const float*)d_in[2];
    const float* ee_b   = (const float*)d_in[3];
    const float* ee_g   = (const float*)d_in[4];
    const float* ee_bt  = (const float*)d_in[5];
    const float* nu1_w  = (const float*)d_in[6];
    const float* nu1_b  = (const float*)d_in[7];
    const float* nu_g   = (const float*)d_in[8];
    const float* nu_bt  = (const float*)d_in[9];
    const float* nu2_w  = (const float*)d_in[10];
    const float* nu2_b  = (const float*)d_in[11];
    const float* eu1_w  = (const float*)d_in[12];
    const float* eu1_b  = (const float*)d_in[13];
    const float* eu_g   = (const float*)d_in[14];
    const float* eu_bt  = (const float*)d_in[15];
    const float* eu2_w  = (const float*)d_in[16];
    const float* eu2_b  = (const float*)d_in[17];
    const float* sp1_w  = (const float*)d_in[18];
    const float* sp1_b  = (const float*)d_in[19];
    const float* sp_g   = (const float*)d_in[20];
    const float* sp_bt  = (const float*)d_in[21];
    const float* sp2_w  = (const float*)d_in[22];
    const float* sp2_b  = (const float*)d_in[23];
    const float* no1_w  = (const float*)d_in[24];
    const float* no1_b  = (const float*)d_in[25];
    const float* no_g   = (const float*)d_in[26];
    const float* no_bt  = (const float*)d_in[27];
    const float* no2_w  = (const float*)d_in[28];
    const float* no2_b  = (const float*)d_in[29];
    float* out = (float*)d_out;

    const int SME = 138752;
    const int SMN = (1536 + 16384 + 2048 + 512 + 16) * 4;
    const int SMF = (512 + 16384 + 2048 + 512 + 16) * 4;
    cudaFuncSetAttribute(k_edge_mma, cudaFuncAttributeMaxDynamicSharedMemorySize, SME);
    cudaFuncSetAttribute(k_node,     cudaFuncAttributeMaxDynamicSharedMemorySize, SMN);
    cudaFuncSetAttribute(k_final,    cudaFuncAttributeMaxDynamicSharedMemorySize, SMF);

    k_prep_w<<<1536, 256>>>(eu1_w, eu2_w);                          // 0
    k_init<<<8192, 256>>>(nodes, coords, ee_w, ee_b, ee_g, ee_bt);  // 1
    k_pq<<<dim3(64, 2), 512>>>(eu1_w + 65536, eu1_w + 131072);      // 2 (layer 0)

    for (int l = 0; l < 3; l++) {
        k_edge_mma<<<1024, 512, SME>>>(l, eu1_b + l*512, eu_g + l*512,   // 3 (l=0): ncu slot
                                       eu_bt + l*512, eu2_b + l*128);
        int do_pq = (l < 2) ? 1 : 0;
        const float* Wp = eu1_w + (l+1)*196608 + 65536;
        const float* Wq = eu1_w + (l+1)*196608 + 131072;
        k_node<<<64, 256, SMN>>>(nu1_w + l*196608, nu1_b + l*512,
                                 nu_g + l*512, nu_bt + l*512,
                                 nu2_w + l*65536, nu2_b + l*128,
                                 Wp, Wq, do_pq);
    }
    // layer 3: edge output is dead code — msgs only
    k_msgs<<<8192, 256>>>();
    k_node<<<64, 256, SMN>>>(nu1_w + 3*196608, nu1_b + 3*512,
                             nu_g + 3*512, nu_bt + 3*512,
                             nu2_w + 3*65536, nu2_b + 3*128,
                             nu1_w, nu1_w, 0);
    k_final<<<64, 256, SMF>>>(no1_w, no1_b, no_g, no_bt, no2_w, no2_b,
                              sp1_w, sp1_b, sp_g, sp_bt, sp2_w, sp2_b,
                              out, out + 32768);
}

// round 9
// speedup vs baseline: 4.6450x; 1.2130x over previous
#include <cuda_runtime.h>
#include <cuda_fp16.h>
#include <cstdint>

#define EPSF 1e-5f
#define NND 256
#define DD  128
#define HH  512
#define NR  65536

// -------- scratch (device globals: allocation-free rule) --------
__device__ __align__(16) float g_edges[NR * DD];
__device__ float g_adj[NR];
__device__ float g_msgs[NR];
__device__ __align__(16) float g_nodes[NND * DD];
__device__ __align__(16) float g_P[NND * HH];
__device__ __align__(16) float g_Q[NND * HH];
// pre-swizzled fp16 weight tile images: [layer 0..2][chunk 0..3][128n][128k]
__device__ __align__(16) __half g_W1h[196608];
__device__ __align__(16) __half g_W2h[196608];

// ================= low-level helpers =================
__device__ __forceinline__ uint32_t smem_to_u32(const void* p) {
    uint32_t a;
    asm("{ .reg .u64 t; cvta.to.shared.u64 t, %1; cvt.u32.u64 %0, t; }" : "=r"(a) : "l"(p));
    return a;
}
__device__ __forceinline__ void ldsm_x4(uint32_t* r, uint32_t addr) {
    asm volatile("ldmatrix.sync.aligned.m8n8.x4.shared.b16 {%0,%1,%2,%3}, [%4];"
        : "=r"(r[0]), "=r"(r[1]), "=r"(r[2]), "=r"(r[3]) : "r"(addr));
}
__device__ __forceinline__ void mma16816h(float* c, const uint32_t* a, uint32_t b0, uint32_t b1) {
    asm volatile("mma.sync.aligned.m16n8k16.row.col.f32.f16.f16.f32 "
        "{%0,%1,%2,%3}, {%4,%5,%6,%7}, {%8,%9}, {%0,%1,%2,%3};"
        : "+f"(c[0]), "+f"(c[1]), "+f"(c[2]), "+f"(c[3])
        : "r"(a[0]), "r"(a[1]), "r"(a[2]), "r"(a[3]), "r"(b0), "r"(b1));
}
__device__ __forceinline__ void cpasync16(uint32_t dst, const void* src) {
    asm volatile("cp.async.cg.shared.global [%0], [%1], 16;" :: "r"(dst), "l"(src));
}
#define CP_COMMIT() asm volatile("cp.async.commit_group;" ::: "memory")
#define CP_WAIT1()  asm volatile("cp.async.wait_group 1;" ::: "memory")
#define CP_WAIT0()  asm volatile("cp.async.wait_group 0;" ::: "memory")
__device__ __forceinline__ void pair_bar(int wN) {
    asm volatile("bar.sync %0, 64;" :: "r"(1 + wN) : "memory");
}
// fp16 hi/lo split pack of 2 floats
__device__ __forceinline__ void pack2h(float a, float b, uint32_t& hi, uint32_t& lo) {
    __half ah = __float2half_rn(a), bh = __float2half_rn(b);
    float ar = a - __half2float(ah), br = b - __half2float(bh);
    __half al = __float2half_rn(ar), bl = __float2half_rn(br);
    hi = (uint32_t)__half_as_ushort(ah) | ((uint32_t)__half_as_ushort(bh) << 16);
    lo = (uint32_t)__half_as_ushort(al) | ((uint32_t)__half_as_ushort(bl) << 16);
}
__device__ __forceinline__ uint32_t packh(float a, float b) {
    __half2 h = __floats2half2_rn(a, b);
    return reinterpret_cast<uint32_t&>(h);
}
// byte offset inside a [rows][128k] fp16 tile (256B/row, XOR-swizzled 16B chunks)
__device__ __host__ __forceinline__ uint32_t swz_off(int r, int k) {
    return (uint32_t)(r * 256 + ((((k >> 3) ^ (r & 7)) & 15) << 4) + (k & 7) * 2);
}

// ================= weight image prep (layers 0..2, fp16 single) =================
__global__ void k_prep_w(const float* __restrict__ eu1_w, const float* __restrict__ eu2_w) {
    int idx = blockIdx.x * 256 + threadIdx.x;     // < 393216
    int which = idx / 196608;
    int rem = idx - which * 196608;
    int l = rem >> 16;
    int e = rem & 65535;
    int chunk = e >> 14;
    int e2 = e & 16383;
    int n = e2 >> 7, k = e2 & 127;
    float v;
    if (which == 0) v = eu1_w[l * 196608 + k * 512 + chunk * 128 + n];
    else            v = eu2_w[l * 65536 + (chunk * 128 + k) * 128 + n];
    int dst = (l * 4 + chunk) * 16384 + (int)(swz_off(n, k) >> 1);
    if (which == 0) g_W1h[dst] = __float2half_rn(v);
    else            g_W2h[dst] = __float2half_rn(v);
}

// ================= init: copy nodes + edges embedding + adjacency =================
__global__ void k_init(const float* __restrict__ nodes_in,
                       const float* __restrict__ coords,
                       const float* __restrict__ w, const float* __restrict__ b,
                       const float* __restrict__ gg, const float* __restrict__ bb) {
    if (blockIdx.x < 64) {
        int t = blockIdx.x * 256 + threadIdx.x;
        g_nodes[t] = nodes_in[t];
        g_nodes[t + 16384] = nodes_in[t + 16384];
    }
    int warp = threadIdx.x >> 5, lane = threadIdx.x & 31;
    int row = blockIdx.x * 8 + warp;
    int i = row >> 8, j = row & 255;
    float dx = coords[i*3+0] - coords[j*3+0];
    float dy = coords[i*3+1] - coords[j*3+1];
    float dz = coords[i*3+2] - coords[j*3+2];
    float sq = dx*dx + dy*dy + dz*dz;
    float dist = sq > 0.f ? sqrtf(sq) : 0.f;
    if (lane == 0) g_adj[row] = (dist < 10.f) ? 1.f : 0.f;
    float e[4]; float s = 0.f, ss = 0.f;
#pragma unroll
    for (int t = 0; t < 4; t++) {
        int d = lane + 32*t;
        e[t] = dist * w[d] + b[d];
        s += e[t]; ss += e[t]*e[t];
    }
#pragma unroll
    for (int o = 16; o; o >>= 1) {
        s  += __shfl_xor_sync(0xffffffffu, s, o);
        ss += __shfl_xor_sync(0xffffffffu, ss, o);
    }
    float mean = s * (1.f/128.f);
    float var  = ss * (1.f/128.f) - mean*mean;
    float rs   = rsqrtf(var + EPSF);
#pragma unroll
    for (int t = 0; t < 4; t++) {
        int d = lane + 32*t;
        float v = (e[t]-mean)*rs*gg[d] + bb[d];
        g_edges[row*DD + d] = fmaxf(v, 0.f);
    }
}

// standalone msgs (used only for the last layer)
__global__ void k_msgs() {
    int warp = threadIdx.x >> 5, lane = threadIdx.x & 31;
    int row = blockIdx.x * 8 + warp;
    int i = row >> 8;
    const float4* e4 = (const float4*)(g_edges + row*DD);
    const float4* n4 = (const float4*)(g_nodes + i*DD);
    float4 a = e4[lane], c = n4[lane];
    float s = a.x*c.x + a.y*c.y + a.z*c.z + a.w*c.w;
#pragma unroll
    for (int o = 16; o; o >>= 1) s += __shfl_xor_sync(0xffffffffu, s, o);
    if (lane == 0) g_msgs[row] = g_adj[row] * s;
}

// P/Q for layer 0 (from initial nodes); grid (64,2), 512 thr
__global__ void __launch_bounds__(512) k_pq(const float* __restrict__ Wp,
                                            const float* __restrict__ Wq) {
    __shared__ float xs[512];
    int tid = threadIdx.x;
    int r0 = blockIdx.x * 4;
    const float* __restrict__ W = blockIdx.y ? Wq : Wp;
    float* out = blockIdx.y ? g_Q : g_P;
    xs[tid] = g_nodes[r0 * 128 + tid];
    __syncthreads();
    float a0 = 0.f, a1 = 0.f, a2 = 0.f, a3 = 0.f;
#pragma unroll 8
    for (int k = 0; k < 128; k++) {
        float wv = W[k * 512 + tid];
        a0 = fmaf(xs[k],       wv, a0);
        a1 = fmaf(xs[128 + k], wv, a1);
        a2 = fmaf(xs[256 + k], wv, a2);
        a3 = fmaf(xs[384 + k], wv, a3);
    }
    out[(r0+0)*512 + tid] = a0;
    out[(r0+1)*512 + tid] = a1;
    out[(r0+2)*512 + tid] = a2;
    out[(r0+3)*512 + tid] = a3;
}

// ================= HMMA fused edge update (fp16, A-reuse GEMM1, + fused msgs) =====
// smem bytes: A panels 2x32KB @0 (ah 16K + al 16K each), B 4x32KB @65536, params @196608
__global__ void __launch_bounds__(512, 1) k_edge_mma(int l,
        const float* __restrict__ b1, const float* __restrict__ gg,
        const float* __restrict__ bb, const float* __restrict__ b2) {
    extern __shared__ char sm[];
    const uint32_t S = smem_to_u32(sm);
    const int tid = threadIdx.x, lane = tid & 31;
    const int wM = (tid >> 5) & 1, wN = tid >> 6;
    const int row0 = blockIdx.x * 64;
    const int i = row0 >> 8, j0 = row0 & 255;

    const uint32_t BBs = S + 65536;       // 4 bufs x 32KB
    float* Pb    = (float*)(sm + 196608);
    float* Gam   = (float*)(sm + 198656);
    float* Bet   = (float*)(sm + 200704);
    float* B2s   = (float*)(sm + 202752);
    float* redS  = (float*)(sm + 203264);
    float* redQ  = (float*)(sm + 203520);
    float* meanS = (float*)(sm + 203776);
    float* rstdS = (float*)(sm + 204032);

    Pb[tid]  = g_P[i*512 + tid] + b1[tid];
    Gam[tid] = gg[tid];
    Bet[tid] = bb[tid];
    if (tid < 128) B2s[tid] = b2[tid];
    if (tid < 64) { redS[tid] = 0.f; redQ[tid] = 0.f; }

    // per-pair slice fill: pair wN owns B rows [wN*16, wN*16+16) = 4KB per chunk
    const int pid = tid & 63;
    auto fillw = [&](int buf, const __half* sW) {
        uint32_t d = BBs + (uint32_t)buf * 32768 + (uint32_t)wN * 4096;
        const char* g = (const char*)sW + wN * 4096;
#pragma unroll
        for (int t = 0; t < 4; t++) {
            uint32_t byo = (uint32_t)(pid + t * 64) * 16;
            cpasync16(d + byo, g + byo);
        }
        CP_COMMIT();
    };
    const __half* W1b = g_W1h + l * 65536;
    const __half* W2b = g_W2h + l * 65536;
    fillw(0, W1b); fillw(1, W1b + 16384); fillw(2, W1b + 32768); fillw(3, W1b + 49152);

    // A = edges tile -> fp16 hi/lo panel 0; fused msgs from OLD edges
    {
        const int c4 = tid & 31, k0 = c4 * 4, rb = tid >> 5;
        const float4 nv = *(const float4*)&g_nodes[(size_t)i * 128 + k0];
        float4 v[4];
#pragma unroll
        for (int t = 0; t < 4; t++)
            v[t] = *(const float4*)&g_edges[(size_t)(row0 + rb + t * 16) * 128 + k0];
#pragma unroll
        for (int t = 0; t < 4; t++) {
            int r = rb + t * 16;
            float dot = v[t].x*nv.x + v[t].y*nv.y + v[t].z*nv.z + v[t].w*nv.w;
#pragma unroll
            for (int o = 16; o; o >>= 1) dot += __shfl_xor_sync(0xffffffffu, dot, o);
            if (lane == 0) g_msgs[row0 + r] = g_adj[row0 + r] * dot;
            uint32_t h0, l0, h1, l1;
            pack2h(v[t].x, v[t].y, h0, l0);
            pack2h(v[t].z, v[t].w, h1, l1);
            uint32_t off = swz_off(r, k0);
            *(uint2*)(sm + off)         = make_uint2(h0, h1);
            *(uint2*)(sm + 16384 + off) = make_uint2(l0, l1);
        }
    }
    __syncthreads();   // A panel 0 + params visible to all

    // ---- GEMM1: ks-outer, A fragments reused across all 4 N-chunks ----
    float acc1[4][2][2][4];
#pragma unroll
    for (int a = 0; a < 4; a++)
#pragma unroll
        for (int b = 0; b < 2; b++)
#pragma unroll
            for (int c = 0; c < 2; c++)
#pragma unroll
                for (int d = 0; d < 4; d++) acc1[a][b][c][d] = 0.f;

    const int aR  = wM * 32 + (lane & 15);
    const int aKx = lane >> 4;
    const int bR  = wN * 16 + (lane & 7) + ((lane & 16) >> 1);
    const int bKx = (lane & 8) >> 3;

    CP_WAIT0();
    pair_bar(wN);
#pragma unroll
    for (int ks = 0; ks < 8; ks++) {
        uint32_t ah[2][4], al[2][4];
#pragma unroll
        for (int mt = 0; mt < 2; mt++) {
            int r = aR + mt * 16;
            uint32_t off = (uint32_t)r * 256 + (uint32_t)((((ks * 2 + aKx) ^ (r & 7)) & 15) << 4);
            ldsm_x4(ah[mt], S + off);
            ldsm_x4(al[mt], S + 16384 + off);
        }
        uint32_t boff = (uint32_t)bR * 256 + (uint32_t)((((ks * 2 + bKx) ^ (bR & 7)) & 15) << 4);
#pragma unroll
        for (int nc = 0; nc < 4; nc++) {
            uint32_t bh[4];
            ldsm_x4(bh, BBs + (uint32_t)nc * 32768 + boff);
#pragma unroll
            for (int mt = 0; mt < 2; mt++) {
                mma16816h(acc1[nc][mt][0], ah[mt], bh[0], bh[1]);
                mma16816h(acc1[nc][mt][1], ah[mt], bh[2], bh[3]);
            }
#pragma unroll
            for (int mt = 0; mt < 2; mt++) {
                mma16816h(acc1[nc][mt][0], al[mt], bh[0], bh[1]);
                mma16816h(acc1[nc][mt][1], al[mt], bh[2], bh[3]);
            }
        }
    }
    pair_bar(wN);
    // refill all 4 buffers with W2 chunks; lands during the LN epilogue
    fillw(0, W2b); fillw(1, W2b + 16384); fillw(2, W2b + 32768); fillw(3, W2b + 49152);

    // ---- epilogue: y = acc + P + Q, LN stats ----
    const int R = wM * 32 + (lane >> 2);
    const int colB = wN * 16 + (lane & 3) * 2;
    float s4[4] = {0.f, 0.f, 0.f, 0.f}, q4[4] = {0.f, 0.f, 0.f, 0.f};
#pragma unroll
    for (int nc = 0; nc < 4; nc++)
#pragma unroll
        for (int mt = 0; mt < 2; mt++)
#pragma unroll
            for (int nt = 0; nt < 2; nt++) {
                int col = nc * 128 + colB + nt * 8;
                int rA = j0 + R + mt * 16;
                float2 qa = *(const float2*)&g_Q[(size_t)rA * 512 + col];
                float2 qb = *(const float2*)&g_Q[(size_t)(rA + 8) * 512 + col];
                float p0 = Pb[col], p1 = Pb[col + 1];
                float* a = acc1[nc][mt][nt];
                a[0] += p0 + qa.x; a[1] += p1 + qa.y;
                a[2] += p0 + qb.x; a[3] += p1 + qb.y;
                s4[mt*2+0] += a[0] + a[1]; q4[mt*2+0] += a[0]*a[0] + a[1]*a[1];
                s4[mt*2+1] += a[2] + a[3]; q4[mt*2+1] += a[2]*a[2] + a[3]*a[3];
            }
#pragma unroll
    for (int o = 1; o <= 2; o <<= 1)
#pragma unroll
        for (int t = 0; t < 4; t++) {
            s4[t] += __shfl_xor_sync(0xffffffffu, s4[t], o);
            q4[t] += __shfl_xor_sync(0xffffffffu, q4[t], o);
        }
    if ((lane & 3) == 0) {
#pragma unroll
        for (int t = 0; t < 4; t++) {
            int rr = R + (t >> 1) * 16 + (t & 1) * 8;
            atomicAdd(&redS[rr], s4[t]);
            atomicAdd(&redQ[rr], q4[t]);
        }
    }
    __syncthreads();
    if (tid < 64) {
        float mean = redS[tid] * (1.f / 512.f);
        float var = redQ[tid] * (1.f / 512.f) - mean * mean;
        meanS[tid] = mean;
        rstdS[tid] = rsqrtf(var + EPSF);
    }
    __syncthreads();
    float mn[4], rs[4];
#pragma unroll
    for (int t = 0; t < 4; t++) {
        int rr = R + (t >> 1) * 16 + (t & 1) * 8;
        mn[t] = meanS[rr]; rs[t] = rstdS[rr];
    }

    // ---- GEMM2: h single-pass fp16, all W2 chunks resident ----
    float acc2[2][2][4];
#pragma unroll
    for (int b = 0; b < 2; b++)
#pragma unroll
        for (int c = 0; c < 2; c++)
#pragma unroll
            for (int d = 0; d < 4; d++) acc2[b][c][d] = 0.f;

    CP_WAIT0();
    pair_bar(wN);
#pragma unroll
    for (int kc = 0; kc < 4; kc++) {
        const uint32_t p = (uint32_t)((kc & 1) ^ 1);
        const uint32_t AHp = S + p * 32768;
#pragma unroll
        for (int mt = 0; mt < 2; mt++)
#pragma unroll
            for (int nt = 0; nt < 2; nt++) {
                int col = kc * 128 + colB + nt * 8;
                float g0 = Gam[col], g1 = Gam[col + 1];
                float be0 = Bet[col], be1 = Bet[col + 1];
                float* a = acc1[kc][mt][nt];
                float h0 = fmaxf((a[0] - mn[mt*2])   * rs[mt*2]   * g0 + be0, 0.f);
                float h1 = fmaxf((a[1] - mn[mt*2])   * rs[mt*2]   * g1 + be1, 0.f);
                float h2 = fmaxf((a[2] - mn[mt*2+1]) * rs[mt*2+1] * g0 + be0, 0.f);
                float h3 = fmaxf((a[3] - mn[mt*2+1]) * rs[mt*2+1] * g1 + be1, 0.f);
                int kl = colB + nt * 8;
                int r1 = R + mt * 16, r2 = r1 + 8;
                *(uint32_t*)(sm + p * 32768 + swz_off(r1, kl)) = packh(h0, h1);
                *(uint32_t*)(sm + p * 32768 + swz_off(r2, kl)) = packh(h2, h3);
            }
        __syncthreads();      // h panel cross-warp
        uint32_t BH = BBs + (uint32_t)kc * 32768;
#pragma unroll
        for (int ks = 0; ks < 8; ks++) {
            uint32_t ah[2][4], bh[4];
#pragma unroll
            for (int mt = 0; mt < 2; mt++) {
                int r = aR + mt * 16;
                uint32_t off = (uint32_t)r * 256 + (uint32_t)((((ks * 2 + aKx) ^ (r & 7)) & 15) << 4);
                ldsm_x4(ah[mt], AHp + off);
            }
            {
                uint32_t off = (uint32_t)bR * 256 + (uint32_t)((((ks * 2 + bKx) ^ (bR & 7)) & 15) << 4);
                ldsm_x4(bh, BH + off);
            }
#pragma unroll
            for (int mt = 0; mt < 2; mt++) {
                mma16816h(acc2[mt][0], ah[mt], bh[0], bh[1]);
                mma16816h(acc2[mt][1], ah[mt], bh[2], bh[3]);
            }
        }
    }

    // ---- output: acc2 + residual + b2 ----
#pragma unroll
    for (int mt = 0; mt < 2; mt++)
#pragma unroll
        for (int nt = 0; nt < 2; nt++) {
            int col = colB + nt * 8;
            int r1 = row0 + R + mt * 16;
            float b20 = B2s[col], b21 = B2s[col + 1];
            float2 e0 = *(const float2*)&g_edges[(size_t)r1 * 128 + col];
            float2 e1 = *(const float2*)&g_edges[(size_t)(r1 + 8) * 128 + col];
            float* a = acc2[mt][nt];
            *(float2*)&g_edges[(size_t)r1 * 128 + col]       = make_float2(a[0] + e0.x + b20, a[1] + e0.y + b21);
            *(float2*)&g_edges[(size_t)(r1 + 8) * 128 + col] = make_float2(a[2] + e1.x + b20, a[3] + e1.y + b21);
        }
}

// ================= pipelined BM=4 FFMA MLP blocks (256 threads) =================
template<int KD>
__device__ __forceinline__ void mlp4p(const float* Xs, float* Bs, float* Hs, float* red,
        const float* __restrict__ W1, const float* __restrict__ b1,
        const float* __restrict__ gg, const float* __restrict__ bb, int tid) {
    constexpr int NT = KD / 16;      // 32KB tiles (16k x 512n fp32)
    uint32_t bsa = smem_to_u32(Bs);
#pragma unroll
    for (int t = 0; t < 8; t++)
        cpasync16(bsa + tid * 16 + t * 4096, (const char*)W1 + tid * 16 + t * 4096);
    CP_COMMIT();
#pragma unroll
    for (int t = 0; t < 8; t++)
        cpasync16(bsa + 32768 + tid * 16 + t * 4096, (const char*)W1 + 32768 + tid * 16 + t * 4096);
    CP_COMMIT();

    int tr = tid >> 6, tc = tid & 63, c0 = tc * 8;
    float acc[8];
#pragma unroll
    for (int n = 0; n < 8; n++) acc[n] = 0.f;
    for (int kt = 0; kt < NT; kt++) {
        CP_WAIT1();
        __syncthreads();
        const float* B = Bs + (kt & 1) * 8192;
#pragma unroll
        for (int k = 0; k < 16; k++) {
            float a = Xs[tr * KD + kt * 16 + k];
            const float* br = &B[k * 512 + c0];
#pragma unroll
            for (int n = 0; n < 8; n++) acc[n] = fmaf(a, br[n], acc[n]);
        }
        __syncthreads();
        if (kt + 2 < NT) {
#pragma unroll
            for (int t = 0; t < 8; t++)
                cpasync16(bsa + (kt & 1) * 32768 + tid * 16 + t * 4096,
                          (const char*)W1 + (size_t)(kt + 2) * 32768 + tid * 16 + t * 4096);
        }
        CP_COMMIT();
    }
    float s = 0.f, q = 0.f;
#pragma unroll
    for (int n = 0; n < 8; n++) {
        float y = acc[n] + b1[c0 + n];
        acc[n] = y; s += y; q += y * y;
    }
#pragma unroll
    for (int o = 16; o; o >>= 1) {
        s += __shfl_xor_sync(0xffffffffu, s, o);
        q += __shfl_xor_sync(0xffffffffu, q, o);
    }
    int wid = tid >> 5;
    if ((tid & 31) == 0) { red[wid] = s; red[8 + wid] = q; }
    __syncthreads();
    {
        float S = red[2 * tr] + red[2 * tr + 1];
        float Q2 = red[8 + 2 * tr] + red[8 + 2 * tr + 1];
        float mean = S * (1.f / 512.f);
        float var = Q2 * (1.f / 512.f) - mean * mean;
        float rstd = rsqrtf(var + EPSF);
#pragma unroll
        for (int n = 0; n < 8; n++)
            Hs[tr * 512 + c0 + n] = fmaxf((acc[n] - mean) * rstd * gg[c0 + n] + bb[c0 + n], 0.f);
    }
    __syncthreads();
}

__device__ __forceinline__ void gemm2_4p(const float* Hs, float* Bs,
        const float* __restrict__ W2, int tid, float& o0, float& o1) {
    uint32_t bsa = smem_to_u32(Bs);
#pragma unroll
    for (int t = 0; t < 2; t++)
        cpasync16(bsa + tid * 16 + t * 4096, (const char*)W2 + tid * 16 + t * 4096);
    CP_COMMIT();
#pragma unroll
    for (int t = 0; t < 2; t++)
        cpasync16(bsa + 8192 + tid * 16 + t * 4096, (const char*)W2 + 8192 + tid * 16 + t * 4096);
    CP_COMMIT();
    int col = tid & 127, rp = tid >> 7;
    o0 = 0.f; o1 = 0.f;
    for (int kt = 0; kt < 32; kt++) {
        CP_WAIT1();
        __syncthreads();
        const float* B = Bs + (kt & 1) * 2048;
#pragma unroll
        for (int k = 0; k < 16; k++) {
            float w = B[k * 128 + col];
            o0 = fmaf(Hs[(2 * rp) * 512 + kt * 16 + k], w, o0);
            o1 = fmaf(Hs[(2 * rp + 1) * 512 + kt * 16 + k], w, o1);
        }
        __syncthreads();
        if (kt + 2 < 32) {
#pragma unroll
            for (int t = 0; t < 2; t++)
                cpasync16(bsa + (kt & 1) * 8192 + tid * 16 + t * 4096,
                          (const char*)W2 + (size_t)(kt + 2) * 8192 + tid * 16 + t * 4096);
        }
        CP_COMMIT();
    }
}

// node update + fused P/Q for next layer; BM=4, grid 64, 256 thr
__global__ void __launch_bounds__(256, 1) k_node(
        const float* __restrict__ W1, const float* __restrict__ b1,
        const float* __restrict__ gg, const float* __restrict__ bb,
        const float* __restrict__ W2, const float* __restrict__ b2,
        const float* __restrict__ Wp, const float* __restrict__ Wq, int do_pq) {
    extern __shared__ float smf[];
    float* Xs = smf;            // 4*384 = 1536
    float* Bs = Xs + 1536;      // 16384
    float* Hs = Bs + 16384;     // 2048
    float* Xn = Hs + 2048;      // 512
    float* red = Xn + 512;      // 16
    int tid = threadIdx.x;
    int r0 = blockIdx.x * 4;
    {
        float4* x4 = (float4*)Xs;
        if (tid < 128) {
            int row = tid >> 5, c4 = tid & 31;
            x4[row * 96 + c4] = *(const float4*)&g_nodes[(r0 + row) * 128 + c4 * 4];
        }
        int row = tid >> 6, c4 = tid & 63;
        x4[row * 96 + 32 + c4] = *(const float4*)&g_msgs[(r0 + row) * 256 + c4 * 4];
    }
    __syncthreads();
    mlp4p<384>(Xs, Bs, Hs, red, W1, b1, gg, bb, tid);
    float o0, o1;
    gemm2_4p(Hs, Bs, W2, tid, o0, o1);
    int col = tid & 127, rp = tid >> 7;
    float v0 = o0 + Xs[(2 * rp) * 384 + col] + b2[col];
    float v1 = o1 + Xs[(2 * rp + 1) * 384 + col] + b2[col];
    g_nodes[(r0 + 2 * rp) * 128 + col]     = v0;
    g_nodes[(r0 + 2 * rp + 1) * 128 + col] = v1;
    if (do_pq) {
        Xn[(2 * rp) * 128 + col] = v0;
        Xn[(2 * rp + 1) * 128 + col] = v1;
        __syncthreads();
#pragma unroll
        for (int hfl = 0; hfl < 2; hfl++) {
            int c = hfl * 256 + tid;
            float pa[4], qa[4];
#pragma unroll
            for (int r = 0; r < 4; r++) { pa[r] = 0.f; qa[r] = 0.f; }
#pragma unroll 4
            for (int k = 0; k < 128; k++) {
                float wp = Wp[k * 512 + c];
                float wq = Wq[k * 512 + c];
#pragma unroll
                for (int r = 0; r < 4; r++) {
                    pa[r] = fmaf(Xn[r * 128 + k], wp, pa[r]);
                    qa[r] = fmaf(Xn[r * 128 + k], wq, qa[r]);
                }
            }
#pragma unroll
            for (int r = 0; r < 4; r++) {
                g_P[(r0 + r) * 512 + c] = pa[r];
                g_Q[(r0 + r) * 512 + c] = qa[r];
            }
        }
    }
}

// final output head; BM=4, grid 64, 256 thr
__global__ void __launch_bounds__(256, 1) k_final(
        const float* __restrict__ no1_w, const float* __restrict__ no1_b,
        const float* __restrict__ no_g,  const float* __restrict__ no_bt,
        const float* __restrict__ no2_w, const float* __restrict__ no2_b,
        const float* __restrict__ sp1_w, const float* __restrict__ sp1_b,
        const float* __restrict__ sp_g,  const float* __restrict__ sp_bt,
        const float* __restrict__ sp2_w, const float* __restrict__ sp2_b,
        float* __restrict__ out_nodes, float* __restrict__ out_coords) {
    extern __shared__ float smf[];
    float* Xs = smf;           // 512
    float* Bs = Xs + 512;      // 16384
    float* Hs = Bs + 16384;    // 2048
    float* X2 = Hs + 2048;     // 512
    float* red = X2 + 512;     // 16
    int tid = threadIdx.x;
    int r0 = blockIdx.x * 4;
    if (tid < 128) ((float4*)Xs)[tid] = *(const float4*)&g_nodes[r0 * 128 + tid * 4];
    __syncthreads();
    mlp4p<128>(Xs, Bs, Hs, red, no1_w, no1_b, no_g, no_bt, tid);
    float o0, o1;
    gemm2_4p(Hs, Bs, no2_w, tid, o0, o1);
    int col = tid & 127, rp = tid >> 7;
    float v0 = o0 + no2_b[col], v1 = o1 + no2_b[col];
    out_nodes[(r0 + 2 * rp) * 128 + col] = v0;
    out_nodes[(r0 + 2 * rp + 1) * 128 + col] = v1;
    X2[(2 * rp) * 128 + col] = v0;
    X2[(2 * rp + 1) * 128 + col] = v1;
    __syncthreads();
    mlp4p<128>(X2, Bs, Hs, red, sp1_w, sp1_b, sp_g, sp_bt, tid);
    int g = tid >> 4;
    if (g < 12) {
        int row = g / 3, cc = g - row * 3;
        int l16 = tid & 15;
        float s = 0.f;
        for (int k = l16; k < 512; k += 16) s = fmaf(Hs[row * 512 + k], sp2_w[k * 3 + cc], s);
#pragma unroll
        for (int o = 8; o; o >>= 1) s += __shfl_xor_sync(0xffffffffu, s, o);
        if (l16 == 0) out_coords[(r0 + row) * 3 + cc] = s + sp2_b[cc];
    }
}

// ================= launcher =================
extern "C" void kernel_launch(void* const* d_in, const int* in_sizes, int n_in,
                              void* d_out, int out_size) {
    const float* nodes  = (const float*)d_in[0];
    const float* coords = (const float*)d_in[1];
    const float* ee_w   = (const float*)d_in[2];
    const float* ee_b   = (const float*)d_in[3];
    const float* ee_g   = (const float*)d_in[4];
    const float* ee_bt  = (const float*)d_in[5];
    const float* nu1_w  = (const float*)d_in[6];
    const float* nu1_b  = (const float*)d_in[7];
    const float* nu_g   = (const float*)d_in[8];
    const float* nu_bt  = (const float*)d_in[9];
    const float* nu2_w  = (const float*)d_in[10];
    const float* nu2_b  = (const float*)d_in[11];
    const float* eu1_w  = (const float*)d_in[12];
    const float* eu1_b  = (const float*)d_in[13];
    const float* eu_g   = (const float*)d_in[14];
    const float* eu_bt  = (const float*)d_in[15];
    const float* eu2_w  = (const float*)d_in[16];
    const float* eu2_b  = (const float*)d_in[17];
    const float* sp1_w  = (const float*)d_in[18];
    const float* sp1_b  = (const float*)d_in[19];
    const float* sp_g   = (const float*)d_in[20];
    const float* sp_bt  = (const float*)d_in[21];
    const float* sp2_w  = (const float*)d_in[22];
    const float* sp2_b  = (const float*)d_in[23];
    const float* no1_w  = (const float*)d_in[24];
    const float* no1_b  = (const float*)d_in[25];
    const float* no_g   = (const float*)d_in[26];
    const float* no_bt  = (const float*)d_in[27];
    const float* no2_w  = (const float*)d_in[28];
    const float* no2_b  = (const float*)d_in[29];
    float* out = (float*)d_out;

    const int SME = 204288;
    const int SMN = (1536 + 16384 + 2048 + 512 + 16) * 4;
    const int SMF = (512 + 16384 + 2048 + 512 + 16) * 4;
    cudaFuncSetAttribute(k_edge_mma, cudaFuncAttributeMaxDynamicSharedMemorySize, SME);
    cudaFuncSetAttribute(k_node,     cudaFuncAttributeMaxDynamicSharedMemorySize, SMN);
    cudaFuncSetAttribute(k_final,    cudaFuncAttributeMaxDynamicSharedMemorySize, SMF);

    k_prep_w<<<1536, 256>>>(eu1_w, eu2_w);                          // 0
    k_init<<<8192, 256>>>(nodes, coords, ee_w, ee_b, ee_g, ee_bt);  // 1
    k_pq<<<dim3(64, 2), 512>>>(eu1_w + 65536, eu1_w + 131072);      // 2 (layer 0)

    for (int l = 0; l < 3; l++) {
        k_edge_mma<<<1024, 512, SME>>>(l, eu1_b + l*512, eu_g + l*512,   // 3 (l=0): ncu slot
                                       eu_bt + l*512, eu2_b + l*128);
        int do_pq = (l < 2) ? 1 : 0;
        const float* Wp = eu1_w + (l+1)*196608 + 65536;
        const float* Wq = eu1_w + (l+1)*196608 + 131072;
        k_node<<<64, 256, SMN>>>(nu1_w + l*196608, nu1_b + l*512,
                                 nu_g + l*512, nu_bt + l*512,
                                 nu2_w + l*65536, nu2_b + l*128,
                                 Wp, Wq, do_pq);
    }
    // layer 3: edge output is dead code — msgs only
    k_msgs<<<8192, 256>>>();
    k_node<<<64, 256, SMN>>>(nu1_w + 3*196608, nu1_b + 3*512,
                             nu_g + 3*512, nu_bt + 3*512,
                             nu2_w + 3*65536, nu2_b + 3*128,
                             nu1_w, nu1_w, 0);
    k_final<<<64, 256, SMF>>>(no1_w, no1_b, no_g, no_bt, no2_w, no2_b,
                              sp1_w, sp1_b, sp_g, sp_bt, sp2_w, sp2_b,
                              out, out + 32768);
}

// round 10
// speedup vs baseline: 5.0019x; 1.0768x over previous
#include <cuda_runtime.h>
#include <cuda_fp16.h>
#include <cstdint>

#define EPSF 1e-5f
#define NND 256
#define DD  128
#define HH  512
#define NR  65536

// -------- scratch (device globals: allocation-free rule) --------
__device__ __align__(16) float g_edges[NR * DD];
__device__ float g_adj[NR];
__device__ float g_msgs[NR];
__device__ __align__(16) float g_nodes[NND * DD];
__device__ __align__(16) float g_P[NND * HH];
__device__ __align__(16) float g_Q[NND * HH];
// pre-swizzled fp16 weight tile images: [layer 0..2][chunk 0..3][128n][128k]
__device__ __align__(16) __half g_W1h[196608];
__device__ __align__(16) __half g_W2h[196608];

// ================= low-level helpers =================
__device__ __forceinline__ uint32_t smem_to_u32(const void* p) {
    uint32_t a;
    asm("{ .reg .u64 t; cvta.to.shared.u64 t, %1; cvt.u32.u64 %0, t; }" : "=r"(a) : "l"(p));
    return a;
}
__device__ __forceinline__ void ldsm_x4(uint32_t* r, uint32_t addr) {
    asm volatile("ldmatrix.sync.aligned.m8n8.x4.shared.b16 {%0,%1,%2,%3}, [%4];"
        : "=r"(r[0]), "=r"(r[1]), "=r"(r[2]), "=r"(r[3]) : "r"(addr));
}
__device__ __forceinline__ void mma16816h(float* c, const uint32_t* a, uint32_t b0, uint32_t b1) {
    asm volatile("mma.sync.aligned.m16n8k16.row.col.f32.f16.f16.f32 "
        "{%0,%1,%2,%3}, {%4,%5,%6,%7}, {%8,%9}, {%0,%1,%2,%3};"
        : "+f"(c[0]), "+f"(c[1]), "+f"(c[2]), "+f"(c[3])
        : "r"(a[0]), "r"(a[1]), "r"(a[2]), "r"(a[3]), "r"(b0), "r"(b1));
}
__device__ __forceinline__ void cpasync16(uint32_t dst, const void* src) {
    asm volatile("cp.async.cg.shared.global [%0], [%1], 16;" :: "r"(dst), "l"(src));
}
#define CP_COMMIT() asm volatile("cp.async.commit_group;" ::: "memory")
#define CP_WAIT2()  asm volatile("cp.async.wait_group 2;" ::: "memory")
#define CP_WAIT0()  asm volatile("cp.async.wait_group 0;" ::: "memory")
__device__ __forceinline__ void pair_bar(int wN) {
    asm volatile("bar.sync %0, 64;" :: "r"(1 + wN) : "memory");
}
__device__ __forceinline__ uint32_t packh(float a, float b) {
    __half2 h = __floats2half2_rn(a, b);
    return reinterpret_cast<uint32_t&>(h);
}
// byte offset inside a [rows][128k] fp16 tile (256B/row, XOR-swizzled 16B chunks)
__device__ __host__ __forceinline__ uint32_t swz_off(int r, int k) {
    return (uint32_t)(r * 256 + ((((k >> 3) ^ (r & 7)) & 15) << 4) + (k & 7) * 2);
}

// ================= weight image prep (layers 0..2, fp16 single) =================
__global__ void k_prep_w(const float* __restrict__ eu1_w, const float* __restrict__ eu2_w) {
    int idx = blockIdx.x * 256 + threadIdx.x;     // < 393216
    int which = idx / 196608;
    int rem = idx - which * 196608;
    int l = rem >> 16;
    int e = rem & 65535;
    int chunk = e >> 14;
    int e2 = e & 16383;
    int n = e2 >> 7, k = e2 & 127;
    float v;
    if (which == 0) v = eu1_w[l * 196608 + k * 512 + chunk * 128 + n];
    else            v = eu2_w[l * 65536 + (chunk * 128 + k) * 128 + n];
    int dst = (l * 4 + chunk) * 16384 + (int)(swz_off(n, k) >> 1);
    if (which == 0) g_W1h[dst] = __float2half_rn(v);
    else            g_W2h[dst] = __float2half_rn(v);
}

// ================= init: copy nodes + edges embedding + adjacency =================
__global__ void k_init(const float* __restrict__ nodes_in,
                       const float* __restrict__ coords,
                       const float* __restrict__ w, const float* __restrict__ b,
                       const float* __restrict__ gg, const float* __restrict__ bb) {
    if (blockIdx.x < 64) {
        int t = blockIdx.x * 256 + threadIdx.x;
        g_nodes[t] = nodes_in[t];
        g_nodes[t + 16384] = nodes_in[t + 16384];
    }
    int warp = threadIdx.x >> 5, lane = threadIdx.x & 31;
    int row = blockIdx.x * 8 + warp;
    int i = row >> 8, j = row & 255;
    float dx = coords[i*3+0] - coords[j*3+0];
    float dy = coords[i*3+1] - coords[j*3+1];
    float dz = coords[i*3+2] - coords[j*3+2];
    float sq = dx*dx + dy*dy + dz*dz;
    float dist = sq > 0.f ? sqrtf(sq) : 0.f;
    if (lane == 0) g_adj[row] = (dist < 10.f) ? 1.f : 0.f;
    float e[4]; float s = 0.f, ss = 0.f;
#pragma unroll
    for (int t = 0; t < 4; t++) {
        int d = lane + 32*t;
        e[t] = dist * w[d] + b[d];
        s += e[t]; ss += e[t]*e[t];
    }
#pragma unroll
    for (int o = 16; o; o >>= 1) {
        s  += __shfl_xor_sync(0xffffffffu, s, o);
        ss += __shfl_xor_sync(0xffffffffu, ss, o);
    }
    float mean = s * (1.f/128.f);
    float var  = ss * (1.f/128.f) - mean*mean;
    float rs   = rsqrtf(var + EPSF);
#pragma unroll
    for (int t = 0; t < 4; t++) {
        int d = lane + 32*t;
        float v = (e[t]-mean)*rs*gg[d] + bb[d];
        g_edges[row*DD + d] = fmaxf(v, 0.f);
    }
}

// standalone msgs (used only for the last layer)
__global__ void k_msgs() {
    int warp = threadIdx.x >> 5, lane = threadIdx.x & 31;
    int row = blockIdx.x * 8 + warp;
    int i = row >> 8;
    const float4* e4 = (const float4*)(g_edges + row*DD);
    const float4* n4 = (const float4*)(g_nodes + i*DD);
    float4 a = e4[lane], c = n4[lane];
    float s = a.x*c.x + a.y*c.y + a.z*c.z + a.w*c.w;
#pragma unroll
    for (int o = 16; o; o >>= 1) s += __shfl_xor_sync(0xffffffffu, s, o);
    if (lane == 0) g_msgs[row] = g_adj[row] * s;
}

// P/Q for layer 0 (from initial nodes); grid (64,2), 512 thr
__global__ void __launch_bounds__(512) k_pq(const float* __restrict__ Wp,
                                            const float* __restrict__ Wq) {
    __shared__ float xs[512];
    int tid = threadIdx.x;
    int r0 = blockIdx.x * 4;
    const float* __restrict__ W = blockIdx.y ? Wq : Wp;
    float* out = blockIdx.y ? g_Q : g_P;
    xs[tid] = g_nodes[r0 * 128 + tid];
    __syncthreads();
    float a0 = 0.f, a1 = 0.f, a2 = 0.f, a3 = 0.f;
#pragma unroll 8
    for (int k = 0; k < 128; k++) {
        float wv = W[k * 512 + tid];
        a0 = fmaf(xs[k],       wv, a0);
        a1 = fmaf(xs[128 + k], wv, a1);
        a2 = fmaf(xs[256 + k], wv, a2);
        a3 = fmaf(xs[384 + k], wv, a3);
    }
    out[(r0+0)*512 + tid] = a0;
    out[(r0+1)*512 + tid] = a1;
    out[(r0+2)*512 + tid] = a2;
    out[(r0+3)*512 + tid] = a3;
}

// ================= HMMA fused edge update (fp16 1-pass, + fused msgs) =====
// smem bytes: h/A panels 4x16KB @0, B 4x32KB @65536, params @196608
__global__ void __launch_bounds__(512, 1) k_edge_mma(int l,
        const float* __restrict__ b1, const float* __restrict__ gg,
        const float* __restrict__ bb, const float* __restrict__ b2) {
    extern __shared__ char sm[];
    const uint32_t S = smem_to_u32(sm);
    const int tid = threadIdx.x, lane = tid & 31;
    const int wM = (tid >> 5) & 1, wN = tid >> 6;
    const int row0 = blockIdx.x * 64;
    const int i = row0 >> 8, j0 = row0 & 255;

    const uint32_t BBs = S + 65536;       // 4 bufs x 32KB
    float* Pb    = (float*)(sm + 196608);
    float* Gam   = (float*)(sm + 198656);
    float* Bet   = (float*)(sm + 200704);
    float* B2s   = (float*)(sm + 202752);
    float* redS  = (float*)(sm + 203264);
    float* redQ  = (float*)(sm + 203520);
    float* meanS = (float*)(sm + 203776);
    float* rstdS = (float*)(sm + 204032);

    Pb[tid]  = g_P[i*512 + tid] + b1[tid];
    Gam[tid] = gg[tid];
    Bet[tid] = bb[tid];
    if (tid < 128) B2s[tid] = b2[tid];
    if (tid < 64) { redS[tid] = 0.f; redQ[tid] = 0.f; }

    // per-pair slice fill: pair wN owns B rows [wN*16, wN*16+16) = 4KB per chunk
    const int pid = tid & 63;
    auto fillw = [&](int buf, const __half* sW) {
        uint32_t d = BBs + (uint32_t)buf * 32768 + (uint32_t)wN * 4096;
        const char* g = (const char*)sW + wN * 4096;
#pragma unroll
        for (int t = 0; t < 4; t++) {
            uint32_t byo = (uint32_t)(pid + t * 64) * 16;
            cpasync16(d + byo, g + byo);
        }
        CP_COMMIT();
    };
    const __half* W1b = g_W1h + l * 65536;
    const __half* W2b = g_W2h + l * 65536;
    fillw(0, W1b); fillw(1, W1b + 16384); fillw(2, W1b + 32768); fillw(3, W1b + 49152);

    // A = edges tile -> fp16 panel 0 (single precision pass); fused msgs from OLD edges
    {
        const int c4 = tid & 31, k0 = c4 * 4, rb = tid >> 5;
        const float4 nv = *(const float4*)&g_nodes[(size_t)i * 128 + k0];
        float4 v[4];
#pragma unroll
        for (int t = 0; t < 4; t++)
            v[t] = *(const float4*)&g_edges[(size_t)(row0 + rb + t * 16) * 128 + k0];
#pragma unroll
        for (int t = 0; t < 4; t++) {
            int r = rb + t * 16;
            float dot = v[t].x*nv.x + v[t].y*nv.y + v[t].z*nv.z + v[t].w*nv.w;
#pragma unroll
            for (int o = 16; o; o >>= 1) dot += __shfl_xor_sync(0xffffffffu, dot, o);
            if (lane == 0) g_msgs[row0 + r] = g_adj[row0 + r] * dot;
            uint32_t off = swz_off(r, k0);
            *(uint2*)(sm + off) = make_uint2(packh(v[t].x, v[t].y), packh(v[t].z, v[t].w));
        }
    }
    __syncthreads();   // A panel 0 + params visible to all

    // ---- GEMM1: ks-outer, A fragments reused across all 4 N-chunks ----
    float acc1[4][2][2][4];
#pragma unroll
    for (int a = 0; a < 4; a++)
#pragma unroll
        for (int b = 0; b < 2; b++)
#pragma unroll
            for (int c = 0; c < 2; c++)
#pragma unroll
                for (int d = 0; d < 4; d++) acc1[a][b][c][d] = 0.f;

    const int aR  = wM * 32 + (lane & 15);
    const int aKx = lane >> 4;
    const int bR  = wN * 16 + (lane & 7) + ((lane & 16) >> 1);
    const int bKx = (lane & 8) >> 3;

    CP_WAIT0();
    pair_bar(wN);
#pragma unroll
    for (int ks = 0; ks < 8; ks++) {
        uint32_t ah[2][4];
#pragma unroll
        for (int mt = 0; mt < 2; mt++) {
            int r = aR + mt * 16;
            uint32_t off = (uint32_t)r * 256 + (uint32_t)((((ks * 2 + aKx) ^ (r & 7)) & 15) << 4);
            ldsm_x4(ah[mt], S + off);
        }
        uint32_t boff = (uint32_t)bR * 256 + (uint32_t)((((ks * 2 + bKx) ^ (bR & 7)) & 15) << 4);
#pragma unroll
        for (int nc = 0; nc < 4; nc++) {
            uint32_t bh[4];
            ldsm_x4(bh, BBs + (uint32_t)nc * 32768 + boff);
#pragma unroll
            for (int mt = 0; mt < 2; mt++) {
                mma16816h(acc1[nc][mt][0], ah[mt], bh[0], bh[1]);
                mma16816h(acc1[nc][mt][1], ah[mt], bh[2], bh[3]);
            }
        }
    }
    pair_bar(wN);
    // refill all 4 buffers with W2 chunks; lands during the LN epilogue
    fillw(0, W2b); fillw(1, W2b + 16384); fillw(2, W2b + 32768); fillw(3, W2b + 49152);

    // ---- epilogue: y = acc + P + Q, LN stats ----
    const int R = wM * 32 + (lane >> 2);
    const int colB = wN * 16 + (lane & 3) * 2;
    float s4[4] = {0.f, 0.f, 0.f, 0.f}, q4[4] = {0.f, 0.f, 0.f, 0.f};
#pragma unroll
    for (int nc = 0; nc < 4; nc++)
#pragma unroll
        for (int mt = 0; mt < 2; mt++)
#pragma unroll
            for (int nt = 0; nt < 2; nt++) {
                int col = nc * 128 + colB + nt * 8;
                int rA = j0 + R + mt * 16;
                float2 qa = *(const float2*)&g_Q[(size_t)rA * 512 + col];
                float2 qb = *(const float2*)&g_Q[(size_t)(rA + 8) * 512 + col];
                float p0 = Pb[col], p1 = Pb[col + 1];
                float* a = acc1[nc][mt][nt];
                a[0] += p0 + qa.x; a[1] += p1 + qa.y;
                a[2] += p0 + qb.x; a[3] += p1 + qb.y;
                s4[mt*2+0] += a[0] + a[1]; q4[mt*2+0] += a[0]*a[0] + a[1]*a[1];
                s4[mt*2+1] += a[2] + a[3]; q4[mt*2+1] += a[2]*a[2] + a[3]*a[3];
            }
#pragma unroll
    for (int o = 1; o <= 2; o <<= 1)
#pragma unroll
        for (int t = 0; t < 4; t++) {
            s4[t] += __shfl_xor_sync(0xffffffffu, s4[t], o);
            q4[t] += __shfl_xor_sync(0xffffffffu, q4[t], o);
        }
    if ((lane & 3) == 0) {
#pragma unroll
        for (int t = 0; t < 4; t++) {
            int rr = R + (t >> 1) * 16 + (t & 1) * 8;
            atomicAdd(&redS[rr], s4[t]);
            atomicAdd(&redQ[rr], q4[t]);
        }
    }
    __syncthreads();
    if (tid < 64) {
        float mean = redS[tid] * (1.f / 512.f);
        float var = redQ[tid] * (1.f / 512.f) - mean * mean;
        meanS[tid] = mean;
        rstdS[tid] = rsqrtf(var + EPSF);
    }
    __syncthreads();
    float mn[4], rs[4];
#pragma unroll
    for (int t = 0; t < 4; t++) {
        int rr = R + (t >> 1) * 16 + (t & 1) * 8;
        mn[t] = meanS[rr]; rs[t] = rstdS[rr];
    }

    // ---- stage ALL normalized h chunks into 4 panels, one sync ----
#pragma unroll
    for (int kc = 0; kc < 4; kc++) {
        const uint32_t base = S + (uint32_t)kc * 16384;
#pragma unroll
        for (int mt = 0; mt < 2; mt++)
#pragma unroll
            for (int nt = 0; nt < 2; nt++) {
                int col = kc * 128 + colB + nt * 8;
                float g0 = Gam[col], g1 = Gam[col + 1];
                float be0 = Bet[col], be1 = Bet[col + 1];
                float* a = acc1[kc][mt][nt];
                float h0 = fmaxf((a[0] - mn[mt*2])   * rs[mt*2]   * g0 + be0, 0.f);
                float h1 = fmaxf((a[1] - mn[mt*2])   * rs[mt*2]   * g1 + be1, 0.f);
                float h2 = fmaxf((a[2] - mn[mt*2+1]) * rs[mt*2+1] * g0 + be0, 0.f);
                float h3 = fmaxf((a[3] - mn[mt*2+1]) * rs[mt*2+1] * g1 + be1, 0.f);
                int kl = colB + nt * 8;
                int r1 = R + mt * 16, r2 = r1 + 8;
                *(uint32_t*)((char*)(void*)sm + (base - S) + swz_off(r1, kl)) = packh(h0, h1);
                *(uint32_t*)((char*)(void*)sm + (base - S) + swz_off(r2, kl)) = packh(h2, h3);
            }
    }
    CP_WAIT0();
    __syncthreads();   // h panels + W2 bufs visible to all

    // ---- GEMM2: barrier-free, all W2 chunks + h panels resident ----
    float acc2[2][2][4];
#pragma unroll
    for (int b = 0; b < 2; b++)
#pragma unroll
        for (int c = 0; c < 2; c++)
#pragma unroll
            for (int d = 0; d < 4; d++) acc2[b][c][d] = 0.f;

#pragma unroll
    for (int kc = 0; kc < 4; kc++) {
        const uint32_t AHp = S + (uint32_t)kc * 16384;
        const uint32_t BH = BBs + (uint32_t)kc * 32768;
#pragma unroll
        for (int ks = 0; ks < 8; ks++) {
            uint32_t ah[2][4], bh[4];
#pragma unroll
            for (int mt = 0; mt < 2; mt++) {
                int r = aR + mt * 16;
                uint32_t off = (uint32_t)r * 256 + (uint32_t)((((ks * 2 + aKx) ^ (r & 7)) & 15) << 4);
                ldsm_x4(ah[mt], AHp + off);
            }
            {
                uint32_t off = (uint32_t)bR * 256 + (uint32_t)((((ks * 2 + bKx) ^ (bR & 7)) & 15) << 4);
                ldsm_x4(bh, BH + off);
            }
#pragma unroll
            for (int mt = 0; mt < 2; mt++) {
                mma16816h(acc2[mt][0], ah[mt], bh[0], bh[1]);
                mma16816h(acc2[mt][1], ah[mt], bh[2], bh[3]);
            }
        }
    }

    // ---- output: acc2 + residual + b2 ----
#pragma unroll
    for (int mt = 0; mt < 2; mt++)
#pragma unroll
        for (int nt = 0; nt < 2; nt++) {
            int col = colB + nt * 8;
            int r1 = row0 + R + mt * 16;
            float b20 = B2s[col], b21 = B2s[col + 1];
            float2 e0 = *(const float2*)&g_edges[(size_t)r1 * 128 + col];
            float2 e1 = *(const float2*)&g_edges[(size_t)(r1 + 8) * 128 + col];
            float* a = acc2[mt][nt];
            *(float2*)&g_edges[(size_t)r1 * 128 + col]       = make_float2(a[0] + e0.x + b20, a[1] + e0.y + b21);
            *(float2*)&g_edges[(size_t)(r1 + 8) * 128 + col] = make_float2(a[2] + e1.x + b20, a[3] + e1.y + b21);
        }
}

// ================= 3-deep pipelined BM=4 FFMA MLP blocks (256 threads) ==========
template<int KD>
__device__ __forceinline__ void mlp4p(const float* Xs, float* Bs, float* Hs, float* red,
        const float* __restrict__ W1, const float* __restrict__ b1,
        const float* __restrict__ gg, const float* __restrict__ bb, int tid) {
    constexpr int NT = KD / 16;      // 32KB tiles (16k x 512n fp32), 3 buffers
    uint32_t bsa = smem_to_u32(Bs);
#pragma unroll
    for (int pre = 0; pre < 3; pre++) {
#pragma unroll
        for (int t = 0; t < 8; t++)
            cpasync16(bsa + (uint32_t)pre * 32768 + tid * 16 + t * 4096,
                      (const char*)W1 + (size_t)pre * 32768 + tid * 16 + t * 4096);
        CP_COMMIT();
    }
    int tr = tid >> 6, tc = tid & 63, c0 = tc * 8;
    float acc[8];
#pragma unroll
    for (int n = 0; n < 8; n++) acc[n] = 0.f;
    int buf = 0;
    for (int kt = 0; kt < NT; kt++) {
        CP_WAIT2();
        __syncthreads();
        const float* B = Bs + buf * 8192;
#pragma unroll
        for (int k = 0; k < 16; k++) {
            float a = Xs[tr * KD + kt * 16 + k];
            const float* br = &B[k * 512 + c0];
#pragma unroll
            for (int n = 0; n < 8; n++) acc[n] = fmaf(a, br[n], acc[n]);
        }
        __syncthreads();
        if (kt + 3 < NT) {
#pragma unroll
            for (int t = 0; t < 8; t++)
                cpasync16(bsa + (uint32_t)buf * 32768 + tid * 16 + t * 4096,
                          (const char*)W1 + (size_t)(kt + 3) * 32768 + tid * 16 + t * 4096);
        }
        CP_COMMIT();
        buf = (buf == 2) ? 0 : buf + 1;
    }
    float s = 0.f, q = 0.f;
#pragma unroll
    for (int n = 0; n < 8; n++) {
        float y = acc[n] + b1[c0 + n];
        acc[n] = y; s += y; q += y * y;
    }
#pragma unroll
    for (int o = 16; o; o >>= 1) {
        s += __shfl_xor_sync(0xffffffffu, s, o);
        q += __shfl_xor_sync(0xffffffffu, q, o);
    }
    int wid = tid >> 5;
    if ((tid & 31) == 0) { red[wid] = s; red[8 + wid] = q; }
    __syncthreads();
    {
        float S = red[2 * tr] + red[2 * tr + 1];
        float Q2 = red[8 + 2 * tr] + red[8 + 2 * tr + 1];
        float mean = S * (1.f / 512.f);
        float var = Q2 * (1.f / 512.f) - mean * mean;
        float rstd = rsqrtf(var + EPSF);
#pragma unroll
        for (int n = 0; n < 8; n++)
            Hs[tr * 512 + c0 + n] = fmaxf((acc[n] - mean) * rstd * gg[c0 + n] + bb[c0 + n], 0.f);
    }
    __syncthreads();
}

__device__ __forceinline__ void gemm2_4p(const float* Hs, float* Bs,
        const float* __restrict__ W2, int tid, float& o0, float& o1) {
    uint32_t bsa = smem_to_u32(Bs);
#pragma unroll
    for (int pre = 0; pre < 3; pre++) {
#pragma unroll
        for (int t = 0; t < 2; t++)
            cpasync16(bsa + (uint32_t)pre * 8192 + tid * 16 + t * 4096,
                      (const char*)W2 + (size_t)pre * 8192 + tid * 16 + t * 4096);
        CP_COMMIT();
    }
    int col = tid & 127, rp = tid >> 7;
    o0 = 0.f; o1 = 0.f;
    int buf = 0;
    for (int kt = 0; kt < 32; kt++) {
        CP_WAIT2();
        __syncthreads();
        const float* B = Bs + buf * 2048;
#pragma unroll
        for (int k = 0; k < 16; k++) {
            float w = B[k * 128 + col];
            o0 = fmaf(Hs[(2 * rp) * 512 + kt * 16 + k], w, o0);
            o1 = fmaf(Hs[(2 * rp + 1) * 512 + kt * 16 + k], w, o1);
        }
        __syncthreads();
        if (kt + 3 < 32) {
#pragma unroll
            for (int t = 0; t < 2; t++)
                cpasync16(bsa + (uint32_t)buf * 8192 + tid * 16 + t * 4096,
                          (const char*)W2 + (size_t)(kt + 3) * 8192 + tid * 16 + t * 4096);
        }
        CP_COMMIT();
        buf = (buf == 2) ? 0 : buf + 1;
    }
}

// node update + fused P/Q for next layer; BM=4, grid 64, 256 thr
__global__ void __launch_bounds__(256, 1) k_node(
        const float* __restrict__ W1, const float* __restrict__ b1,
        const float* __restrict__ gg, const float* __restrict__ bb,
        const float* __restrict__ W2, const float* __restrict__ b2,
        const float* __restrict__ Wp, const float* __restrict__ Wq, int do_pq) {
    extern __shared__ float smf[];
    float* Xs = smf;            // 4*384 = 1536
    float* Bs = Xs + 1536;      // 24576 (3x 32KB tiles)
    float* Hs = Bs + 24576;     // 2048
    float* Xn = Hs + 2048;      // 512
    float* red = Xn + 512;      // 16
    int tid = threadIdx.x;
    int r0 = blockIdx.x * 4;
    {
        float4* x4 = (float4*)Xs;
        if (tid < 128) {
            int row = tid >> 5, c4 = tid & 31;
            x4[row * 96 + c4] = *(const float4*)&g_nodes[(r0 + row) * 128 + c4 * 4];
        }
        int row = tid >> 6, c4 = tid & 63;
        x4[row * 96 + 32 + c4] = *(const float4*)&g_msgs[(r0 + row) * 256 + c4 * 4];
    }
    __syncthreads();
    mlp4p<384>(Xs, Bs, Hs, red, W1, b1, gg, bb, tid);
    float o0, o1;
    gemm2_4p(Hs, Bs, W2, tid, o0, o1);
    int col = tid & 127, rp = tid >> 7;
    float v0 = o0 + Xs[(2 * rp) * 384 + col] + b2[col];
    float v1 = o1 + Xs[(2 * rp + 1) * 384 + col] + b2[col];
    g_nodes[(r0 + 2 * rp) * 128 + col]     = v0;
    g_nodes[(r0 + 2 * rp + 1) * 128 + col] = v1;
    if (do_pq) {
        Xn[(2 * rp) * 128 + col] = v0;
        Xn[(2 * rp + 1) * 128 + col] = v1;
        __syncthreads();
#pragma unroll
        for (int hfl = 0; hfl < 2; hfl++) {
            int c = hfl * 256 + tid;
            float pa[4], qa[4];
#pragma unroll
            for (int r = 0; r < 4; r++) { pa[r] = 0.f; qa[r] = 0.f; }
#pragma unroll 4
            for (int k = 0; k < 128; k++) {
                float wp = Wp[k * 512 + c];
                float wq = Wq[k * 512 + c];
#pragma unroll
                for (int r = 0; r < 4; r++) {
                    pa[r] = fmaf(Xn[r * 128 + k], wp, pa[r]);
                    qa[r] = fmaf(Xn[r * 128 + k], wq, qa[r]);
                }
            }
#pragma unroll
            for (int r = 0; r < 4; r++) {
                g_P[(r0 + r) * 512 + c] = pa[r];
                g_Q[(r0 + r) * 512 + c] = qa[r];
            }
        }
    }
}

// final output head; BM=4, grid 64, 256 thr
__global__ void __launch_bounds__(256, 1) k_final(
        const float* __restrict__ no1_w, const float* __restrict__ no1_b,
        const float* __restrict__ no_g,  const float* __restrict__ no_bt,
        const float* __restrict__ no2_w, const float* __restrict__ no2_b,
        const float* __restrict__ sp1_w, const float* __restrict__ sp1_b,
        const float* __restrict__ sp_g,  const float* __restrict__ sp_bt,
        const float* __restrict__ sp2_w, const float* __restrict__ sp2_b,
        float* __restrict__ out_nodes, float* __restrict__ out_coords) {
    extern __shared__ float smf[];
    float* Xs = smf;           // 512
    float* Bs = Xs + 512;      // 24576
    float* Hs = Bs + 24576;    // 2048
    float* X2 = Hs + 2048;     // 512
    float* red = X2 + 512;     // 16
    int tid = threadIdx.x;
    int r0 = blockIdx.x * 4;
    if (tid < 128) ((float4*)Xs)[tid] = *(const float4*)&g_nodes[r0 * 128 + tid * 4];
    __syncthreads();
    mlp4p<128>(Xs, Bs, Hs, red, no1_w, no1_b, no_g, no_bt, tid);
    float o0, o1;
    gemm2_4p(Hs, Bs, no2_w, tid, o0, o1);
    int col = tid & 127, rp = tid >> 7;
    float v0 = o0 + no2_b[col], v1 = o1 + no2_b[col];
    out_nodes[(r0 + 2 * rp) * 128 + col] = v0;
    out_nodes[(r0 + 2 * rp + 1) * 128 + col] = v1;
    X2[(2 * rp) * 128 + col] = v0;
    X2[(2 * rp + 1) * 128 + col] = v1;
    __syncthreads();
    mlp4p<128>(X2, Bs, Hs, red, sp1_w, sp1_b, sp_g, sp_bt, tid);
    int g = tid >> 4;
    if (g < 12) {
        int row = g / 3, cc = g - row * 3;
        int l16 = tid & 15;
        float s = 0.f;
        for (int k = l16; k < 512; k += 16) s = fmaf(Hs[row * 512 + k], sp2_w[k * 3 + cc], s);
#pragma unroll
        for (int o = 8; o; o >>= 1) s += __shfl_xor_sync(0xffffffffu, s, o);
        if (l16 == 0) out_coords[(r0 + row) * 3 + cc] = s + sp2_b[cc];
    }
}

// ================= launcher =================
extern "C" void kernel_launch(void* const* d_in, const int* in_sizes, int n_in,
                              void* d_out, int out_size) {
    const float* nodes  = (const float*)d_in[0];
    const float* coords = (const float*)d_in[1];
    const float* ee_w   = (const float*)d_in[2];
    const float* ee_b   = (const float*)d_in[3];
    const float* ee_g   = (const float*)d_in[4];
    const float* ee_bt  = (const float*)d_in[5];
    const float* nu1_w  = (const float*)d_in[6];
    const float* nu1_b  = (const float*)d_in[7];
    const float* nu_g   = (const float*)d_in[8];
    const float* nu_bt  = (const float*)d_in[9];
    const float* nu2_w  = (const float*)d_in[10];
    const float* nu2_b  = (const float*)d_in[11];
    const float* eu1_w  = (const float*)d_in[12];
    const float* eu1_b  = (const float*)d_in[13];
    const float* eu_g   = (const float*)d_in[14];
    const float* eu_bt  = (const float*)d_in[15];
    const float* eu2_w  = (const float*)d_in[16];
    const float* eu2_b  = (const float*)d_in[17];
    const float* sp1_w  = (const float*)d_in[18];
    const float* sp1_b  = (const float*)d_in[19];
    const float* sp_g   = (const float*)d_in[20];
    const float* sp_bt  = (const float*)d_in[21];
    const float* sp2_w  = (const float*)d_in[22];
    const float* sp2_b  = (const float*)d_in[23];
    const float* no1_w  = (const float*)d_in[24];
    const float* no1_b  = (const float*)d_in[25];
    const float* no_g   = (const float*)d_in[26];
    const float* no_bt  = (const float*)d_in[27];
    const float* no2_w  = (const float*)d_in[28];
    const float* no2_b  = (const float*)d_in[29];
    float* out = (float*)d_out;

    const int SME = 204288;
    const int SMN = (1536 + 24576 + 2048 + 512 + 16) * 4;   // 114752
    const int SMF = (512 + 24576 + 2048 + 512 + 16) * 4;    // 110656
    cudaFuncSetAttribute(k_edge_mma, cudaFuncAttributeMaxDynamicSharedMemorySize, SME);
    cudaFuncSetAttribute(k_node,     cudaFuncAttributeMaxDynamicSharedMemorySize, SMN);
    cudaFuncSetAttribute(k_final,    cudaFuncAttributeMaxDynamicSharedMemorySize, SMF);

    k_prep_w<<<1536, 256>>>(eu1_w, eu2_w);                          // 0
    k_init<<<8192, 256>>>(nodes, coords, ee_w, ee_b, ee_g, ee_bt);  // 1
    k_pq<<<dim3(64, 2), 512>>>(eu1_w + 65536, eu1_w + 131072);      // 2 (layer 0)

    for (int l = 0; l < 3; l++) {
        k_edge_mma<<<1024, 512, SME>>>(l, eu1_b + l*512, eu_g + l*512,   // 3 (l=0): ncu slot
                                       eu_bt + l*512, eu2_b + l*128);
        int do_pq = (l < 2) ? 1 : 0;
        const float* Wp = eu1_w + (l+1)*196608 + 65536;
        const float* Wq = eu1_w + (l+1)*196608 + 131072;
        k_node<<<64, 256, SMN>>>(nu1_w + l*196608, nu1_b + l*512,
                                 nu_g + l*512, nu_bt + l*512,
                                 nu2_w + l*65536, nu2_b + l*128,
                                 Wp, Wq, do_pq);
    }
    // layer 3: edge output is dead code — msgs only
    k_msgs<<<8192, 256>>>();
    k_node<<<64, 256, SMN>>>(nu1_w + 3*196608, nu1_b + 3*512,
                             nu_g + 3*512, nu_bt + 3*512,
                             nu2_w + 3*65536, nu2_b + 3*128,
                             nu1_w, nu1_w, 0);
    k_final<<<64, 256, SMF>>>(no1_w, no1_b, no_g, no_bt, no2_w, no2_b,
                              sp1_w, sp1_b, sp_g, sp_bt, sp2_w, sp2_b,
                              out, out + 32768);
}

// round 11
// speedup vs baseline: 5.2649x; 1.0526x over previous
#include <cuda_runtime.h>
#include <cuda_fp16.h>
#include <cstdint>

#define EPSF 1e-5f
#define NND 256
#define DD  128
#define HH  512
#define NR  65536

// -------- scratch (device globals: allocation-free rule) --------
__device__ __align__(16) float g_edges[NR * DD];
__device__ float g_adj[NR];
__device__ float g_msgs[NR];
__device__ __align__(16) float g_nodes[NND * DD];
__device__ __align__(16) float g_P[NND * HH];
__device__ __align__(16) float g_Q[NND * HH];
// pre-swizzled fp16 weight tile images: [layer 0..2][chunk 0..3][128n][128k]
__device__ __align__(16) __half g_W1h[196608];
__device__ __align__(16) __half g_W2h[196608];

// ================= low-level helpers =================
__device__ __forceinline__ uint32_t smem_to_u32(const void* p) {
    uint32_t a;
    asm("{ .reg .u64 t; cvta.to.shared.u64 t, %1; cvt.u32.u64 %0, t; }" : "=r"(a) : "l"(p));
    return a;
}
__device__ __forceinline__ void ldsm_x4(uint32_t* r, uint32_t addr) {
    asm volatile("ldmatrix.sync.aligned.m8n8.x4.shared.b16 {%0,%1,%2,%3}, [%4];"
        : "=r"(r[0]), "=r"(r[1]), "=r"(r[2]), "=r"(r[3]) : "r"(addr));
}
__device__ __forceinline__ void mma16816h(float* c, const uint32_t* a, uint32_t b0, uint32_t b1) {
    asm volatile("mma.sync.aligned.m16n8k16.row.col.f32.f16.f16.f32 "
        "{%0,%1,%2,%3}, {%4,%5,%6,%7}, {%8,%9}, {%0,%1,%2,%3};"
        : "+f"(c[0]), "+f"(c[1]), "+f"(c[2]), "+f"(c[3])
        : "r"(a[0]), "r"(a[1]), "r"(a[2]), "r"(a[3]), "r"(b0), "r"(b1));
}
__device__ __forceinline__ void cpasync16(uint32_t dst, const void* src) {
    asm volatile("cp.async.cg.shared.global [%0], [%1], 16;" :: "r"(dst), "l"(src));
}
#define CP_COMMIT() asm volatile("cp.async.commit_group;" ::: "memory")
#define CP_WAIT2()  asm volatile("cp.async.wait_group 2;" ::: "memory")
#define CP_WAIT0()  asm volatile("cp.async.wait_group 0;" ::: "memory")
__device__ __forceinline__ void pair_bar(int wN) {
    asm volatile("bar.sync %0, 64;" :: "r"(1 + wN) : "memory");
}
__device__ __forceinline__ uint32_t packh(float a, float b) {
    __half2 h = __floats2half2_rn(a, b);
    return reinterpret_cast<uint32_t&>(h);
}
// byte offset inside a [rows][128k] fp16 tile (256B/row, XOR-swizzled 16B chunks)
__device__ __host__ __forceinline__ uint32_t swz_off(int r, int k) {
    return (uint32_t)(r * 256 + ((((k >> 3) ^ (r & 7)) & 15) << 4) + (k & 7) * 2);
}

// ================= init (fused): nodes copy + edge embedding + weight prep =======
__global__ void k_init(const float* __restrict__ nodes_in,
                       const float* __restrict__ coords,
                       const float* __restrict__ w, const float* __restrict__ b,
                       const float* __restrict__ gg, const float* __restrict__ bb,
                       const float* __restrict__ eu1_w, const float* __restrict__ eu2_w) {
    if (blockIdx.x >= 8192) {
        // weight image prep (layers 0..2, fp16)
        int idx = (blockIdx.x - 8192) * 256 + threadIdx.x;   // < 393216
        int which = idx / 196608;
        int rem = idx - which * 196608;
        int l = rem >> 16;
        int e = rem & 65535;
        int chunk = e >> 14;
        int e2 = e & 16383;
        int n = e2 >> 7, k = e2 & 127;
        float v;
        if (which == 0) v = eu1_w[l * 196608 + k * 512 + chunk * 128 + n];
        else            v = eu2_w[l * 65536 + (chunk * 128 + k) * 128 + n];
        int dst = (l * 4 + chunk) * 16384 + (int)(swz_off(n, k) >> 1);
        if (which == 0) g_W1h[dst] = __float2half_rn(v);
        else            g_W2h[dst] = __float2half_rn(v);
        return;
    }
    if (blockIdx.x < 64) {
        int t = blockIdx.x * 256 + threadIdx.x;
        g_nodes[t] = nodes_in[t];
        g_nodes[t + 16384] = nodes_in[t + 16384];
    }
    int warp = threadIdx.x >> 5, lane = threadIdx.x & 31;
    int row = blockIdx.x * 8 + warp;
    int i = row >> 8, j = row & 255;
    float dx = coords[i*3+0] - coords[j*3+0];
    float dy = coords[i*3+1] - coords[j*3+1];
    float dz = coords[i*3+2] - coords[j*3+2];
    float sq = dx*dx + dy*dy + dz*dz;
    float dist = sq > 0.f ? sqrtf(sq) : 0.f;
    if (lane == 0) g_adj[row] = (dist < 10.f) ? 1.f : 0.f;
    float e[4]; float s = 0.f, ss = 0.f;
#pragma unroll
    for (int t = 0; t < 4; t++) {
        int d = lane + 32*t;
        e[t] = dist * w[d] + b[d];
        s += e[t]; ss += e[t]*e[t];
    }
#pragma unroll
    for (int o = 16; o; o >>= 1) {
        s  += __shfl_xor_sync(0xffffffffu, s, o);
        ss += __shfl_xor_sync(0xffffffffu, ss, o);
    }
    float mean = s * (1.f/128.f);
    float var  = ss * (1.f/128.f) - mean*mean;
    float rs   = rsqrtf(var + EPSF);
#pragma unroll
    for (int t = 0; t < 4; t++) {
        int d = lane + 32*t;
        float v = (e[t]-mean)*rs*gg[d] + bb[d];
        g_edges[row*DD + d] = fmaxf(v, 0.f);
    }
}

// standalone msgs (used only for the last layer)
__global__ void k_msgs() {
    int warp = threadIdx.x >> 5, lane = threadIdx.x & 31;
    int row = blockIdx.x * 8 + warp;
    int i = row >> 8;
    const float4* e4 = (const float4*)(g_edges + row*DD);
    const float4* n4 = (const float4*)(g_nodes + i*DD);
    float4 a = e4[lane], c = n4[lane];
    float s = a.x*c.x + a.y*c.y + a.z*c.z + a.w*c.w;
#pragma unroll
    for (int o = 16; o; o >>= 1) s += __shfl_xor_sync(0xffffffffu, s, o);
    if (lane == 0) g_msgs[row] = g_adj[row] * s;
}

// P/Q for layer 0 (from initial nodes); grid (64,2), 512 thr
__global__ void __launch_bounds__(512) k_pq(const float* __restrict__ Wp,
                                            const float* __restrict__ Wq) {
    __shared__ float xs[512];
    int tid = threadIdx.x;
    int r0 = blockIdx.x * 4;
    const float* __restrict__ W = blockIdx.y ? Wq : Wp;
    float* out = blockIdx.y ? g_Q : g_P;
    xs[tid] = g_nodes[r0 * 128 + tid];
    __syncthreads();
    float a0 = 0.f, a1 = 0.f, a2 = 0.f, a3 = 0.f;
#pragma unroll 8
    for (int k = 0; k < 128; k++) {
        float wv = W[k * 512 + tid];
        a0 = fmaf(xs[k],       wv, a0);
        a1 = fmaf(xs[128 + k], wv, a1);
        a2 = fmaf(xs[256 + k], wv, a2);
        a3 = fmaf(xs[384 + k], wv, a3);
    }
    out[(r0+0)*512 + tid] = a0;
    out[(r0+1)*512 + tid] = a1;
    out[(r0+2)*512 + tid] = a2;
    out[(r0+3)*512 + tid] = a3;
}

// ================= HMMA fused edge update (fp16 1-pass, + fused msgs) =====
// smem bytes: h/A panels 4x16KB @0, B 4x32KB @65536, params @196608
__global__ void __launch_bounds__(512, 1) k_edge_mma(int l,
        const float* __restrict__ b1, const float* __restrict__ gg,
        const float* __restrict__ bb, const float* __restrict__ b2) {
    extern __shared__ char sm[];
    const uint32_t S = smem_to_u32(sm);
    const int tid = threadIdx.x, lane = tid & 31;
    const int wM = (tid >> 5) & 1, wN = tid >> 6;
    const int row0 = blockIdx.x * 64;
    const int i = row0 >> 8, j0 = row0 & 255;

    const uint32_t BBs = S + 65536;       // 4 bufs x 32KB
    float* Pb    = (float*)(sm + 196608);
    float* Gam   = (float*)(sm + 198656);
    float* Bet   = (float*)(sm + 200704);
    float* B2s   = (float*)(sm + 202752);
    float* redPS = (float*)(sm + 203264);   // [8][64]
    float* redPQ = (float*)(sm + 205312);   // [8][64]
    float* meanS = (float*)(sm + 207360);
    float* rstdS = (float*)(sm + 207616);

    Pb[tid]  = g_P[i*512 + tid] + b1[tid];
    Gam[tid] = gg[tid];
    Bet[tid] = bb[tid];
    if (tid < 128) B2s[tid] = b2[tid];

    // per-pair slice fill: pair wN owns B rows [wN*16, wN*16+16) = 4KB per chunk
    const int pid = tid & 63;
    auto fillw = [&](int buf, const __half* sW) {
        uint32_t d = BBs + (uint32_t)buf * 32768 + (uint32_t)wN * 4096;
        const char* g = (const char*)sW + wN * 4096;
#pragma unroll
        for (int t = 0; t < 4; t++) {
            uint32_t byo = (uint32_t)(pid + t * 64) * 16;
            cpasync16(d + byo, g + byo);
        }
        CP_COMMIT();
    };
    const __half* W1b = g_W1h + l * 65536;
    const __half* W2b = g_W2h + l * 65536;
    fillw(0, W1b); fillw(1, W1b + 16384); fillw(2, W1b + 32768); fillw(3, W1b + 49152);

    // A = edges tile -> fp16 panel 0; fused msgs from OLD edges
    {
        const int c4 = tid & 31, k0 = c4 * 4, rb = tid >> 5;
        const float4 nv = *(const float4*)&g_nodes[(size_t)i * 128 + k0];
        float4 v[4];
#pragma unroll
        for (int t = 0; t < 4; t++)
            v[t] = *(const float4*)&g_edges[(size_t)(row0 + rb + t * 16) * 128 + k0];
#pragma unroll
        for (int t = 0; t < 4; t++) {
            int r = rb + t * 16;
            float dot = v[t].x*nv.x + v[t].y*nv.y + v[t].z*nv.z + v[t].w*nv.w;
#pragma unroll
            for (int o = 16; o; o >>= 1) dot += __shfl_xor_sync(0xffffffffu, dot, o);
            if (lane == 0) g_msgs[row0 + r] = g_adj[row0 + r] * dot;
            uint32_t off = swz_off(r, k0);
            *(uint2*)(sm + off) = make_uint2(packh(v[t].x, v[t].y), packh(v[t].z, v[t].w));
        }
    }
    __syncthreads();   // A panel 0 + params visible to all

    // ---- GEMM1: ks-outer, A fragments reused across all 4 N-chunks ----
    float acc1[4][2][2][4];
#pragma unroll
    for (int a = 0; a < 4; a++)
#pragma unroll
        for (int b = 0; b < 2; b++)
#pragma unroll
            for (int c = 0; c < 2; c++)
#pragma unroll
                for (int d = 0; d < 4; d++) acc1[a][b][c][d] = 0.f;

    const int aR  = wM * 32 + (lane & 15);
    const int aKx = lane >> 4;
    const int bR  = wN * 16 + (lane & 7) + ((lane & 16) >> 1);
    const int bKx = (lane & 8) >> 3;

    CP_WAIT0();
    pair_bar(wN);
#pragma unroll
    for (int ks = 0; ks < 8; ks++) {
        uint32_t ah[2][4];
#pragma unroll
        for (int mt = 0; mt < 2; mt++) {
            int r = aR + mt * 16;
            uint32_t off = (uint32_t)r * 256 + (uint32_t)((((ks * 2 + aKx) ^ (r & 7)) & 15) << 4);
            ldsm_x4(ah[mt], S + off);
        }
        uint32_t boff = (uint32_t)bR * 256 + (uint32_t)((((ks * 2 + bKx) ^ (bR & 7)) & 15) << 4);
#pragma unroll
        for (int nc = 0; nc < 4; nc++) {
            uint32_t bh[4];
            ldsm_x4(bh, BBs + (uint32_t)nc * 32768 + boff);
#pragma unroll
            for (int mt = 0; mt < 2; mt++) {
                mma16816h(acc1[nc][mt][0], ah[mt], bh[0], bh[1]);
                mma16816h(acc1[nc][mt][1], ah[mt], bh[2], bh[3]);
            }
        }
    }
    pair_bar(wN);
    // refill all 4 buffers with W2 chunks; lands during the LN epilogue
    fillw(0, W2b); fillw(1, W2b + 16384); fillw(2, W2b + 32768); fillw(3, W2b + 49152);

    // ---- epilogue: y = acc + P + Q, LN stats (smem partials, no atomics) ----
    const int R = wM * 32 + (lane >> 2);
    const int colB = wN * 16 + (lane & 3) * 2;
    float s4[4] = {0.f, 0.f, 0.f, 0.f}, q4[4] = {0.f, 0.f, 0.f, 0.f};
#pragma unroll
    for (int nc = 0; nc < 4; nc++)
#pragma unroll
        for (int mt = 0; mt < 2; mt++)
#pragma unroll
            for (int nt = 0; nt < 2; nt++) {
                int col = nc * 128 + colB + nt * 8;
                int rA = j0 + R + mt * 16;
                float2 qa = *(const float2*)&g_Q[(size_t)rA * 512 + col];
                float2 qb = *(const float2*)&g_Q[(size_t)(rA + 8) * 512 + col];
                float p0 = Pb[col], p1 = Pb[col + 1];
                float* a = acc1[nc][mt][nt];
                a[0] += p0 + qa.x; a[1] += p1 + qa.y;
                a[2] += p0 + qb.x; a[3] += p1 + qb.y;
                s4[mt*2+0] += a[0] + a[1]; q4[mt*2+0] += a[0]*a[0] + a[1]*a[1];
                s4[mt*2+1] += a[2] + a[3]; q4[mt*2+1] += a[2]*a[2] + a[3]*a[3];
            }
#pragma unroll
    for (int o = 1; o <= 2; o <<= 1)
#pragma unroll
        for (int t = 0; t < 4; t++) {
            s4[t] += __shfl_xor_sync(0xffffffffu, s4[t], o);
            q4[t] += __shfl_xor_sync(0xffffffffu, q4[t], o);
        }
    if ((lane & 3) == 0) {
#pragma unroll
        for (int t = 0; t < 4; t++) {
            int rr = R + (t >> 1) * 16 + (t & 1) * 8;
            redPS[wN * 64 + rr] = s4[t];
            redPQ[wN * 64 + rr] = q4[t];
        }
    }
    __syncthreads();
    if (tid < 64) {
        float Ssum = 0.f, Qsum = 0.f;
#pragma unroll
        for (int p = 0; p < 8; p++) {
            Ssum += redPS[p * 64 + tid];
            Qsum += redPQ[p * 64 + tid];
        }
        float mean = Ssum * (1.f / 512.f);
        float var = Qsum * (1.f / 512.f) - mean * mean;
        meanS[tid] = mean;
        rstdS[tid] = rsqrtf(var + EPSF);
    }
    __syncthreads();
    float mn[4], rs[4];
#pragma unroll
    for (int t = 0; t < 4; t++) {
        int rr = R + (t >> 1) * 16 + (t & 1) * 8;
        mn[t] = meanS[rr]; rs[t] = rstdS[rr];
    }

    // ---- stage ALL normalized h chunks into 4 panels, one sync ----
#pragma unroll
    for (int kc = 0; kc < 4; kc++) {
        const uint32_t pb = (uint32_t)kc * 16384;
#pragma unroll
        for (int mt = 0; mt < 2; mt++)
#pragma unroll
            for (int nt = 0; nt < 2; nt++) {
                int col = kc * 128 + colB + nt * 8;
                float g0 = Gam[col], g1 = Gam[col + 1];
                float be0 = Bet[col], be1 = Bet[col + 1];
                float* a = acc1[kc][mt][nt];
                float h0 = fmaxf((a[0] - mn[mt*2])   * rs[mt*2]   * g0 + be0, 0.f);
                float h1 = fmaxf((a[1] - mn[mt*2])   * rs[mt*2]   * g1 + be1, 0.f);
                float h2 = fmaxf((a[2] - mn[mt*2+1]) * rs[mt*2+1] * g0 + be0, 0.f);
                float h3 = fmaxf((a[3] - mn[mt*2+1]) * rs[mt*2+1] * g1 + be1, 0.f);
                int kl = colB + nt * 8;
                int r1 = R + mt * 16, r2 = r1 + 8;
                *(uint32_t*)(sm + pb + swz_off(r1, kl)) = packh(h0, h1);
                *(uint32_t*)(sm + pb + swz_off(r2, kl)) = packh(h2, h3);
            }
    }
    CP_WAIT0();
    __syncthreads();   // h panels + W2 bufs visible to all

    // prefetch residual (hidden under GEMM2)
    float2 e0r[2][2], e1r[2][2];
#pragma unroll
    for (int mt = 0; mt < 2; mt++)
#pragma unroll
        for (int nt = 0; nt < 2; nt++) {
            int col = colB + nt * 8;
            int r1 = row0 + R + mt * 16;
            e0r[mt][nt] = *(const float2*)&g_edges[(size_t)r1 * 128 + col];
            e1r[mt][nt] = *(const float2*)&g_edges[(size_t)(r1 + 8) * 128 + col];
        }

    // ---- GEMM2: barrier-free, all W2 chunks + h panels resident ----
    float acc2[2][2][4];
#pragma unroll
    for (int b = 0; b < 2; b++)
#pragma unroll
        for (int c = 0; c < 2; c++)
#pragma unroll
            for (int d = 0; d < 4; d++) acc2[b][c][d] = 0.f;

#pragma unroll
    for (int kc = 0; kc < 4; kc++) {
        const uint32_t AHp = S + (uint32_t)kc * 16384;
        const uint32_t BH = BBs + (uint32_t)kc * 32768;
#pragma unroll
        for (int ks = 0; ks < 8; ks++) {
            uint32_t ah[2][4], bh[4];
#pragma unroll
            for (int mt = 0; mt < 2; mt++) {
                int r = aR + mt * 16;
                uint32_t off = (uint32_t)r * 256 + (uint32_t)((((ks * 2 + aKx) ^ (r & 7)) & 15) << 4);
                ldsm_x4(ah[mt], AHp + off);
            }
            {
                uint32_t off = (uint32_t)bR * 256 + (uint32_t)((((ks * 2 + bKx) ^ (bR & 7)) & 15) << 4);
                ldsm_x4(bh, BH + off);
            }
#pragma unroll
            for (int mt = 0; mt < 2; mt++) {
                mma16816h(acc2[mt][0], ah[mt], bh[0], bh[1]);
                mma16816h(acc2[mt][1], ah[mt], bh[2], bh[3]);
            }
        }
    }

    // ---- output: acc2 + residual + b2 ----
#pragma unroll
    for (int mt = 0; mt < 2; mt++)
#pragma unroll
        for (int nt = 0; nt < 2; nt++) {
            int col = colB + nt * 8;
            int r1 = row0 + R + mt * 16;
            float b20 = B2s[col], b21 = B2s[col + 1];
            float* a = acc2[mt][nt];
            *(float2*)&g_edges[(size_t)r1 * 128 + col] =
                make_float2(a[0] + e0r[mt][nt].x + b20, a[1] + e0r[mt][nt].y + b21);
            *(float2*)&g_edges[(size_t)(r1 + 8) * 128 + col] =
                make_float2(a[2] + e1r[mt][nt].x + b20, a[3] + e1r[mt][nt].y + b21);
        }
}

// ================= 3-deep pipelined BM=4 FFMA MLP blocks (256 threads) ==========
template<int KD>
__device__ __forceinline__ void mlp4p(const float* Xs, float* Bs, float* Hs, float* red,
        const float* __restrict__ W1, const float* __restrict__ b1,
        const float* __restrict__ gg, const float* __restrict__ bb, int tid) {
    constexpr int NT = KD / 16;      // 32KB tiles (16k x 512n fp32), 3 buffers
    uint32_t bsa = smem_to_u32(Bs);
#pragma unroll
    for (int pre = 0; pre < 3; pre++) {
#pragma unroll
        for (int t = 0; t < 8; t++)
            cpasync16(bsa + (uint32_t)pre * 32768 + tid * 16 + t * 4096,
                      (const char*)W1 + (size_t)pre * 32768 + tid * 16 + t * 4096);
        CP_COMMIT();
    }
    int tr = tid >> 6, tc = tid & 63, c0 = tc * 8;
    float acc[8];
#pragma unroll
    for (int n = 0; n < 8; n++) acc[n] = 0.f;
    int buf = 0;
    for (int kt = 0; kt < NT; kt++) {
        CP_WAIT2();
        __syncthreads();
        const float* B = Bs + buf * 8192;
#pragma unroll
        for (int k = 0; k < 16; k++) {
            float a = Xs[tr * KD + kt * 16 + k];
            const float* br = &B[k * 512 + c0];
#pragma unroll
            for (int n = 0; n < 8; n++) acc[n] = fmaf(a, br[n], acc[n]);
        }
        __syncthreads();
        if (kt + 3 < NT) {
#pragma unroll
            for (int t = 0; t < 8; t++)
                cpasync16(bsa + (uint32_t)buf * 32768 + tid * 16 + t * 4096,
                          (const char*)W1 + (size_t)(kt + 3) * 32768 + tid * 16 + t * 4096);
        }
        CP_COMMIT();
        buf = (buf == 2) ? 0 : buf + 1;
    }
    float s = 0.f, q = 0.f;
#pragma unroll
    for (int n = 0; n < 8; n++) {
        float y = acc[n] + b1[c0 + n];
        acc[n] = y; s += y; q += y * y;
    }
#pragma unroll
    for (int o = 16; o; o >>= 1) {
        s += __shfl_xor_sync(0xffffffffu, s, o);
        q += __shfl_xor_sync(0xffffffffu, q, o);
    }
    int wid = tid >> 5;
    if ((tid & 31) == 0) { red[wid] = s; red[8 + wid] = q; }
    __syncthreads();
    {
        float S = red[2 * tr] + red[2 * tr + 1];
        float Q2 = red[8 + 2 * tr] + red[8 + 2 * tr + 1];
        float mean = S * (1.f / 512.f);
        float var = Q2 * (1.f / 512.f) - mean * mean;
        float rstd = rsqrtf(var + EPSF);
#pragma unroll
        for (int n = 0; n < 8; n++)
            Hs[tr * 512 + c0 + n] = fmaxf((acc[n] - mean) * rstd * gg[c0 + n] + bb[c0 + n], 0.f);
    }
    __syncthreads();
}

__device__ __forceinline__ void gemm2_4p(const float* Hs, float* Bs,
        const float* __restrict__ W2, int tid, float& o0, float& o1) {
    uint32_t bsa = smem_to_u32(Bs);
#pragma unroll
    for (int pre = 0; pre < 3; pre++) {
#pragma unroll
        for (int t = 0; t < 2; t++)
            cpasync16(bsa + (uint32_t)pre * 8192 + tid * 16 + t * 4096,
                      (const char*)W2 + (size_t)pre * 8192 + tid * 16 + t * 4096);
        CP_COMMIT();
    }
    int col = tid & 127, rp = tid >> 7;
    o0 = 0.f; o1 = 0.f;
    int buf = 0;
    for (int kt = 0; kt < 32; kt++) {
        CP_WAIT2();
        __syncthreads();
        const float* B = Bs + buf * 2048;
#pragma unroll
        for (int k = 0; k < 16; k++) {
            float w = B[k * 128 + col];
            o0 = fmaf(Hs[(2 * rp) * 512 + kt * 16 + k], w, o0);
            o1 = fmaf(Hs[(2 * rp + 1) * 512 + kt * 16 + k], w, o1);
        }
        __syncthreads();
        if (kt + 3 < 32) {
#pragma unroll
            for (int t = 0; t < 2; t++)
                cpasync16(bsa + (uint32_t)buf * 8192 + tid * 16 + t * 4096,
                          (const char*)W2 + (size_t)(kt + 3) * 8192 + tid * 16 + t * 4096);
        }
        CP_COMMIT();
        buf = (buf == 2) ? 0 : buf + 1;
    }
}

// node update + fused pipelined P/Q for next layer; BM=4, grid 64, 256 thr
__global__ void __launch_bounds__(256, 1) k_node(
        const float* __restrict__ W1, const float* __restrict__ b1,
        const float* __restrict__ gg, const float* __restrict__ bb,
        const float* __restrict__ W2, const float* __restrict__ b2,
        const float* __restrict__ Wp, const float* __restrict__ Wq, int do_pq) {
    extern __shared__ float smf[];
    float* Xs = smf;            // 4*384 = 1536
    float* Bs = Xs + 1536;      // 24576 (3x 32KB tiles)
    float* Hs = Bs + 24576;     // 2048
    float* Xn = Hs + 2048;      // 512
    float* red = Xn + 512;      // 16
    int tid = threadIdx.x;
    int r0 = blockIdx.x * 4;
    {
        float4* x4 = (float4*)Xs;
        if (tid < 128) {
            int row = tid >> 5, c4 = tid & 31;
            x4[row * 96 + c4] = *(const float4*)&g_nodes[(r0 + row) * 128 + c4 * 4];
        }
        int row = tid >> 6, c4 = tid & 63;
        x4[row * 96 + 32 + c4] = *(const float4*)&g_msgs[(r0 + row) * 256 + c4 * 4];
    }
    __syncthreads();
    mlp4p<384>(Xs, Bs, Hs, red, W1, b1, gg, bb, tid);
    float o0, o1;
    gemm2_4p(Hs, Bs, W2, tid, o0, o1);
    int col = tid & 127, rp = tid >> 7;
    float v0 = o0 + Xs[(2 * rp) * 384 + col] + b2[col];
    float v1 = o1 + Xs[(2 * rp + 1) * 384 + col] + b2[col];
    g_nodes[(r0 + 2 * rp) * 128 + col]     = v0;
    g_nodes[(r0 + 2 * rp + 1) * 128 + col] = v1;
    if (do_pq) {
        Xn[(2 * rp) * 128 + col] = v0;
        Xn[(2 * rp + 1) * 128 + col] = v1;
        __syncthreads();
        // pipelined P/Q: 16 tiles (8 of Wp, 8 of Wq), each 16k x 512n fp32 (32KB)
        uint32_t bsa = smem_to_u32(Bs);
#pragma unroll
        for (int pre = 0; pre < 3; pre++) {
            const char* s = (const char*)Wp + (size_t)pre * 32768;
#pragma unroll
            for (int t = 0; t < 8; t++)
                cpasync16(bsa + (uint32_t)pre * 32768 + tid * 16 + t * 4096,
                          s + tid * 16 + t * 4096);
            CP_COMMIT();
        }
        float pa[8];
#pragma unroll
        for (int r = 0; r < 8; r++) pa[r] = 0.f;
        int buf = 0;
        for (int tile = 0; tile < 16; tile++) {
            CP_WAIT2();
            __syncthreads();
            const float* B = Bs + buf * 8192;
            int kb = (tile & 7) * 16;
#pragma unroll
            for (int k = 0; k < 16; k++) {
                float w0 = B[k * 512 + tid];
                float w1 = B[k * 512 + 256 + tid];
#pragma unroll
                for (int r = 0; r < 4; r++) {
                    float x = Xn[r * 128 + kb + k];
                    pa[r]     = fmaf(x, w0, pa[r]);
                    pa[4 + r] = fmaf(x, w1, pa[4 + r]);
                }
            }
            __syncthreads();
            if (tile + 3 < 16) {
                int nt = tile + 3;
                const char* s = (const char*)((nt >> 3) ? Wq : Wp) + (size_t)(nt & 7) * 32768;
#pragma unroll
                for (int t = 0; t < 8; t++)
                    cpasync16(bsa + (uint32_t)buf * 32768 + tid * 16 + t * 4096,
                              s + tid * 16 + t * 4096);
            }
            CP_COMMIT();
            buf = (buf == 2) ? 0 : buf + 1;
            if (tile == 7) {
#pragma unroll
                for (int r = 0; r < 4; r++) {
                    g_P[(r0 + r) * 512 + tid]       = pa[r];
                    g_P[(r0 + r) * 512 + 256 + tid] = pa[4 + r];
                }
#pragma unroll
                for (int r = 0; r < 8; r++) pa[r] = 0.f;
            }
        }
#pragma unroll
        for (int r = 0; r < 4; r++) {
            g_Q[(r0 + r) * 512 + tid]       = pa[r];
            g_Q[(r0 + r) * 512 + 256 + tid] = pa[4 + r];
        }
    }
}

// final output head; BM=4, grid 64, 256 thr
__global__ void __launch_bounds__(256, 1) k_final(
        const float* __restrict__ no1_w, const float* __restrict__ no1_b,
        const float* __restrict__ no_g,  const float* __restrict__ no_bt,
        const float* __restrict__ no2_w, const float* __restrict__ no2_b,
        const float* __restrict__ sp1_w, const float* __restrict__ sp1_b,
        const float* __restrict__ sp_g,  const float* __restrict__ sp_bt,
        const float* __restrict__ sp2_w, const float* __restrict__ sp2_b,
        float* __restrict__ out_nodes, float* __restrict__ out_coords) {
    extern __shared__ float smf[];
    float* Xs = smf;           // 512
    float* Bs = Xs + 512;      // 24576
    float* Hs = Bs + 24576;    // 2048
    float* X2 = Hs + 2048;     // 512
    float* red = X2 + 512;     // 16
    int tid = threadIdx.x;
    int r0 = blockIdx.x * 4;
    if (tid < 128) ((float4*)Xs)[tid] = *(const float4*)&g_nodes[r0 * 128 + tid * 4];
    __syncthreads();
    mlp4p<128>(Xs, Bs, Hs, red, no1_w, no1_b, no_g, no_bt, tid);
    float o0, o1;
    gemm2_4p(Hs, Bs, no2_w, tid, o0, o1);
    int col = tid & 127, rp = tid >> 7;
    float v0 = o0 + no2_b[col], v1 = o1 + no2_b[col];
    out_nodes[(r0 + 2 * rp) * 128 + col] = v0;
    out_nodes[(r0 + 2 * rp + 1) * 128 + col] = v1;
    X2[(2 * rp) * 128 + col] = v0;
    X2[(2 * rp + 1) * 128 + col] = v1;
    __syncthreads();
    mlp4p<128>(X2, Bs, Hs, red, sp1_w, sp1_b, sp_g, sp_bt, tid);
    int g = tid >> 4;
    if (g < 12) {
        int row = g / 3, cc = g - row * 3;
        int l16 = tid & 15;
        float s = 0.f;
        for (int k = l16; k < 512; k += 16) s = fmaf(Hs[row * 512 + k], sp2_w[k * 3 + cc], s);
#pragma unroll
        for (int o = 8; o; o >>= 1) s += __shfl_xor_sync(0xffffffffu, s, o);
        if (l16 == 0) out_coords[(r0 + row) * 3 + cc] = s + sp2_b[cc];
    }
}

// ================= launcher =================
extern "C" void kernel_launch(void* const* d_in, const int* in_sizes, int n_in,
                              void* d_out, int out_size) {
    const float* nodes  = (const float*)d_in[0];
    const float* coords = (const float*)d_in[1];
    const float* ee_w   = (const float*)d_in[2];
    const float* ee_b   = (const float*)d_in[3];
    const float* ee_g   = (const float*)d_in[4];
    const float* ee_bt  = (const float*)d_in[5];
    const float* nu1_w  = (const float*)d_in[6];
    const float* nu1_b  = (const float*)d_in[7];
    const float* nu_g   = (const float*)d_in[8];
    const float* nu_bt  = (const float*)d_in[9];
    const float* nu2_w  = (const float*)d_in[10];
    const float* nu2_b  = (const float*)d_in[11];
    const float* eu1_w  = (const float*)d_in[12];
    const float* eu1_b  = (const float*)d_in[13];
    const float* eu_g   = (const float*)d_in[14];
    const float* eu_bt  = (const float*)d_in[15];
    const float* eu2_w  = (const float*)d_in[16];
    const float* eu2_b  = (const float*)d_in[17];
    const float* sp1_w  = (const float*)d_in[18];
    const float* sp1_b  = (const float*)d_in[19];
    const float* sp_g   = (const float*)d_in[20];
    const float* sp_bt  = (const float*)d_in[21];
    const float* sp2_w  = (const float*)d_in[22];
    const float* sp2_b  = (const float*)d_in[23];
    const float* no1_w  = (const float*)d_in[24];
    const float* no1_b  = (const float*)d_in[25];
    const float* no_g   = (const float*)d_in[26];
    const float* no_bt  = (const float*)d_in[27];
    const float* no2_w  = (const float*)d_in[28];
    const float* no2_b  = (const float*)d_in[29];
    float* out = (float*)d_out;

    const int SME = 207872;
    const int SMN = (1536 + 24576 + 2048 + 512 + 16) * 4;   // 114752
    const int SMF = (512 + 24576 + 2048 + 512 + 16) * 4;    // 110656
    cudaFuncSetAttribute(k_edge_mma, cudaFuncAttributeMaxDynamicSharedMemorySize, SME);
    cudaFuncSetAttribute(k_node,     cudaFuncAttributeMaxDynamicSharedMemorySize, SMN);
    cudaFuncSetAttribute(k_final,    cudaFuncAttributeMaxDynamicSharedMemorySize, SMF);

    k_init<<<9728, 256>>>(nodes, coords, ee_w, ee_b, ee_g, ee_bt, eu1_w, eu2_w);  // 0
    k_pq<<<dim3(64, 2), 512>>>(eu1_w + 65536, eu1_w + 131072);                    // 1

    for (int l = 0; l < 3; l++) {
        k_edge_mma<<<1024, 512, SME>>>(l, eu1_b + l*512, eu_g + l*512,   // 2 (l=0)
                                       eu_bt + l*512, eu2_b + l*128);
        int do_pq = (l < 2) ? 1 : 0;
        const float* Wp = eu1_w + (l+1)*196608 + 65536;
        const float* Wq = eu1_w + (l+1)*196608 + 131072;
        k_node<<<64, 256, SMN>>>(nu1_w + l*196608, nu1_b + l*512,        // 3 (l=0): ncu slot
                                 nu_g + l*512, nu_bt + l*512,
                                 nu2_w + l*65536, nu2_b + l*128,
                                 Wp, Wq, do_pq);
    }
    // layer 3: edge output is dead code — msgs only
    k_msgs<<<8192, 256>>>();
    k_node<<<64, 256, SMN>>>(nu1_w + 3*196608, nu1_b + 3*512,
                             nu_g + 3*512, nu_bt + 3*512,
                             nu2_w + 3*65536, nu2_b + 3*128,
                             nu1_w, nu1_w, 0);
    k_final<<<64, 256, SMF>>>(no1_w, no1_b, no_g, no_bt, no2_w, no2_b,
                              sp1_w, sp1_b, sp_g, sp_bt, sp2_w, sp2_b,
                              out, out + 32768);
}

// round 12
// speedup vs baseline: 6.6262x; 1.2586x over previous
#include <cuda_runtime.h>
#include <cuda_fp16.h>
#include <cstdint>

#define EPSF 1e-5f
#define NND 256
#define DD  128
#define HH  512
#define NR  65536

// -------- scratch (device globals: allocation-free rule) --------
__device__ __align__(16) float g_edges[NR * DD];
__device__ float g_adj[NR];
__device__ float g_msgs[NR];
__device__ __align__(16) float g_nodes[NND * DD];
__device__ __align__(16) float g_P[NND * HH];
__device__ __align__(16) float g_Q[NND * HH];
// pre-swizzled fp16 weight tile images: [layer 0..2][chunk 0..3][128n][128k]
__device__ __align__(16) __half g_W1h[196608];
__device__ __align__(16) __half g_W2h[196608];

// ================= low-level helpers =================
__device__ __forceinline__ uint32_t smem_to_u32(const void* p) {
    uint32_t a;
    asm("{ .reg .u64 t; cvta.to.shared.u64 t, %1; cvt.u32.u64 %0, t; }" : "=r"(a) : "l"(p));
    return a;
}
__device__ __forceinline__ void ldsm_x4(uint32_t* r, uint32_t addr) {
    asm volatile("ldmatrix.sync.aligned.m8n8.x4.shared.b16 {%0,%1,%2,%3}, [%4];"
        : "=r"(r[0]), "=r"(r[1]), "=r"(r[2]), "=r"(r[3]) : "r"(addr));
}
__device__ __forceinline__ void mma16816h(float* c, const uint32_t* a, uint32_t b0, uint32_t b1) {
    asm volatile("mma.sync.aligned.m16n8k16.row.col.f32.f16.f16.f32 "
        "{%0,%1,%2,%3}, {%4,%5,%6,%7}, {%8,%9}, {%0,%1,%2,%3};"
        : "+f"(c[0]), "+f"(c[1]), "+f"(c[2]), "+f"(c[3])
        : "r"(a[0]), "r"(a[1]), "r"(a[2]), "r"(a[3]), "r"(b0), "r"(b1));
}
__device__ __forceinline__ void cpasync16(uint32_t dst, const void* src) {
    asm volatile("cp.async.cg.shared.global [%0], [%1], 16;" :: "r"(dst), "l"(src));
}
#define CP_COMMIT() asm volatile("cp.async.commit_group;" ::: "memory")
#define CP_WAIT0()  asm volatile("cp.async.wait_group 0;" ::: "memory")
__device__ __forceinline__ void pair_bar(int wN) {
    asm volatile("bar.sync %0, 64;" :: "r"(1 + wN) : "memory");
}
__device__ __forceinline__ uint32_t packh(float a, float b) {
    __half2 h = __floats2half2_rn(a, b);
    return reinterpret_cast<uint32_t&>(h);
}
// byte offset inside a [rows][128k] fp16 tile (256B/row, XOR-swizzled 16B chunks)
__device__ __host__ __forceinline__ uint32_t swz_off(int r, int k) {
    return (uint32_t)(r * 256 + ((((k >> 3) ^ (r & 7)) & 15) << 4) + (k & 7) * 2);
}

// ================= init (fused): nodes copy + edge embedding + weight prep =======
__global__ void k_init(const float* __restrict__ nodes_in,
                       const float* __restrict__ coords,
                       const float* __restrict__ w, const float* __restrict__ b,
                       const float* __restrict__ gg, const float* __restrict__ bb,
                       const float* __restrict__ eu1_w, const float* __restrict__ eu2_w) {
    if (blockIdx.x >= 8192) {
        int idx = (blockIdx.x - 8192) * 256 + threadIdx.x;   // < 393216
        int which = idx / 196608;
        int rem = idx - which * 196608;
        int l = rem >> 16;
        int e = rem & 65535;
        int chunk = e >> 14;
        int e2 = e & 16383;
        int n = e2 >> 7, k = e2 & 127;
        float v;
        if (which == 0) v = eu1_w[l * 196608 + k * 512 + chunk * 128 + n];
        else            v = eu2_w[l * 65536 + (chunk * 128 + k) * 128 + n];
        int dst = (l * 4 + chunk) * 16384 + (int)(swz_off(n, k) >> 1);
        if (which == 0) g_W1h[dst] = __float2half_rn(v);
        else            g_W2h[dst] = __float2half_rn(v);
        return;
    }
    if (blockIdx.x < 64) {
        int t = blockIdx.x * 256 + threadIdx.x;
        g_nodes[t] = nodes_in[t];
        g_nodes[t + 16384] = nodes_in[t + 16384];
    }
    int warp = threadIdx.x >> 5, lane = threadIdx.x & 31;
    int row = blockIdx.x * 8 + warp;
    int i = row >> 8, j = row & 255;
    float dx = coords[i*3+0] - coords[j*3+0];
    float dy = coords[i*3+1] - coords[j*3+1];
    float dz = coords[i*3+2] - coords[j*3+2];
    float sq = dx*dx + dy*dy + dz*dz;
    float dist = sq > 0.f ? sqrtf(sq) : 0.f;
    if (lane == 0) g_adj[row] = (dist < 10.f) ? 1.f : 0.f;
    float e[4]; float s = 0.f, ss = 0.f;
#pragma unroll
    for (int t = 0; t < 4; t++) {
        int d = lane + 32*t;
        e[t] = dist * w[d] + b[d];
        s += e[t]; ss += e[t]*e[t];
    }
#pragma unroll
    for (int o = 16; o; o >>= 1) {
        s  += __shfl_xor_sync(0xffffffffu, s, o);
        ss += __shfl_xor_sync(0xffffffffu, ss, o);
    }
    float mean = s * (1.f/128.f);
    float var  = ss * (1.f/128.f) - mean*mean;
    float rs   = rsqrtf(var + EPSF);
#pragma unroll
    for (int t = 0; t < 4; t++) {
        int d = lane + 32*t;
        float v = (e[t]-mean)*rs*gg[d] + bb[d];
        g_edges[row*DD + d] = fmaxf(v, 0.f);
    }
}

// standalone msgs (used only for the last layer)
__global__ void k_msgs() {
    int warp = threadIdx.x >> 5, lane = threadIdx.x & 31;
    int row = blockIdx.x * 8 + warp;
    int i = row >> 8;
    const float4* e4 = (const float4*)(g_edges + row*DD);
    const float4* n4 = (const float4*)(g_nodes + i*DD);
    float4 a = e4[lane], c = n4[lane];
    float s = a.x*c.x + a.y*c.y + a.z*c.z + a.w*c.w;
#pragma unroll
    for (int o = 16; o; o >>= 1) s += __shfl_xor_sync(0xffffffffu, s, o);
    if (lane == 0) g_msgs[row] = g_adj[row] * s;
}

// P/Q for layer 0 (from initial nodes); grid (64,2), 512 thr
__global__ void __launch_bounds__(512) k_pq(const float* __restrict__ Wp,
                                            const float* __restrict__ Wq) {
    __shared__ float xs[512];
    int tid = threadIdx.x;
    int r0 = blockIdx.x * 4;
    const float* __restrict__ W = blockIdx.y ? Wq : Wp;
    float* out = blockIdx.y ? g_Q : g_P;
    xs[tid] = g_nodes[r0 * 128 + tid];
    __syncthreads();
    float a0 = 0.f, a1 = 0.f, a2 = 0.f, a3 = 0.f;
#pragma unroll 8
    for (int k = 0; k < 128; k++) {
        float wv = W[k * 512 + tid];
        a0 = fmaf(xs[k],       wv, a0);
        a1 = fmaf(xs[128 + k], wv, a1);
        a2 = fmaf(xs[256 + k], wv, a2);
        a3 = fmaf(xs[384 + k], wv, a3);
    }
    out[(r0+0)*512 + tid] = a0;
    out[(r0+1)*512 + tid] = a1;
    out[(r0+2)*512 + tid] = a2;
    out[(r0+3)*512 + tid] = a3;
}

// ================= HMMA fused edge update (fp16 1-pass, + fused msgs) =====
// smem bytes: h/A panels 4x16KB @0, B 4x32KB @65536, params @196608
__global__ void __launch_bounds__(512, 1) k_edge_mma(int l,
        const float* __restrict__ b1, const float* __restrict__ gg,
        const float* __restrict__ bb, const float* __restrict__ b2) {
    extern __shared__ char sm[];
    const uint32_t S = smem_to_u32(sm);
    const int tid = threadIdx.x, lane = tid & 31;
    const int wM = (tid >> 5) & 1, wN = tid >> 6;
    const int row0 = blockIdx.x * 64;
    const int i = row0 >> 8, j0 = row0 & 255;

    const uint32_t BBs = S + 65536;       // 4 bufs x 32KB
    float* Pb    = (float*)(sm + 196608);
    float* Gam   = (float*)(sm + 198656);
    float* Bet   = (float*)(sm + 200704);
    float* B2s   = (float*)(sm + 202752);
    float* redPS = (float*)(sm + 203264);   // [8][64]
    float* redPQ = (float*)(sm + 205312);   // [8][64]
    float* meanS = (float*)(sm + 207360);
    float* rstdS = (float*)(sm + 207616);

    Pb[tid]  = g_P[i*512 + tid] + b1[tid];
    Gam[tid] = gg[tid];
    Bet[tid] = bb[tid];
    if (tid < 128) B2s[tid] = b2[tid];

    const int pid = tid & 63;
    auto fillw = [&](int buf, const __half* sW) {
        uint32_t d = BBs + (uint32_t)buf * 32768 + (uint32_t)wN * 4096;
        const char* g = (const char*)sW + wN * 4096;
#pragma unroll
        for (int t = 0; t < 4; t++) {
            uint32_t byo = (uint32_t)(pid + t * 64) * 16;
            cpasync16(d + byo, g + byo);
        }
        CP_COMMIT();
    };
    const __half* W1b = g_W1h + l * 65536;
    const __half* W2b = g_W2h + l * 65536;
    fillw(0, W1b); fillw(1, W1b + 16384); fillw(2, W1b + 32768); fillw(3, W1b + 49152);

    // A = edges tile -> fp16 panel 0; fused msgs from OLD edges
    {
        const int c4 = tid & 31, k0 = c4 * 4, rb = tid >> 5;
        const float4 nv = *(const float4*)&g_nodes[(size_t)i * 128 + k0];
        float4 v[4];
#pragma unroll
        for (int t = 0; t < 4; t++)
            v[t] = *(const float4*)&g_edges[(size_t)(row0 + rb + t * 16) * 128 + k0];
#pragma unroll
        for (int t = 0; t < 4; t++) {
            int r = rb + t * 16;
            float dot = v[t].x*nv.x + v[t].y*nv.y + v[t].z*nv.z + v[t].w*nv.w;
#pragma unroll
            for (int o = 16; o; o >>= 1) dot += __shfl_xor_sync(0xffffffffu, dot, o);
            if (lane == 0) g_msgs[row0 + r] = g_adj[row0 + r] * dot;
            uint32_t off = swz_off(r, k0);
            *(uint2*)(sm + off) = make_uint2(packh(v[t].x, v[t].y), packh(v[t].z, v[t].w));
        }
    }
    __syncthreads();

    // ---- GEMM1: ks-outer, A fragments reused across all 4 N-chunks ----
    float acc1[4][2][2][4];
#pragma unroll
    for (int a = 0; a < 4; a++)
#pragma unroll
        for (int b = 0; b < 2; b++)
#pragma unroll
            for (int c = 0; c < 2; c++)
#pragma unroll
                for (int d = 0; d < 4; d++) acc1[a][b][c][d] = 0.f;

    const int aR  = wM * 32 + (lane & 15);
    const int aKx = lane >> 4;
    const int bR  = wN * 16 + (lane & 7) + ((lane & 16) >> 1);
    const int bKx = (lane & 8) >> 3;

    CP_WAIT0();
    pair_bar(wN);
#pragma unroll
    for (int ks = 0; ks < 8; ks++) {
        uint32_t ah[2][4];
#pragma unroll
        for (int mt = 0; mt < 2; mt++) {
            int r = aR + mt * 16;
            uint32_t off = (uint32_t)r * 256 + (uint32_t)((((ks * 2 + aKx) ^ (r & 7)) & 15) << 4);
            ldsm_x4(ah[mt], S + off);
        }
        uint32_t boff = (uint32_t)bR * 256 + (uint32_t)((((ks * 2 + bKx) ^ (bR & 7)) & 15) << 4);
#pragma unroll
        for (int nc = 0; nc < 4; nc++) {
            uint32_t bh[4];
            ldsm_x4(bh, BBs + (uint32_t)nc * 32768 + boff);
#pragma unroll
            for (int mt = 0; mt < 2; mt++) {
                mma16816h(acc1[nc][mt][0], ah[mt], bh[0], bh[1]);
                mma16816h(acc1[nc][mt][1], ah[mt], bh[2], bh[3]);
            }
        }
    }
    pair_bar(wN);
    fillw(0, W2b); fillw(1, W2b + 16384); fillw(2, W2b + 32768); fillw(3, W2b + 49152);

    // ---- epilogue: y = acc + P + Q, LN stats (smem partials, no atomics) ----
    const int R = wM * 32 + (lane >> 2);
    const int colB = wN * 16 + (lane & 3) * 2;
    float s4[4] = {0.f, 0.f, 0.f, 0.f}, q4[4] = {0.f, 0.f, 0.f, 0.f};
#pragma unroll
    for (int nc = 0; nc < 4; nc++)
#pragma unroll
        for (int mt = 0; mt < 2; mt++)
#pragma unroll
            for (int nt = 0; nt < 2; nt++) {
                int col = nc * 128 + colB + nt * 8;
                int rA = j0 + R + mt * 16;
                float2 qa = *(const float2*)&g_Q[(size_t)rA * 512 + col];
                float2 qb = *(const float2*)&g_Q[(size_t)(rA + 8) * 512 + col];
                float p0 = Pb[col], p1 = Pb[col + 1];
                float* a = acc1[nc][mt][nt];
                a[0] += p0 + qa.x; a[1] += p1 + qa.y;
                a[2] += p0 + qb.x; a[3] += p1 + qb.y;
                s4[mt*2+0] += a[0] + a[1]; q4[mt*2+0] += a[0]*a[0] + a[1]*a[1];
                s4[mt*2+1] += a[2] + a[3]; q4[mt*2+1] += a[2]*a[2] + a[3]*a[3];
            }
#pragma unroll
    for (int o = 1; o <= 2; o <<= 1)
#pragma unroll
        for (int t = 0; t < 4; t++) {
            s4[t] += __shfl_xor_sync(0xffffffffu, s4[t], o);
            q4[t] += __shfl_xor_sync(0xffffffffu, q4[t], o);
        }
    if ((lane & 3) == 0) {
#pragma unroll
        for (int t = 0; t < 4; t++) {
            int rr = R + (t >> 1) * 16 + (t & 1) * 8;
            redPS[wN * 64 + rr] = s4[t];
            redPQ[wN * 64 + rr] = q4[t];
        }
    }
    __syncthreads();
    if (tid < 64) {
        float Ssum = 0.f, Qsum = 0.f;
#pragma unroll
        for (int p = 0; p < 8; p++) {
            Ssum += redPS[p * 64 + tid];
            Qsum += redPQ[p * 64 + tid];
        }
        float mean = Ssum * (1.f / 512.f);
        float var = Qsum * (1.f / 512.f) - mean * mean;
        meanS[tid] = mean;
        rstdS[tid] = rsqrtf(var + EPSF);
    }
    __syncthreads();
    float mn[4], rs[4];
#pragma unroll
    for (int t = 0; t < 4; t++) {
        int rr = R + (t >> 1) * 16 + (t & 1) * 8;
        mn[t] = meanS[rr]; rs[t] = rstdS[rr];
    }

    // ---- stage ALL normalized h chunks into 4 panels, one sync ----
#pragma unroll
    for (int kc = 0; kc < 4; kc++) {
        const uint32_t pb = (uint32_t)kc * 16384;
#pragma unroll
        for (int mt = 0; mt < 2; mt++)
#pragma unroll
            for (int nt = 0; nt < 2; nt++) {
                int col = kc * 128 + colB + nt * 8;
                float g0 = Gam[col], g1 = Gam[col + 1];
                float be0 = Bet[col], be1 = Bet[col + 1];
                float* a = acc1[kc][mt][nt];
                float h0 = fmaxf((a[0] - mn[mt*2])   * rs[mt*2]   * g0 + be0, 0.f);
                float h1 = fmaxf((a[1] - mn[mt*2])   * rs[mt*2]   * g1 + be1, 0.f);
                float h2 = fmaxf((a[2] - mn[mt*2+1]) * rs[mt*2+1] * g0 + be0, 0.f);
                float h3 = fmaxf((a[3] - mn[mt*2+1]) * rs[mt*2+1] * g1 + be1, 0.f);
                int kl = colB + nt * 8;
                int r1 = R + mt * 16, r2 = r1 + 8;
                *(uint32_t*)(sm + pb + swz_off(r1, kl)) = packh(h0, h1);
                *(uint32_t*)(sm + pb + swz_off(r2, kl)) = packh(h2, h3);
            }
    }
    CP_WAIT0();
    __syncthreads();

    // prefetch residual (hidden under GEMM2)
    float2 e0r[2][2], e1r[2][2];
#pragma unroll
    for (int mt = 0; mt < 2; mt++)
#pragma unroll
        for (int nt = 0; nt < 2; nt++) {
            int col = colB + nt * 8;
            int r1 = row0 + R + mt * 16;
            e0r[mt][nt] = *(const float2*)&g_edges[(size_t)r1 * 128 + col];
            e1r[mt][nt] = *(const float2*)&g_edges[(size_t)(r1 + 8) * 128 + col];
        }

    // ---- GEMM2: barrier-free ----
    float acc2[2][2][4];
#pragma unroll
    for (int b = 0; b < 2; b++)
#pragma unroll
        for (int c = 0; c < 2; c++)
#pragma unroll
            for (int d = 0; d < 4; d++) acc2[b][c][d] = 0.f;

#pragma unroll
    for (int kc = 0; kc < 4; kc++) {
        const uint32_t AHp = S + (uint32_t)kc * 16384;
        const uint32_t BH = BBs + (uint32_t)kc * 32768;
#pragma unroll
        for (int ks = 0; ks < 8; ks++) {
            uint32_t ah[2][4], bh[4];
#pragma unroll
            for (int mt = 0; mt < 2; mt++) {
                int r = aR + mt * 16;
                uint32_t off = (uint32_t)r * 256 + (uint32_t)((((ks * 2 + aKx) ^ (r & 7)) & 15) << 4);
                ldsm_x4(ah[mt], AHp + off);
            }
            {
                uint32_t off = (uint32_t)bR * 256 + (uint32_t)((((ks * 2 + bKx) ^ (bR & 7)) & 15) << 4);
                ldsm_x4(bh, BH + off);
            }
#pragma unroll
            for (int mt = 0; mt < 2; mt++) {
                mma16816h(acc2[mt][0], ah[mt], bh[0], bh[1]);
                mma16816h(acc2[mt][1], ah[mt], bh[2], bh[3]);
            }
        }
    }

    // ---- output: acc2 + residual + b2 ----
#pragma unroll
    for (int mt = 0; mt < 2; mt++)
#pragma unroll
        for (int nt = 0; nt < 2; nt++) {
            int col = colB + nt * 8;
            int r1 = row0 + R + mt * 16;
            float b20 = B2s[col], b21 = B2s[col + 1];
            float* a = acc2[mt][nt];
            *(float2*)&g_edges[(size_t)r1 * 128 + col] =
                make_float2(a[0] + e0r[mt][nt].x + b20, a[1] + e0r[mt][nt].y + b21);
            *(float2*)&g_edges[(size_t)(r1 + 8) * 128 + col] =
                make_float2(a[2] + e1r[mt][nt].x + b20, a[3] + e1r[mt][nt].y + b21);
        }
}

// ================= barrier-free BM=4 node MLP (512 thr, 64 CTAs) =================
__global__ void __launch_bounds__(512, 1) k_node(
        const float* __restrict__ W1, const float* __restrict__ b1,
        const float* __restrict__ gg, const float* __restrict__ bb,
        const float* __restrict__ W2, const float* __restrict__ b2,
        const float* __restrict__ Wp, const float* __restrict__ Wq, int do_pq) {
    __shared__ float Xs[4 * 384];
    __shared__ float Hs[4 * 512];
    __shared__ float part[4096];
    __shared__ float red[136];
    __shared__ float Xn[512];
    const int tid = threadIdx.x, lane = tid & 31, wid = tid >> 5;
    const int r0 = blockIdx.x * 4;
    {
        int row = tid >> 7, c = tid & 127;
        Xs[row * 384 + c] = g_nodes[(r0 + row) * 128 + c];
        int i1 = tid + 512;
        Xs[(tid >> 8) * 384 + 128 + (tid & 255)] = g_msgs[(r0 + (tid >> 8)) * 256 + (tid & 255)];
        Xs[(i1 >> 8) * 384 + 128 + (i1 & 255)]   = g_msgs[(r0 + (i1 >> 8)) * 256 + (i1 & 255)];
    }
    __syncthreads();
    // GEMM1: 2 k-slices x 256 col-pairs, float2 weight loads, no barriers inside
    {
        int ks = tid >> 8, cp = tid & 255;
        float a00=0,a01=0,a10=0,a11=0,a20=0,a21=0,a30=0,a31=0;
        int kb = ks * 192;
#pragma unroll 8
        for (int kk = 0; kk < 192; kk++) {
            int k = kb + kk;
            float2 w = *(const float2*)&W1[(size_t)k * 512 + cp * 2];
            float x0 = Xs[k], x1 = Xs[384 + k], x2 = Xs[768 + k], x3 = Xs[1152 + k];
            a00 = fmaf(x0, w.x, a00); a01 = fmaf(x0, w.y, a01);
            a10 = fmaf(x1, w.x, a10); a11 = fmaf(x1, w.y, a11);
            a20 = fmaf(x2, w.x, a20); a21 = fmaf(x2, w.y, a21);
            a30 = fmaf(x3, w.x, a30); a31 = fmaf(x3, w.y, a31);
        }
        float* pg = part + ks * 2048 + cp * 2;
        pg[0] = a00;    pg[1] = a01;
        pg[512] = a10;  pg[513] = a11;
        pg[1024] = a20; pg[1025] = a21;
        pg[1536] = a30; pg[1537] = a31;
    }
    __syncthreads();
    float y0, y1, y2, y3;
    {
        float bv = b1[tid];
        y0 = part[tid]        + part[2048 + tid]        + bv;
        y1 = part[512 + tid]  + part[2048 + 512 + tid]  + bv;
        y2 = part[1024 + tid] + part[2048 + 1024 + tid] + bv;
        y3 = part[1536 + tid] + part[2048 + 1536 + tid] + bv;
    }
    {
        float s0=y0,s1=y1,s2=y2,s3=y3,q0=y0*y0,q1=y1*y1,q2=y2*y2,q3=y3*y3;
#pragma unroll
        for (int o = 16; o; o >>= 1) {
            s0 += __shfl_xor_sync(0xffffffffu, s0, o);
            s1 += __shfl_xor_sync(0xffffffffu, s1, o);
            s2 += __shfl_xor_sync(0xffffffffu, s2, o);
            s3 += __shfl_xor_sync(0xffffffffu, s3, o);
            q0 += __shfl_xor_sync(0xffffffffu, q0, o);
            q1 += __shfl_xor_sync(0xffffffffu, q1, o);
            q2 += __shfl_xor_sync(0xffffffffu, q2, o);
            q3 += __shfl_xor_sync(0xffffffffu, q3, o);
        }
        if (lane == 0) {
            float* rw = red + wid * 8;
            rw[0]=s0; rw[1]=s1; rw[2]=s2; rw[3]=s3; rw[4]=q0; rw[5]=q1; rw[6]=q2; rw[7]=q3;
        }
    }
    __syncthreads();
    if (tid < 8) {
        float v = 0.f;
#pragma unroll
        for (int w = 0; w < 16; w++) v += red[w * 8 + tid];
        red[128 + tid] = v;
    }
    __syncthreads();
    {
        float gv = gg[tid], btv = bb[tid];
        float m0 = red[128] * (1.f/512.f), m1 = red[129] * (1.f/512.f);
        float m2 = red[130] * (1.f/512.f), m3 = red[131] * (1.f/512.f);
        float rs0 = rsqrtf(red[132] * (1.f/512.f) - m0*m0 + EPSF);
        float rs1 = rsqrtf(red[133] * (1.f/512.f) - m1*m1 + EPSF);
        float rs2 = rsqrtf(red[134] * (1.f/512.f) - m2*m2 + EPSF);
        float rs3 = rsqrtf(red[135] * (1.f/512.f) - m3*m3 + EPSF);
        Hs[tid]        = fmaxf((y0 - m0) * rs0 * gv + btv, 0.f);
        Hs[512 + tid]  = fmaxf((y1 - m1) * rs1 * gv + btv, 0.f);
        Hs[1024 + tid] = fmaxf((y2 - m2) * rs2 * gv + btv, 0.f);
        Hs[1536 + tid] = fmaxf((y3 - m3) * rs3 * gv + btv, 0.f);
    }
    __syncthreads();
    // GEMM2: 4 k-slices x 128 cols
    {
        int ks = tid >> 7, col = tid & 127;
        float o0=0,o1=0,o2=0,o3=0;
        int kb = ks * 128;
#pragma unroll 8
        for (int kk = 0; kk < 128; kk++) {
            int k = kb + kk;
            float w = W2[(size_t)k * 128 + col];
            o0 = fmaf(Hs[k], w, o0);        o1 = fmaf(Hs[512 + k], w, o1);
            o2 = fmaf(Hs[1024 + k], w, o2); o3 = fmaf(Hs[1536 + k], w, o3);
        }
        float* pg = part + ks * 512 + col;
        pg[0] = o0; pg[128] = o1; pg[256] = o2; pg[384] = o3;
    }
    __syncthreads();
    {
        int row = tid >> 7, c = tid & 127;
        float v = part[row * 128 + c] + part[512 + row * 128 + c]
                + part[1024 + row * 128 + c] + part[1536 + row * 128 + c]
                + Xs[row * 384 + c] + b2[c];
        g_nodes[(r0 + row) * 128 + c] = v;
        Xn[row * 128 + c] = v;
    }
    if (do_pq) {
        __syncthreads();
        float p0=0,p1=0,p2=0,p3=0,u0=0,u1=0,u2=0,u3=0;
#pragma unroll 4
        for (int k = 0; k < 128; k++) {
            float wp = Wp[(size_t)k * 512 + tid];
            float wq = Wq[(size_t)k * 512 + tid];
            float x0 = Xn[k], x1 = Xn[128 + k], x2 = Xn[256 + k], x3 = Xn[384 + k];
            p0 = fmaf(x0, wp, p0); p1 = fmaf(x1, wp, p1);
            p2 = fmaf(x2, wp, p2); p3 = fmaf(x3, wp, p3);
            u0 = fmaf(x0, wq, u0); u1 = fmaf(x1, wq, u1);
            u2 = fmaf(x2, wq, u2); u3 = fmaf(x3, wq, u3);
        }
        g_P[(r0+0)*512 + tid] = p0; g_P[(r0+1)*512 + tid] = p1;
        g_P[(r0+2)*512 + tid] = p2; g_P[(r0+3)*512 + tid] = p3;
        g_Q[(r0+0)*512 + tid] = u0; g_Q[(r0+1)*512 + tid] = u1;
        g_Q[(r0+2)*512 + tid] = u2; g_Q[(r0+3)*512 + tid] = u3;
    }
}

// ---- barrier-free 4-row LN-MLP stage (KD=128): Xs[4*128] -> Hs[4*512] ----
__device__ __forceinline__ void stage128(const float* Xs, float* Hs, float* part, float* red,
        const float* __restrict__ W1, const float* __restrict__ b1,
        const float* __restrict__ gg, const float* __restrict__ bb,
        int tid, int lane, int wid) {
    {
        int ks = tid >> 8, cp = tid & 255;
        float a00=0,a01=0,a10=0,a11=0,a20=0,a21=0,a30=0,a31=0;
        int kb = ks * 64;
#pragma unroll 8
        for (int kk = 0; kk < 64; kk++) {
            int k = kb + kk;
            float2 w = *(const float2*)&W1[(size_t)k * 512 + cp * 2];
            float x0 = Xs[k], x1 = Xs[128 + k], x2 = Xs[256 + k], x3 = Xs[384 + k];
            a00 = fmaf(x0, w.x, a00); a01 = fmaf(x0, w.y, a01);
            a10 = fmaf(x1, w.x, a10); a11 = fmaf(x1, w.y, a11);
            a20 = fmaf(x2, w.x, a20); a21 = fmaf(x2, w.y, a21);
            a30 = fmaf(x3, w.x, a30); a31 = fmaf(x3, w.y, a31);
        }
        float* pg = part + ks * 2048 + cp * 2;
        pg[0] = a00;    pg[1] = a01;
        pg[512] = a10;  pg[513] = a11;
        pg[1024] = a20; pg[1025] = a21;
        pg[1536] = a30; pg[1537] = a31;
    }
    __syncthreads();
    float y0, y1, y2, y3;
    {
        float bv = b1[tid];
        y0 = part[tid]        + part[2048 + tid]        + bv;
        y1 = part[512 + tid]  + part[2048 + 512 + tid]  + bv;
        y2 = part[1024 + tid] + part[2048 + 1024 + tid] + bv;
        y3 = part[1536 + tid] + part[2048 + 1536 + tid] + bv;
    }
    {
        float s0=y0,s1=y1,s2=y2,s3=y3,q0=y0*y0,q1=y1*y1,q2=y2*y2,q3=y3*y3;
#pragma unroll
        for (int o = 16; o; o >>= 1) {
            s0 += __shfl_xor_sync(0xffffffffu, s0, o);
            s1 += __shfl_xor_sync(0xffffffffu, s1, o);
            s2 += __shfl_xor_sync(0xffffffffu, s2, o);
            s3 += __shfl_xor_sync(0xffffffffu, s3, o);
            q0 += __shfl_xor_sync(0xffffffffu, q0, o);
            q1 += __shfl_xor_sync(0xffffffffu, q1, o);
            q2 += __shfl_xor_sync(0xffffffffu, q2, o);
            q3 += __shfl_xor_sync(0xffffffffu, q3, o);
        }
        if (lane == 0) {
            float* rw = red + wid * 8;
            rw[0]=s0; rw[1]=s1; rw[2]=s2; rw[3]=s3; rw[4]=q0; rw[5]=q1; rw[6]=q2; rw[7]=q3;
        }
    }
    __syncthreads();
    if (tid < 8) {
        float v = 0.f;
#pragma unroll
        for (int w = 0; w < 16; w++) v += red[w * 8 + tid];
        red[128 + tid] = v;
    }
    __syncthreads();
    {
        float gv = gg[tid], btv = bb[tid];
        float m0 = red[128] * (1.f/512.f), m1 = red[129] * (1.f/512.f);
        float m2 = red[130] * (1.f/512.f), m3 = red[131] * (1.f/512.f);
        float rs0 = rsqrtf(red[132] * (1.f/512.f) - m0*m0 + EPSF);
        float rs1 = rsqrtf(red[133] * (1.f/512.f) - m1*m1 + EPSF);
        float rs2 = rsqrtf(red[134] * (1.f/512.f) - m2*m2 + EPSF);
        float rs3 = rsqrtf(red[135] * (1.f/512.f) - m3*m3 + EPSF);
        Hs[tid]        = fmaxf((y0 - m0) * rs0 * gv + btv, 0.f);
        Hs[512 + tid]  = fmaxf((y1 - m1) * rs1 * gv + btv, 0.f);
        Hs[1024 + tid] = fmaxf((y2 - m2) * rs2 * gv + btv, 0.f);
        Hs[1536 + tid] = fmaxf((y3 - m3) * rs3 * gv + btv, 0.f);
    }
    __syncthreads();
}

// final output head; BM=4, grid 64, 512 thr, barrier-light
__global__ void __launch_bounds__(512, 1) k_final(
        const float* __restrict__ no1_w, const float* __restrict__ no1_b,
        const float* __restrict__ no_g,  const float* __restrict__ no_bt,
        const float* __restrict__ no2_w, const float* __restrict__ no2_b,
        const float* __restrict__ sp1_w, const float* __restrict__ sp1_b,
        const float* __restrict__ sp_g,  const float* __restrict__ sp_bt,
        const float* __restrict__ sp2_w, const float* __restrict__ sp2_b,
        float* __restrict__ out_nodes, float* __restrict__ out_coords) {
    __shared__ float Xs[512];
    __shared__ float Hs[4 * 512];
    __shared__ float part[4096];
    __shared__ float red[136];
    __shared__ float X2[512];
    const int tid = threadIdx.x, lane = tid & 31, wid = tid >> 5;
    const int r0 = blockIdx.x * 4;
    {
        int row = tid >> 7, c = tid & 127;
        Xs[row * 128 + c] = g_nodes[(r0 + row) * 128 + c];
    }
    __syncthreads();
    stage128(Xs, Hs, part, red, no1_w, no1_b, no_g, no_bt, tid, lane, wid);
    // GEMM2 (no2_w)
    {
        int ks = tid >> 7, col = tid & 127;
        float o0=0,o1=0,o2=0,o3=0;
        int kb = ks * 128;
#pragma unroll 8
        for (int kk = 0; kk < 128; kk++) {
            int k = kb + kk;
            float w = no2_w[(size_t)k * 128 + col];
            o0 = fmaf(Hs[k], w, o0);        o1 = fmaf(Hs[512 + k], w, o1);
            o2 = fmaf(Hs[1024 + k], w, o2); o3 = fmaf(Hs[1536 + k], w, o3);
        }
        float* pg = part + ks * 512 + col;
        pg[0] = o0; pg[128] = o1; pg[256] = o2; pg[384] = o3;
    }
    __syncthreads();
    {
        int row = tid >> 7, c = tid & 127;
        float v = part[row * 128 + c] + part[512 + row * 128 + c]
                + part[1024 + row * 128 + c] + part[1536 + row * 128 + c] + no2_b[c];
        out_nodes[(r0 + row) * 128 + c] = v;
        X2[row * 128 + c] = v;
    }
    __syncthreads();
    stage128(X2, Hs, part, red, sp1_w, sp1_b, sp_g, sp_bt, tid, lane, wid);
    int g = tid >> 4;
    if (g < 12) {
        int row = g / 3, cc = g - row * 3;
        int l16 = tid & 15;
        float s = 0.f;
        for (int k = l16; k < 512; k += 16) s = fmaf(Hs[row * 512 + k], sp2_w[k * 3 + cc], s);
#pragma unroll
        for (int o = 8; o; o >>= 1) s += __shfl_xor_sync(0xffffffffu, s, o);
        if (l16 == 0) out_coords[(r0 + row) * 3 + cc] = s + sp2_b[cc];
    }
}

// ================= launcher =================
extern "C" void kernel_launch(void* const* d_in, const int* in_sizes, int n_in,
                              void* d_out, int out_size) {
    const float* nodes  = (const float*)d_in[0];
    const float* coords = (const float*)d_in[1];
    const float* ee_w   = (const float*)d_in[2];
    const float* ee_b   = (const float*)d_in[3];
    const float* ee_g   = (const float*)d_in[4];
    const float* ee_bt  = (const float*)d_in[5];
    const float* nu1_w  = (const float*)d_in[6];
    const float* nu1_b  = (const float*)d_in[7];
    const float* nu_g   = (const float*)d_in[8];
    const float* nu_bt  = (const float*)d_in[9];
    const float* nu2_w  = (const float*)d_in[10];
    const float* nu2_b  = (const float*)d_in[11];
    const float* eu1_w  = (const float*)d_in[12];
    const float* eu1_b  = (const float*)d_in[13];
    const float* eu_g   = (const float*)d_in[14];
    const float* eu_bt  = (const float*)d_in[15];
    const float* eu2_w  = (const float*)d_in[16];
    const float* eu2_b  = (const float*)d_in[17];
    const float* sp1_w  = (const float*)d_in[18];
    const float* sp1_b  = (const float*)d_in[19];
    const float* sp_g   = (const float*)d_in[20];
    const float* sp_bt  = (const float*)d_in[21];
    const float* sp2_w  = (const float*)d_in[22];
    const float* sp2_b  = (const float*)d_in[23];
    const float* no1_w  = (const float*)d_in[24];
    const float* no1_b  = (const float*)d_in[25];
    const float* no_g   = (const float*)d_in[26];
    const float* no_bt  = (const float*)d_in[27];
    const float* no2_w  = (const float*)d_in[28];
    const float* no2_b  = (const float*)d_in[29];
    float* out = (float*)d_out;

    const int SME = 207872;
    cudaFuncSetAttribute(k_edge_mma, cudaFuncAttributeMaxDynamicSharedMemorySize, SME);

    k_init<<<9728, 256>>>(nodes, coords, ee_w, ee_b, ee_g, ee_bt, eu1_w, eu2_w);  // 0
    k_pq<<<dim3(64, 2), 512>>>(eu1_w + 65536, eu1_w + 131072);                    // 1

    for (int l = 0; l < 3; l++) {
        k_edge_mma<<<1024, 512, SME>>>(l, eu1_b + l*512, eu_g + l*512,   // 2 (l=0)
                                       eu_bt + l*512, eu2_b + l*128);
        int do_pq = (l < 2) ? 1 : 0;
        const float* Wp = eu1_w + (l+1)*196608 + 65536;
        const float* Wq = eu1_w + (l+1)*196608 + 131072;
        k_node<<<64, 512>>>(nu1_w + l*196608, nu1_b + l*512,             // 3 (l=0): ncu slot
                            nu_g + l*512, nu_bt + l*512,
                            nu2_w + l*65536, nu2_b + l*128,
                            Wp, Wq, do_pq);
    }
    // layer 3: edge output is dead code — msgs only
    k_msgs<<<8192, 256>>>();
    k_node<<<64, 512>>>(nu1_w + 3*196608, nu1_b + 3*512,
                        nu_g + 3*512, nu_bt + 3*512,
                        nu2_w + 3*65536, nu2_b + 3*128,
                        nu1_w, nu1_w, 0);
    k_final<<<64, 512>>>(no1_w, no1_b, no_g, no_bt, no2_w, no2_b,
                         sp1_w, sp1_b, sp_g, sp_bt, sp2_w, sp2_b,
                         out, out + 32768);
}